// round 1
// baseline (speedup 1.0000x reference)
#include <cuda_runtime.h>

// Problem constants
#define BATCH  2
#define S_LEN  2048
#define DMODEL 1024
#define NHEAD  16
#define DKH    64
#define M_TOT  (BATCH * S_LEN)   // 4096

// Scratch (device globals: allocation-free)
__device__ float g_q[BATCH * NHEAD * S_LEN * DKH];    // [B,H,S,DK]
__device__ float g_k[BATCH * NHEAD * S_LEN * DKH];
__device__ float g_v[BATCH * NHEAD * S_LEN * DKH];
__device__ float g_att[M_TOT * DMODEL];               // [B*S, D] plain

// ---------------------------------------------------------------------------
// GEMM: out = A[M,K] @ W[N,K]^T + bias, M=4096, N=K=1024.
// HEADOUT=1: scatter into [B,H,S,DK]; HEADOUT=0: plain [M,N].
// 128x128 tile, BK=16, 256 threads, 8x8 per thread (split 4+4 rows/cols).
// ---------------------------------------------------------------------------
template <int HEADOUT>
__global__ __launch_bounds__(256) void gemm_kernel(
    const float* __restrict__ A, const float* __restrict__ W,
    const float* __restrict__ bias, float* __restrict__ out)
{
    __shared__ float As[16][132];
    __shared__ float Bs[16][132];

    const int tid = threadIdx.x;
    const int tx = tid & 15;        // 0..15 (cols)
    const int ty = tid >> 4;        // 0..15 (rows)
    const int m0 = blockIdx.y * 128;
    const int n0 = blockIdx.x * 128;

    float acc[8][8];
#pragma unroll
    for (int i = 0; i < 8; ++i)
#pragma unroll
        for (int j = 0; j < 8; ++j) acc[i][j] = 0.f;

    for (int kt = 0; kt < DMODEL; kt += 16) {
#pragma unroll
        for (int it = 0; it < 2; ++it) {
            int u  = tid + it * 256;        // 0..511
            int r  = u >> 2;                // 0..127
            int c4 = (u & 3) * 4;           // 0,4,8,12
            float4 va = *(const float4*)&A[(m0 + r) * DMODEL + kt + c4];
            As[c4 + 0][r] = va.x; As[c4 + 1][r] = va.y;
            As[c4 + 2][r] = va.z; As[c4 + 3][r] = va.w;
            float4 vb = *(const float4*)&W[(n0 + r) * DMODEL + kt + c4];
            Bs[c4 + 0][r] = vb.x; Bs[c4 + 1][r] = vb.y;
            Bs[c4 + 2][r] = vb.z; Bs[c4 + 3][r] = vb.w;
        }
        __syncthreads();

#pragma unroll
        for (int kk = 0; kk < 16; ++kk) {
            float a[8], b[8];
            *(float4*)(a)     = *(const float4*)&As[kk][4 * ty];
            *(float4*)(a + 4) = *(const float4*)&As[kk][64 + 4 * ty];
            *(float4*)(b)     = *(const float4*)&Bs[kk][4 * tx];
            *(float4*)(b + 4) = *(const float4*)&Bs[kk][64 + 4 * tx];
#pragma unroll
            for (int i = 0; i < 8; ++i)
#pragma unroll
                for (int j = 0; j < 8; ++j)
                    acc[i][j] += a[i] * b[j];
        }
        __syncthreads();
    }

    // Epilogue: bias + store
#pragma unroll
    for (int ih = 0; ih < 2; ++ih) {
#pragma unroll
        for (int i = 0; i < 4; ++i) {
            int m = m0 + ih * 64 + 4 * ty + i;
#pragma unroll
            for (int jh = 0; jh < 2; ++jh) {
                int nb = n0 + jh * 64 + 4 * tx;
                float4 r;
                r.x = acc[ih * 4 + i][jh * 4 + 0] + bias[nb + 0];
                r.y = acc[ih * 4 + i][jh * 4 + 1] + bias[nb + 1];
                r.z = acc[ih * 4 + i][jh * 4 + 2] + bias[nb + 2];
                r.w = acc[ih * 4 + i][jh * 4 + 3] + bias[nb + 3];
                if (HEADOUT) {
                    int b  = m >> 11;           // /2048
                    int s  = m & 2047;
                    int h  = nb >> 6;           // /64
                    int d  = nb & 63;
                    *(float4*)&out[(((b * NHEAD) + h) * S_LEN + s) * DKH + d] = r;
                } else {
                    *(float4*)&out[m * DMODEL + nb] = r;
                }
            }
        }
    }
}

// ---------------------------------------------------------------------------
// Flash attention per (b,h). 64 queries x 64 keys per tile, DK=64.
// scores = (dot64 + a_q*a_k + b_q*b_k) / 16,  a=sum(q)/8, b=sum((-1)^d q)/8.
// Output written directly to plain [B*S, D] layout for the Wo GEMM.
// ---------------------------------------------------------------------------
#define ATTN_SMEM_FLOATS (64*64 /*Qst*/ + 64*64 /*Kst*/ + 64*64 /*Vs*/ + 64*72 /*Ps*/ + 4*64 /*stats*/)

__global__ __launch_bounds__(256) void attn_kernel(
    const float* __restrict__ q, const float* __restrict__ k,
    const float* __restrict__ v, float* __restrict__ out)
{
    extern __shared__ float sm[];
    float* Qst = sm;                    // [64][64] d-major (transposed)
    float* Kst = Qst + 64 * 64;         // [64][64] d-major
    float* Vs  = Kst + 64 * 64;         // [64][64] k-major (natural)
    float* Ps  = Vs + 64 * 64;          // [64][72] padded
    float* Qa  = Ps + 64 * 72;
    float* Qb  = Qa + 64;
    float* Ka  = Qb + 64;
    float* Kb  = Ka + 64;

    const int tid = threadIdx.x;
    const int tx = tid & 15;
    const int ty = tid >> 4;
    const int bh = blockIdx.y;          // 0..31
    const int s0 = blockIdx.x * 64;

    const float* qb = q + (size_t)bh * S_LEN * DKH;
    const float* kb = k + (size_t)bh * S_LEN * DKH;
    const float* vb = v + (size_t)bh * S_LEN * DKH;

    // Load Q tile (transposed into smem)
#pragma unroll
    for (int it = 0; it < 4; ++it) {
        int u  = tid + it * 256;        // 0..1023
        int s  = u & 63;
        int d4 = (u >> 6) * 4;          // 0..60
        float4 val = *(const float4*)&qb[(s0 + s) * DKH + d4];
        Qst[(d4 + 0) * 64 + s] = val.x;
        Qst[(d4 + 1) * 64 + s] = val.y;
        Qst[(d4 + 2) * 64 + s] = val.z;
        Qst[(d4 + 3) * 64 + s] = val.w;
    }
    __syncthreads();
    if (tid < 64) {
        float sa = 0.f, sb = 0.f;
#pragma unroll
        for (int d = 0; d < 64; ++d) {
            float qv = Qst[d * 64 + tid];
            sa += qv;
            sb += (d & 1) ? -qv : qv;
        }
        Qa[tid] = sa * 0.125f;
        Qb[tid] = sb * 0.125f;
    }

    float mI[4], lI[4], acc[4][4];
#pragma unroll
    for (int i = 0; i < 4; ++i) {
        mI[i] = -1e30f; lI[i] = 0.f;
#pragma unroll
        for (int j = 0; j < 4; ++j) acc[i][j] = 0.f;
    }

    for (int t0 = 0; t0 < S_LEN; t0 += 64) {
        __syncthreads();  // previous PV done with Kst/Vs/Ps (also covers Q-stats on iter 0)

        // Load K (transposed) and V (natural)
#pragma unroll
        for (int it = 0; it < 4; ++it) {
            int u  = tid + it * 256;
            int s  = u & 63;
            int d4 = (u >> 6) * 4;
            float4 kv = *(const float4*)&kb[(t0 + s) * DKH + d4];
            Kst[(d4 + 0) * 64 + s] = kv.x;
            Kst[(d4 + 1) * 64 + s] = kv.y;
            Kst[(d4 + 2) * 64 + s] = kv.z;
            Kst[(d4 + 3) * 64 + s] = kv.w;
            *(float4*)&Vs[s * 64 + d4] = *(const float4*)&vb[(t0 + s) * DKH + d4];
        }
        __syncthreads();
        if (tid < 64) {
            float sa = 0.f, sb = 0.f;
#pragma unroll
            for (int d = 0; d < 64; ++d) {
                float kv = Kst[d * 64 + tid];
                sa += kv;
                sb += (d & 1) ? -kv : kv;
            }
            Ka[tid] = sa * 0.125f;
            Kb[tid] = sb * 0.125f;
        }
        __syncthreads();

        // Scores: 64x64, 4x4 per thread
        float sc[4][4];
#pragma unroll
        for (int i = 0; i < 4; ++i)
#pragma unroll
            for (int j = 0; j < 4; ++j) sc[i][j] = 0.f;

#pragma unroll
        for (int d = 0; d < 64; ++d) {
            float4 qv = *(const float4*)&Qst[d * 64 + 4 * ty];
            float4 kv = *(const float4*)&Kst[d * 64 + 4 * tx];
            float aq[4] = {qv.x, qv.y, qv.z, qv.w};
            float ak[4] = {kv.x, kv.y, kv.z, kv.w};
#pragma unroll
            for (int i = 0; i < 4; ++i)
#pragma unroll
                for (int j = 0; j < 4; ++j)
                    sc[i][j] += aq[i] * ak[j];
        }

        // rank-2 correction + scale, then online softmax
#pragma unroll
        for (int i = 0; i < 4; ++i) {
            int row = 4 * ty + i;
            float qa = Qa[row], qbv = Qb[row];
#pragma unroll
            for (int j = 0; j < 4; ++j) {
                int col = 4 * tx + j;
                sc[i][j] = (sc[i][j] + qa * Ka[col] + qbv * Kb[col]) * 0.0625f;
            }
            float rm = fmaxf(fmaxf(sc[i][0], sc[i][1]), fmaxf(sc[i][2], sc[i][3]));
#pragma unroll
            for (int o = 8; o >= 1; o >>= 1)
                rm = fmaxf(rm, __shfl_xor_sync(0xffffffffu, rm, o));
            float mn = fmaxf(mI[i], rm);
            float sum = 0.f;
#pragma unroll
            for (int j = 0; j < 4; ++j) {
                sc[i][j] = __expf(sc[i][j] - mn);
                sum += sc[i][j];
            }
#pragma unroll
            for (int o = 8; o >= 1; o >>= 1)
                sum += __shfl_xor_sync(0xffffffffu, sum, o);
            float scale = __expf(mI[i] - mn);
            lI[i] = lI[i] * scale + sum;
            mI[i] = mn;
#pragma unroll
            for (int j = 0; j < 4; ++j) acc[i][j] *= scale;
            // stage P
            float4 pw = make_float4(sc[i][0], sc[i][1], sc[i][2], sc[i][3]);
            *(float4*)&Ps[(4 * ty + i) * 72 + 4 * tx] = pw;
        }
        __syncthreads();

        // PV: acc[q][d] += P[q][k] * V[k][d]
#pragma unroll 8
        for (int kk = 0; kk < 64; ++kk) {
            float4 vv = *(const float4*)&Vs[kk * 64 + 4 * tx];
            float vr[4] = {vv.x, vv.y, vv.z, vv.w};
#pragma unroll
            for (int i = 0; i < 4; ++i) {
                float p = Ps[(4 * ty + i) * 72 + kk];
#pragma unroll
                for (int j = 0; j < 4; ++j)
                    acc[i][j] += p * vr[j];
            }
        }
    }

    // Finalize + write plain [B*S, D]
    const int b = bh >> 4;
    const int h = bh & 15;
#pragma unroll
    for (int i = 0; i < 4; ++i) {
        int s = s0 + 4 * ty + i;
        float inv = 1.f / lI[i];
        float4 o = make_float4(acc[i][0] * inv, acc[i][1] * inv,
                               acc[i][2] * inv, acc[i][3] * inv);
        *(float4*)&out[((size_t)(b * S_LEN + s)) * DMODEL + h * DKH + 4 * tx] = o;
    }
}

// ---------------------------------------------------------------------------
// Launch
// ---------------------------------------------------------------------------
extern "C" void kernel_launch(void* const* d_in, const int* in_sizes, int n_in,
                              void* d_out, int out_size)
{
    const float* x  = (const float*)d_in[0];
    const float* Wq = (const float*)d_in[1];
    const float* bq = (const float*)d_in[2];
    const float* Wk = (const float*)d_in[3];
    const float* bk = (const float*)d_in[4];
    const float* Wv = (const float*)d_in[5];
    const float* bv = (const float*)d_in[6];
    const float* Wo = (const float*)d_in[7];
    const float* bo = (const float*)d_in[8];
    float* out = (float*)d_out;

    float *qp, *kp, *vp, *ap;
    cudaGetSymbolAddress((void**)&qp, g_q);
    cudaGetSymbolAddress((void**)&kp, g_k);
    cudaGetSymbolAddress((void**)&vp, g_v);
    cudaGetSymbolAddress((void**)&ap, g_att);

    const int attn_smem = ATTN_SMEM_FLOATS * sizeof(float);
    cudaFuncSetAttribute(attn_kernel, cudaFuncAttributeMaxDynamicSharedMemorySize,
                         attn_smem);

    dim3 gg(DMODEL / 128, M_TOT / 128);   // (8, 32)
    gemm_kernel<1><<<gg, 256>>>(x, Wq, bq, qp);
    gemm_kernel<1><<<gg, 256>>>(x, Wk, bk, kp);
    gemm_kernel<1><<<gg, 256>>>(x, Wv, bv, vp);

    dim3 ga(S_LEN / 64, BATCH * NHEAD);   // (32, 32)
    attn_kernel<<<ga, 256, attn_smem>>>(qp, kp, vp, ap);

    gemm_kernel<0><<<gg, 256>>>(ap, Wo, bo, out);
}

// round 2
// speedup vs baseline: 2.5380x; 2.5380x over previous
#include <cuda_runtime.h>
#include <cuda_bf16.h>

#define BATCH  2
#define S_LEN  2048
#define DMODEL 1024
#define NHEAD  16
#define DKH    64
#define DKP    80            // 64 dims + a,b + zero pad
#define M_TOT  (BATCH * S_LEN)
#define BH     (BATCH * NHEAD)

// ---------------- scratch (device globals; allocation-free) ----------------
__device__ __align__(16) __nv_bfloat16 g_xhi[M_TOT * DMODEL];
__device__ __align__(16) __nv_bfloat16 g_xlo[M_TOT * DMODEL];
__device__ __align__(16) __nv_bfloat16 g_whi[4][DMODEL * DMODEL];
__device__ __align__(16) __nv_bfloat16 g_wlo[4][DMODEL * DMODEL];
__device__ __align__(16) float g_q[BH * S_LEN * DKH];
__device__ __align__(16) float g_k[BH * S_LEN * DKH];
__device__ __align__(16) float g_v[BH * S_LEN * DKH];
__device__ __align__(16) __nv_bfloat16 g_qahi[BH * S_LEN * DKP];
__device__ __align__(16) __nv_bfloat16 g_qalo[BH * S_LEN * DKP];
__device__ __align__(16) __nv_bfloat16 g_kahi[BH * S_LEN * DKP];
__device__ __align__(16) __nv_bfloat16 g_kalo[BH * S_LEN * DKP];
__device__ __align__(16) __nv_bfloat16 g_vthi[BH * DKH * S_LEN];   // [bh][d][s]
__device__ __align__(16) __nv_bfloat16 g_vtlo[BH * DKH * S_LEN];
__device__ __align__(16) __nv_bfloat16 g_ahi[M_TOT * DMODEL];
__device__ __align__(16) __nv_bfloat16 g_alo[M_TOT * DMODEL];

// ---------------- mma / ldmatrix helpers ----------------
__device__ __forceinline__ unsigned smem_u32(const void* p) {
    return (unsigned)__cvta_generic_to_shared(p);
}
__device__ __forceinline__ void ldsm4(unsigned* r, unsigned addr) {
    asm volatile("ldmatrix.sync.aligned.m8n8.x4.shared.b16 {%0,%1,%2,%3}, [%4];\n"
                 : "=r"(r[0]), "=r"(r[1]), "=r"(r[2]), "=r"(r[3]) : "r"(addr));
}
__device__ __forceinline__ void mma_bf16(float* c, const unsigned* a, unsigned b0, unsigned b1) {
    asm volatile("mma.sync.aligned.m16n8k16.row.col.f32.bf16.bf16.f32 "
                 "{%0,%1,%2,%3}, {%4,%5,%6,%7}, {%8,%9}, {%0,%1,%2,%3};\n"
                 : "+f"(c[0]), "+f"(c[1]), "+f"(c[2]), "+f"(c[3])
                 : "r"(a[0]), "r"(a[1]), "r"(a[2]), "r"(a[3]), "r"(b0), "r"(b1));
}
__device__ __forceinline__ void split_pack(float x, float y, unsigned& hi, unsigned& lo) {
    __nv_bfloat16 hx = __float2bfloat16(x), hy = __float2bfloat16(y);
    __nv_bfloat16 lx = __float2bfloat16(x - __bfloat162float(hx));
    __nv_bfloat16 ly = __float2bfloat16(y - __bfloat162float(hy));
    __nv_bfloat162 H = __halves2bfloat162(hx, hy);
    __nv_bfloat162 L = __halves2bfloat162(lx, ly);
    hi = *(unsigned*)&H; lo = *(unsigned*)&L;
}

// ---------------- elementwise fp32 -> bf16 hi/lo split ----------------
__global__ void split_kernel(const float* __restrict__ in,
                             __nv_bfloat16* __restrict__ hi,
                             __nv_bfloat16* __restrict__ lo, int n4) {
    int i = blockIdx.x * blockDim.x + threadIdx.x;
    if (i >= n4) return;
    float4 v = ((const float4*)in)[i];
    float vv[4] = {v.x, v.y, v.z, v.w};
    __nv_bfloat16 h[4], l[4];
#pragma unroll
    for (int j = 0; j < 4; ++j) {
        h[j] = __float2bfloat16(vv[j]);
        l[j] = __float2bfloat16(vv[j] - __bfloat162float(h[j]));
    }
    *(__nv_bfloat162*)&hi[4 * i]     = __halves2bfloat162(h[0], h[1]);
    *(__nv_bfloat162*)&hi[4 * i + 2] = __halves2bfloat162(h[2], h[3]);
    *(__nv_bfloat162*)&lo[4 * i]     = __halves2bfloat162(l[0], l[1]);
    *(__nv_bfloat162*)&lo[4 * i + 2] = __halves2bfloat162(l[2], l[3]);
}

// ---------------- GEMM: out = A[M,K] @ W[N,K]^T + bias (bf16 split-3) ------
// 128x128 tile, BK=32, 8 warps (2x4), each warp 64x32 via m16n8k16.
template <int HEADOUT>
__global__ __launch_bounds__(256) void mma_gemm(
    const __nv_bfloat16* __restrict__ Ahi, const __nv_bfloat16* __restrict__ Alo,
    const __nv_bfloat16* __restrict__ Bhi, const __nv_bfloat16* __restrict__ Blo,
    const float* __restrict__ bias, float* __restrict__ out)
{
    __shared__ __nv_bfloat16 sA[2][128 * 40];
    __shared__ __nv_bfloat16 sB[2][128 * 40];
    const int tid = threadIdx.x, lane = tid & 31, warp = tid >> 5;
    const int wm = warp >> 2, wn = warp & 3;
    const int m0 = blockIdx.y * 128, n0 = blockIdx.x * 128;

    float d[4][4][4] = {};

    for (int kt = 0; kt < DMODEL; kt += 32) {
#pragma unroll
        for (int i = 0; i < 2; ++i) {
            int u = tid + i * 256;
            int r = u >> 2, c8 = (u & 3) * 8;
            size_t ga = (size_t)(m0 + r) * DMODEL + kt + c8;
            size_t gb = (size_t)(n0 + r) * DMODEL + kt + c8;
            *(uint4*)&sA[0][r * 40 + c8] = *(const uint4*)&Ahi[ga];
            *(uint4*)&sA[1][r * 40 + c8] = *(const uint4*)&Alo[ga];
            *(uint4*)&sB[0][r * 40 + c8] = *(const uint4*)&Bhi[gb];
            *(uint4*)&sB[1][r * 40 + c8] = *(const uint4*)&Blo[gb];
        }
        __syncthreads();
#pragma unroll
        for (int ks = 0; ks < 32; ks += 16) {
            unsigned ah[4][4], al[4][4];
#pragma unroll
            for (int i = 0; i < 4; ++i) {
                int row = wm * 64 + i * 16 + (lane & 15);
                int col = ks + (lane >> 4) * 8;
                ldsm4(ah[i], smem_u32(&sA[0][row * 40 + col]));
                ldsm4(al[i], smem_u32(&sA[1][row * 40 + col]));
            }
#pragma unroll
            for (int g = 0; g < 2; ++g) {
                int row = wn * 32 + g * 16 + (lane & 7) + ((lane & 16) >> 1);
                int col = ks + ((lane >> 3) & 1) * 8;
                unsigned bhr[4], blr[4];
                ldsm4(bhr, smem_u32(&sB[0][row * 40 + col]));
                ldsm4(blr, smem_u32(&sB[1][row * 40 + col]));
#pragma unroll
                for (int i = 0; i < 4; ++i) {
                    mma_bf16(d[i][2 * g],     ah[i], bhr[0], bhr[1]);
                    mma_bf16(d[i][2 * g],     ah[i], blr[0], blr[1]);
                    mma_bf16(d[i][2 * g],     al[i], bhr[0], bhr[1]);
                    mma_bf16(d[i][2 * g + 1], ah[i], bhr[2], bhr[3]);
                    mma_bf16(d[i][2 * g + 1], ah[i], blr[2], blr[3]);
                    mma_bf16(d[i][2 * g + 1], al[i], bhr[2], bhr[3]);
                }
            }
        }
        __syncthreads();
    }

#pragma unroll
    for (int i = 0; i < 4; ++i) {
#pragma unroll
        for (int j = 0; j < 4; ++j) {
            int c = n0 + wn * 32 + j * 8 + (lane & 3) * 2;
            float b0 = bias[c], b1 = bias[c + 1];
#pragma unroll
            for (int h = 0; h < 2; ++h) {
                int m = m0 + wm * 64 + i * 16 + (lane >> 2) + 8 * h;
                float2 r = make_float2(d[i][j][2 * h] + b0, d[i][j][2 * h + 1] + b1);
                if (HEADOUT) {
                    int bb = m >> 11, s = m & 2047, hh = c >> 6, dd = c & 63;
                    *(float2*)&out[(((size_t)(bb * NHEAD + hh)) * S_LEN + s) * DKH + dd] = r;
                } else {
                    *(float2*)&out[(size_t)m * DMODEL + c] = r;
                }
            }
        }
    }
}

// ---------------- prep: q/k fp32 [row][64] -> hi/lo bf16 [row][80] ----------
// dims 0..63 = values, 64 = sum/8, 65 = alt-sum/8, 66..79 = 0
__global__ void prep_qk(const float* __restrict__ q,
                        __nv_bfloat16* __restrict__ hi,
                        __nv_bfloat16* __restrict__ lo) {
    int row = blockIdx.x * 8 + (threadIdx.x >> 5);
    int lane = threadIdx.x & 31;
    const float* src = q + (size_t)row * DKH;
    float v0 = src[lane], v1 = src[lane + 32];
    float a = v0 + v1;
    float b = (lane & 1) ? -(v0 + v1) : (v0 + v1);
#pragma unroll
    for (int o = 16; o >= 1; o >>= 1) {
        a += __shfl_xor_sync(0xffffffffu, a, o);
        b += __shfl_xor_sync(0xffffffffu, b, o);
    }
    a *= 0.125f; b *= 0.125f;
    size_t ob = (size_t)row * DKP;
    __nv_bfloat16 h0 = __float2bfloat16(v0);
    __nv_bfloat16 h1 = __float2bfloat16(v1);
    hi[ob + lane]      = h0;
    lo[ob + lane]      = __float2bfloat16(v0 - __bfloat162float(h0));
    hi[ob + lane + 32] = h1;
    lo[ob + lane + 32] = __float2bfloat16(v1 - __bfloat162float(h1));
    if (lane < 16) {
        float e = (lane == 0) ? a : (lane == 1) ? b : 0.f;
        __nv_bfloat16 eh = __float2bfloat16(e);
        hi[ob + 64 + lane] = eh;
        lo[ob + 64 + lane] = __float2bfloat16(e - __bfloat162float(eh));
    }
}

// ---------------- prep: v fp32 [bh][s][64] -> vt hi/lo bf16 [bh][d][s] ------
__global__ void prep_vt(const float* __restrict__ v,
                        __nv_bfloat16* __restrict__ hi,
                        __nv_bfloat16* __restrict__ lo) {
    __shared__ float sm[64 * 68];     // [d][s] tile, padded
    const int bh = blockIdx.y, s0 = blockIdx.x * 64;
    const int tid = threadIdx.x;
    const float* src = v + ((size_t)bh * S_LEN + s0) * DKH;
#pragma unroll
    for (int i = 0; i < 4; ++i) {
        int u = tid + i * 256;
        int s = u >> 4, d4 = (u & 15) * 4;
        float4 val = *(const float4*)&src[s * DKH + d4];
        sm[(d4 + 0) * 68 + s] = val.x;
        sm[(d4 + 1) * 68 + s] = val.y;
        sm[(d4 + 2) * 68 + s] = val.z;
        sm[(d4 + 3) * 68 + s] = val.w;
    }
    __syncthreads();
#pragma unroll
    for (int i = 0; i < 4; ++i) {
        int u = tid + i * 256;
        int dd = (u >> 4) & 63;       // 2 d-values per warp
        int s4 = (u & 15) * 4;
        // remap so each 1024-range covers all (d, s4)
        dd = u >> 4; s4 = (u & 15) * 4;
        float4 f = *(const float4*)&sm[dd * 68 + s4];
        float vv[4] = {f.x, f.y, f.z, f.w};
        __nv_bfloat16 h[4], l[4];
#pragma unroll
        for (int j = 0; j < 4; ++j) {
            h[j] = __float2bfloat16(vv[j]);
            l[j] = __float2bfloat16(vv[j] - __bfloat162float(h[j]));
        }
        size_t ob = ((size_t)bh * DKH + dd) * S_LEN + s0 + s4;
        *(__nv_bfloat162*)&hi[ob]     = __halves2bfloat162(h[0], h[1]);
        *(__nv_bfloat162*)&hi[ob + 2] = __halves2bfloat162(h[2], h[3]);
        *(__nv_bfloat162*)&lo[ob]     = __halves2bfloat162(l[0], l[1]);
        *(__nv_bfloat162*)&lo[ob + 2] = __halves2bfloat162(l[2], l[3]);
    }
}

// ---------------- attention: warp-mma flash, bf16 split-3 -------------------
// CTA: 128 queries, 8 warps (16 q-rows each). Key tiles of 128. DKP=80.
#define ATT_SMEM_BYTES ((2 * 128 * 88 + 2 * 64 * 136) * 2)

__global__ __launch_bounds__(256, 1) void attn_mma(
    const __nv_bfloat16* __restrict__ qhi, const __nv_bfloat16* __restrict__ qlo,
    const __nv_bfloat16* __restrict__ khi, const __nv_bfloat16* __restrict__ klo,
    const __nv_bfloat16* __restrict__ vhi, const __nv_bfloat16* __restrict__ vlo,
    __nv_bfloat16* __restrict__ ohi, __nv_bfloat16* __restrict__ olo)
{
    extern __shared__ __nv_bfloat16 smn[];
    __nv_bfloat16* sK0 = smn;
    __nv_bfloat16* sK1 = smn + 128 * 88;
    __nv_bfloat16* sV0 = smn + 2 * 128 * 88;
    __nv_bfloat16* sV1 = smn + 2 * 128 * 88 + 64 * 136;

    const int tid = threadIdx.x, lane = tid & 31, warp = tid >> 5;
    const int bh = blockIdx.y, q0 = blockIdx.x * 128;
    const __nv_bfloat16* qh = qhi + (size_t)bh * S_LEN * DKP;
    const __nv_bfloat16* ql = qlo + (size_t)bh * S_LEN * DKP;
    const __nv_bfloat16* kh = khi + (size_t)bh * S_LEN * DKP;
    const __nv_bfloat16* kl = klo + (size_t)bh * S_LEN * DKP;
    const __nv_bfloat16* vh = vhi + (size_t)bh * DKH * S_LEN;
    const __nv_bfloat16* vl = vlo + (size_t)bh * DKH * S_LEN;

    // stage Q tile into sK buffers, extract persistent Q fragments
#pragma unroll
    for (int i = 0; i < 10; ++i) {
        int u = tid + i * 256;                  // 0..2559
        int buf = u / 1280, rem = u - buf * 1280;
        int r = rem / 10, c8 = (rem - r * 10) * 8;
        const __nv_bfloat16* src = buf ? ql : qh;
        __nv_bfloat16* dst = buf ? sK1 : sK0;
        *(uint4*)&dst[r * 88 + c8] = *(const uint4*)&src[(size_t)(q0 + r) * DKP + c8];
    }
    __syncthreads();
    unsigned qf[2][5][4];
#pragma unroll
    for (int ks = 0; ks < 5; ++ks) {
        int row = warp * 16 + (lane & 15);
        int col = ks * 16 + (lane >> 4) * 8;
        ldsm4(qf[0][ks], smem_u32(&sK0[row * 88 + col]));
        ldsm4(qf[1][ks], smem_u32(&sK1[row * 88 + col]));
    }
    __syncthreads();

    float m_[2] = {-1e30f, -1e30f}, l_[2] = {0.f, 0.f};
    float o[8][4] = {};

    for (int kt = 0; kt < S_LEN; kt += 128) {
        // load K (128x80 hi/lo) and Vt (64x128 hi/lo)
#pragma unroll
        for (int i = 0; i < 10; ++i) {
            int u = tid + i * 256;
            int buf = u / 1280, rem = u - buf * 1280;
            int r = rem / 10, c8 = (rem - r * 10) * 8;
            const __nv_bfloat16* src = buf ? kl : kh;
            __nv_bfloat16* dst = buf ? sK1 : sK0;
            *(uint4*)&dst[r * 88 + c8] = *(const uint4*)&src[(size_t)(kt + r) * DKP + c8];
        }
#pragma unroll
        for (int i = 0; i < 8; ++i) {
            int u = tid + i * 256;
            int buf = u >> 10, rem = u & 1023;
            int r = rem >> 4, c8 = (rem & 15) * 8;
            const __nv_bfloat16* src = buf ? vl : vh;
            __nv_bfloat16* dst = buf ? sV1 : sV0;
            *(uint4*)&dst[r * 136 + c8] = *(const uint4*)&src[(size_t)r * S_LEN + kt + c8];
        }
        __syncthreads();

        // scores: 16 rows x 128 keys per warp
        float sc[16][4] = {};
#pragma unroll
        for (int g = 0; g < 8; ++g) {
#pragma unroll
            for (int ks = 0; ks < 5; ++ks) {
                int row = g * 16 + (lane & 7) + ((lane & 16) >> 1);
                int col = ks * 16 + ((lane >> 3) & 1) * 8;
                unsigned kbh[4], kbl[4];
                ldsm4(kbh, smem_u32(&sK0[row * 88 + col]));
                ldsm4(kbl, smem_u32(&sK1[row * 88 + col]));
                mma_bf16(sc[2 * g],     qf[0][ks], kbh[0], kbh[1]);
                mma_bf16(sc[2 * g],     qf[0][ks], kbl[0], kbl[1]);
                mma_bf16(sc[2 * g],     qf[1][ks], kbh[0], kbh[1]);
                mma_bf16(sc[2 * g + 1], qf[0][ks], kbh[2], kbh[3]);
                mma_bf16(sc[2 * g + 1], qf[0][ks], kbl[2], kbl[3]);
                mma_bf16(sc[2 * g + 1], qf[1][ks], kbh[2], kbh[3]);
            }
        }
#pragma unroll
        for (int t = 0; t < 16; ++t)
#pragma unroll
            for (int j = 0; j < 4; ++j) sc[t][j] *= 0.0625f;

        // online softmax per row-half (rows lane/4 and lane/4+8)
        float corr[2];
#pragma unroll
        for (int h = 0; h < 2; ++h) {
            float mt = -1e30f;
#pragma unroll
            for (int t = 0; t < 16; ++t)
                mt = fmaxf(mt, fmaxf(sc[t][2 * h], sc[t][2 * h + 1]));
            mt = fmaxf(mt, __shfl_xor_sync(0xffffffffu, mt, 1));
            mt = fmaxf(mt, __shfl_xor_sync(0xffffffffu, mt, 2));
            float mn = fmaxf(m_[h], mt);
            float sum = 0.f;
#pragma unroll
            for (int t = 0; t < 16; ++t) {
                sc[t][2 * h]     = exp2f((sc[t][2 * h]     - mn) * 1.44269504f);
                sc[t][2 * h + 1] = exp2f((sc[t][2 * h + 1] - mn) * 1.44269504f);
                sum += sc[t][2 * h] + sc[t][2 * h + 1];
            }
            sum += __shfl_xor_sync(0xffffffffu, sum, 1);
            sum += __shfl_xor_sync(0xffffffffu, sum, 2);
            corr[h] = exp2f((m_[h] - mn) * 1.44269504f);
            l_[h] = l_[h] * corr[h] + sum;
            m_[h] = mn;
        }
#pragma unroll
        for (int t = 0; t < 8; ++t) {
            o[t][0] *= corr[0]; o[t][1] *= corr[0];
            o[t][2] *= corr[1]; o[t][3] *= corr[1];
        }

        // PV: P (16x128) x V (128x64), P fragments straight from sc layout
#pragma unroll
        for (int ks = 0; ks < 8; ++ks) {
            unsigned ph[4], pl[4];
            split_pack(sc[2 * ks][0],     sc[2 * ks][1],     ph[0], pl[0]);
            split_pack(sc[2 * ks][2],     sc[2 * ks][3],     ph[1], pl[1]);
            split_pack(sc[2 * ks + 1][0], sc[2 * ks + 1][1], ph[2], pl[2]);
            split_pack(sc[2 * ks + 1][2], sc[2 * ks + 1][3], ph[3], pl[3]);
#pragma unroll
            for (int g = 0; g < 4; ++g) {
                int row = g * 16 + (lane & 7) + ((lane & 16) >> 1);
                int col = ks * 16 + ((lane >> 3) & 1) * 8;
                unsigned vbh[4], vbl[4];
                ldsm4(vbh, smem_u32(&sV0[row * 136 + col]));
                ldsm4(vbl, smem_u32(&sV1[row * 136 + col]));
                mma_bf16(o[2 * g],     ph, vbh[0], vbh[1]);
                mma_bf16(o[2 * g],     ph, vbl[0], vbl[1]);
                mma_bf16(o[2 * g],     pl, vbh[0], vbh[1]);
                mma_bf16(o[2 * g + 1], ph, vbh[2], vbh[3]);
                mma_bf16(o[2 * g + 1], ph, vbl[2], vbl[3]);
                mma_bf16(o[2 * g + 1], pl, vbh[2], vbh[3]);
            }
        }
        __syncthreads();
    }

    // epilogue: normalize, split to bf16 hi/lo in plain [B*S, D] layout
    const int b = bh >> 4, head = bh & 15;
#pragma unroll
    for (int h = 0; h < 2; ++h) {
        float inv = 1.f / l_[h];
        int s = q0 + warp * 16 + (lane >> 2) + 8 * h;
        size_t rowbase = ((size_t)(b * S_LEN + s)) * DMODEL + head * DKH;
#pragma unroll
        for (int t = 0; t < 8; ++t) {
            int dd = t * 8 + (lane & 3) * 2;
            unsigned H, L;
            split_pack(o[t][2 * h] * inv, o[t][2 * h + 1] * inv, H, L);
            *(unsigned*)&ohi[rowbase + dd] = H;
            *(unsigned*)&olo[rowbase + dd] = L;
        }
    }
}

// ---------------- launch ----------------
extern "C" void kernel_launch(void* const* d_in, const int* in_sizes, int n_in,
                              void* d_out, int out_size)
{
    const float* x  = (const float*)d_in[0];
    const float* Wq = (const float*)d_in[1];
    const float* bq = (const float*)d_in[2];
    const float* Wk = (const float*)d_in[3];
    const float* bk = (const float*)d_in[4];
    const float* Wv = (const float*)d_in[5];
    const float* bv = (const float*)d_in[6];
    const float* Wo = (const float*)d_in[7];
    const float* bo = (const float*)d_in[8];
    float* out = (float*)d_out;

    __nv_bfloat16 *xhi, *xlo, *whi, *wlo, *qahi, *qalo, *kahi, *kalo,
                  *vthi, *vtlo, *ahi, *alo;
    float *qp, *kp, *vp;
    cudaGetSymbolAddress((void**)&xhi, g_xhi);
    cudaGetSymbolAddress((void**)&xlo, g_xlo);
    cudaGetSymbolAddress((void**)&whi, g_whi);
    cudaGetSymbolAddress((void**)&wlo, g_wlo);
    cudaGetSymbolAddress((void**)&qp, g_q);
    cudaGetSymbolAddress((void**)&kp, g_k);
    cudaGetSymbolAddress((void**)&vp, g_v);
    cudaGetSymbolAddress((void**)&qahi, g_qahi);
    cudaGetSymbolAddress((void**)&qalo, g_qalo);
    cudaGetSymbolAddress((void**)&kahi, g_kahi);
    cudaGetSymbolAddress((void**)&kalo, g_kalo);
    cudaGetSymbolAddress((void**)&vthi, g_vthi);
    cudaGetSymbolAddress((void**)&vtlo, g_vtlo);
    cudaGetSymbolAddress((void**)&ahi, g_ahi);
    cudaGetSymbolAddress((void**)&alo, g_alo);

    const int WSZ = DMODEL * DMODEL;
    // splits
    split_kernel<<<(M_TOT * DMODEL / 4 + 255) / 256, 256>>>(x, xhi, xlo, M_TOT * DMODEL / 4);
    split_kernel<<<(WSZ / 4 + 255) / 256, 256>>>(Wq, whi + 0 * WSZ, wlo + 0 * WSZ, WSZ / 4);
    split_kernel<<<(WSZ / 4 + 255) / 256, 256>>>(Wk, whi + 1 * WSZ, wlo + 1 * WSZ, WSZ / 4);
    split_kernel<<<(WSZ / 4 + 255) / 256, 256>>>(Wv, whi + 2 * WSZ, wlo + 2 * WSZ, WSZ / 4);
    split_kernel<<<(WSZ / 4 + 255) / 256, 256>>>(Wo, whi + 3 * WSZ, wlo + 3 * WSZ, WSZ / 4);

    dim3 gg(DMODEL / 128, M_TOT / 128);
    mma_gemm<1><<<gg, 256>>>(xhi, xlo, whi + 0 * WSZ, wlo + 0 * WSZ, bq, qp);
    mma_gemm<1><<<gg, 256>>>(xhi, xlo, whi + 1 * WSZ, wlo + 1 * WSZ, bk, kp);
    mma_gemm<1><<<gg, 256>>>(xhi, xlo, whi + 2 * WSZ, wlo + 2 * WSZ, bv, vp);

    prep_qk<<<BH * S_LEN / 8, 256>>>(qp, qahi, qalo);
    prep_qk<<<BH * S_LEN / 8, 256>>>(kp, kahi, kalo);
    prep_vt<<<dim3(S_LEN / 64, BH), 256>>>(vp, vthi, vtlo);

    cudaFuncSetAttribute(attn_mma, cudaFuncAttributeMaxDynamicSharedMemorySize,
                         ATT_SMEM_BYTES);
    attn_mma<<<dim3(S_LEN / 128, BH), 256, ATT_SMEM_BYTES>>>(
        qahi, qalo, kahi, kalo, vthi, vtlo, ahi, alo);

    mma_gemm<0><<<gg, 256>>>(ahi, alo, whi + 3 * WSZ, wlo + 3 * WSZ, bo, out);
}

// round 4
// speedup vs baseline: 2.9886x; 1.1775x over previous
#include <cuda_runtime.h>
#include <cuda_bf16.h>
#include <cstdint>

#define BATCH  2
#define S_LEN  2048
#define DMODEL 1024
#define NHEAD  16
#define DKH    64
#define M_TOT  (BATCH * S_LEN)
#define BH     (BATCH * NHEAD)

// ---------------- scratch (device globals; allocation-free) ----------------
__device__ __align__(16) __nv_bfloat16 g_xhi[M_TOT * DMODEL];
__device__ __align__(16) __nv_bfloat16 g_xlo[M_TOT * DMODEL];
__device__ __align__(16) __nv_bfloat16 g_whi[4][DMODEL * DMODEL];
__device__ __align__(16) __nv_bfloat16 g_wlo[4][DMODEL * DMODEL];
__device__ __align__(16) float g_q[BH * S_LEN * DKH];
__device__ __align__(16) float g_k[BH * S_LEN * DKH];
__device__ __align__(16) float g_v[BH * S_LEN * DKH];
__device__ __align__(16) __nv_bfloat16 g_qahi[BH * S_LEN * DKH];
__device__ __align__(16) __nv_bfloat16 g_qalo[BH * S_LEN * DKH];
__device__ __align__(16) __nv_bfloat16 g_kahi[BH * S_LEN * DKH];
__device__ __align__(16) __nv_bfloat16 g_kalo[BH * S_LEN * DKH];
__device__ __align__(16) __nv_bfloat16 g_vthi[BH * DKH * S_LEN];   // [bh][d][s]
__device__ __align__(16) __nv_bfloat16 g_vtlo[BH * DKH * S_LEN];
__device__ __align__(16) __nv_bfloat16 g_ahi[M_TOT * DMODEL];
__device__ __align__(16) __nv_bfloat16 g_alo[M_TOT * DMODEL];

// ---------------- helpers ----------------
__device__ __forceinline__ unsigned smem_u32(const void* p) {
    return (unsigned)__cvta_generic_to_shared(p);
}
__device__ __forceinline__ void ldsm4(unsigned* r, unsigned addr) {
    asm volatile("ldmatrix.sync.aligned.m8n8.x4.shared.b16 {%0,%1,%2,%3}, [%4];\n"
                 : "=r"(r[0]), "=r"(r[1]), "=r"(r[2]), "=r"(r[3]) : "r"(addr));
}
__device__ __forceinline__ void mma_bf16(float* c, const unsigned* a, unsigned b0, unsigned b1) {
    asm volatile("mma.sync.aligned.m16n8k16.row.col.f32.bf16.bf16.f32 "
                 "{%0,%1,%2,%3}, {%4,%5,%6,%7}, {%8,%9}, {%0,%1,%2,%3};\n"
                 : "+f"(c[0]), "+f"(c[1]), "+f"(c[2]), "+f"(c[3])
                 : "r"(a[0]), "r"(a[1]), "r"(a[2]), "r"(a[3]), "r"(b0), "r"(b1));
}
__device__ __forceinline__ void split_pack(float x, float y, unsigned& hi, unsigned& lo) {
    __nv_bfloat16 hx = __float2bfloat16(x), hy = __float2bfloat16(y);
    __nv_bfloat16 lx = __float2bfloat16(x - __bfloat162float(hx));
    __nv_bfloat16 ly = __float2bfloat16(y - __bfloat162float(hy));
    __nv_bfloat162 H = __halves2bfloat162(hx, hy);
    __nv_bfloat162 L = __halves2bfloat162(lx, ly);
    hi = *(unsigned*)&H; lo = *(unsigned*)&L;
}
#define CP16(dst, src) \
    asm volatile("cp.async.cg.shared.global [%0], [%1], 16;\n" :: "r"(dst), "l"(src))
#define CP_COMMIT() asm volatile("cp.async.commit_group;\n" ::: "memory")
#define CP_WAIT1()  asm volatile("cp.async.wait_group 1;\n" ::: "memory")
#define CP_WAIT0()  asm volatile("cp.async.wait_group 0;\n" ::: "memory")

// ---------------- elementwise fp32 -> bf16 hi/lo split ----------------
__global__ void split_kernel(const float* __restrict__ in,
                             __nv_bfloat16* __restrict__ hi,
                             __nv_bfloat16* __restrict__ lo, int n4) {
    int i = blockIdx.x * blockDim.x + threadIdx.x;
    if (i >= n4) return;
    float4 v = ((const float4*)in)[i];
    float vv[4] = {v.x, v.y, v.z, v.w};
    __nv_bfloat16 h[4], l[4];
#pragma unroll
    for (int j = 0; j < 4; ++j) {
        h[j] = __float2bfloat16(vv[j]);
        l[j] = __float2bfloat16(vv[j] - __bfloat162float(h[j]));
    }
    *(__nv_bfloat162*)&hi[4 * i]     = __halves2bfloat162(h[0], h[1]);
    *(__nv_bfloat162*)&hi[4 * i + 2] = __halves2bfloat162(h[2], h[3]);
    *(__nv_bfloat162*)&lo[4 * i]     = __halves2bfloat162(l[0], l[1]);
    *(__nv_bfloat162*)&lo[4 * i + 2] = __halves2bfloat162(l[2], l[3]);
}

// ---------------- GEMM: out = A @ W^T + bias (bf16 split-3, cp.async x2) ----
// 128x128 tile, BK=32, 2-stage pipeline. Stage layout (bytes, stride 80/row):
//   Ahi @0, Alo @10240, Bhi @20480, Blo @30720; stage size 40960.
#define G_STAGE 40960
#define GEMM_SMEM (2 * G_STAGE)

template <int HEADOUT>
__global__ __launch_bounds__(256) void mma_gemm(
    const __nv_bfloat16* __restrict__ Ahi, const __nv_bfloat16* __restrict__ Alo,
    const __nv_bfloat16* __restrict__ Bhi, const __nv_bfloat16* __restrict__ Blo,
    const float* __restrict__ bias, float* __restrict__ out)
{
    extern __shared__ char sm[];
    const int tid = threadIdx.x, lane = tid & 31, warp = tid >> 5;
    const int wm = warp >> 2, wn = warp & 3;
    const int m0 = blockIdx.y * 128, n0 = blockIdx.x * 128;

    auto load_stage = [&](int st, int kt) {
        char* base = sm + st * G_STAGE;
#pragma unroll
        for (int i = 0; i < 2; ++i) {
            int u = tid + i * 256;            // 0..511
            int r = u >> 2, c = u & 3;        // r 0..127, chunk 0..3
            unsigned off = (unsigned)(r * 80 + c * 16);
            const char* pa = (const char*)(Ahi + (size_t)(m0 + r) * DMODEL + kt) + c * 16;
            const char* pb = (const char*)(Alo + (size_t)(m0 + r) * DMODEL + kt) + c * 16;
            const char* pc = (const char*)(Bhi + (size_t)(n0 + r) * DMODEL + kt) + c * 16;
            const char* pd = (const char*)(Blo + (size_t)(n0 + r) * DMODEL + kt) + c * 16;
            CP16(smem_u32(base + off), pa);
            CP16(smem_u32(base + 10240 + off), pb);
            CP16(smem_u32(base + 20480 + off), pc);
            CP16(smem_u32(base + 30720 + off), pd);
        }
    };

    float d[4][4][4] = {};

    load_stage(0, 0);
    CP_COMMIT();

    for (int kb = 0; kb < 32; ++kb) {
        const int st = kb & 1;
        if (kb + 1 < 32) {
            load_stage(st ^ 1, (kb + 1) * 32);
            CP_COMMIT();
            CP_WAIT1();
        } else {
            CP_WAIT0();
        }
        __syncthreads();

        char* base = sm + st * G_STAGE;
#pragma unroll
        for (int ks = 0; ks < 32; ks += 16) {
            unsigned ah[4][4], al[4][4];
#pragma unroll
            for (int i = 0; i < 4; ++i) {
                int row = wm * 64 + i * 16 + (lane & 15);
                int col = ks + (lane >> 4) * 8;
                ldsm4(ah[i], smem_u32(base + row * 80 + col * 2));
                ldsm4(al[i], smem_u32(base + 10240 + row * 80 + col * 2));
            }
#pragma unroll
            for (int g = 0; g < 2; ++g) {
                int row = wn * 32 + g * 16 + (lane & 7) + ((lane & 16) >> 1);
                int col = ks + ((lane >> 3) & 1) * 8;
                unsigned bhr[4], blr[4];
                ldsm4(bhr, smem_u32(base + 20480 + row * 80 + col * 2));
                ldsm4(blr, smem_u32(base + 30720 + row * 80 + col * 2));
#pragma unroll
                for (int i = 0; i < 4; ++i) {
                    mma_bf16(d[i][2 * g],     ah[i], bhr[0], bhr[1]);
                    mma_bf16(d[i][2 * g],     ah[i], blr[0], blr[1]);
                    mma_bf16(d[i][2 * g],     al[i], bhr[0], bhr[1]);
                    mma_bf16(d[i][2 * g + 1], ah[i], bhr[2], bhr[3]);
                    mma_bf16(d[i][2 * g + 1], ah[i], blr[2], blr[3]);
                    mma_bf16(d[i][2 * g + 1], al[i], bhr[2], bhr[3]);
                }
            }
        }
        __syncthreads();
    }

#pragma unroll
    for (int i = 0; i < 4; ++i) {
#pragma unroll
        for (int j = 0; j < 4; ++j) {
            int c = n0 + wn * 32 + j * 8 + (lane & 3) * 2;
            float b0 = bias[c], b1 = bias[c + 1];
#pragma unroll
            for (int h = 0; h < 2; ++h) {
                int m = m0 + wm * 64 + i * 16 + (lane >> 2) + 8 * h;
                float2 r = make_float2(d[i][j][2 * h] + b0, d[i][j][2 * h + 1] + b1);
                if (HEADOUT) {
                    int bb = m >> 11, s = m & 2047, hh = c >> 6, dd = c & 63;
                    *(float2*)&out[(((size_t)(bb * NHEAD + hh)) * S_LEN + s) * DKH + dd] = r;
                } else {
                    *(float2*)&out[(size_t)m * DMODEL + c] = r;
                }
            }
        }
    }
}

// ---------------- prep: fold Fourier rank-2 into q/k, split to bf16 --------
// q'_d = q_d + u*(a + (-1)^d b), a=sum(q)/8, b=sum((-1)^d q)/8, u=(sqrt2-1)/8
__global__ void prep_qk(const float* __restrict__ q,
                        __nv_bfloat16* __restrict__ hi,
                        __nv_bfloat16* __restrict__ lo) {
    int row = blockIdx.x * 8 + (threadIdx.x >> 5);
    int lane = threadIdx.x & 31;
    const float* src = q + (size_t)row * DKH;
    float v0 = src[lane], v1 = src[lane + 32];
    float a = v0 + v1;
    float b = (lane & 1) ? -(v0 + v1) : (v0 + v1);
#pragma unroll
    for (int o = 16; o >= 1; o >>= 1) {
        a += __shfl_xor_sync(0xffffffffu, a, o);
        b += __shfl_xor_sync(0xffffffffu, b, o);
    }
    const float u = 0.05177669529663689f;   // (sqrt(2)-1)/8
    float adj = u * 0.125f * (a + ((lane & 1) ? -b : b));
    v0 += adj; v1 += adj;
    size_t ob = (size_t)row * DKH;
    __nv_bfloat16 h0 = __float2bfloat16(v0);
    __nv_bfloat16 h1 = __float2bfloat16(v1);
    hi[ob + lane]      = h0;
    lo[ob + lane]      = __float2bfloat16(v0 - __bfloat162float(h0));
    hi[ob + lane + 32] = h1;
    lo[ob + lane + 32] = __float2bfloat16(v1 - __bfloat162float(h1));
}

// ---------------- prep: v fp32 [bh][s][64] -> vt hi/lo bf16 [bh][d][s] ------
__global__ void prep_vt(const float* __restrict__ v,
                        __nv_bfloat16* __restrict__ hi,
                        __nv_bfloat16* __restrict__ lo) {
    __shared__ float smv[64 * 68];
    const int bh = blockIdx.y, s0 = blockIdx.x * 64;
    const int tid = threadIdx.x;
    const float* src = v + ((size_t)bh * S_LEN + s0) * DKH;
#pragma unroll
    for (int i = 0; i < 4; ++i) {
        int u = tid + i * 256;
        int s = u >> 4, d4 = (u & 15) * 4;
        float4 val = *(const float4*)&src[s * DKH + d4];
        smv[(d4 + 0) * 68 + s] = val.x;
        smv[(d4 + 1) * 68 + s] = val.y;
        smv[(d4 + 2) * 68 + s] = val.z;
        smv[(d4 + 3) * 68 + s] = val.w;
    }
    __syncthreads();
#pragma unroll
    for (int i = 0; i < 4; ++i) {
        int u = tid + i * 256;
        int dd = u >> 4, s4 = (u & 15) * 4;
        float4 f = *(const float4*)&smv[dd * 68 + s4];
        float vv[4] = {f.x, f.y, f.z, f.w};
        __nv_bfloat16 h[4], l[4];
#pragma unroll
        for (int j = 0; j < 4; ++j) {
            h[j] = __float2bfloat16(vv[j]);
            l[j] = __float2bfloat16(vv[j] - __bfloat162float(h[j]));
        }
        size_t ob = ((size_t)bh * DKH + dd) * S_LEN + s0 + s4;
        *(__nv_bfloat162*)&hi[ob]     = __halves2bfloat162(h[0], h[1]);
        *(__nv_bfloat162*)&hi[ob + 2] = __halves2bfloat162(h[2], h[3]);
        *(__nv_bfloat162*)&lo[ob]     = __halves2bfloat162(l[0], l[1]);
        *(__nv_bfloat162*)&lo[ob + 2] = __halves2bfloat162(l[2], l[3]);
    }
}

// ---------------- attention: warp-mma flash, split-3, cp.async x2 ----------
// smem layout (bytes):
//   K: stage*2*18432 + buf*18432 + r*144 + c*2   (128 rows x 72 elems)
//   V: 73728 + stage*2*17408 + buf*17408 + r*272 + c*2  (64 rows x 136 elems)
#define K_BUF 18432
#define V_BUF 17408
#define V_BASE 73728
#define ATT_SMEM_BYTES (V_BASE + 4 * V_BUF)   // 143360

__global__ __launch_bounds__(256, 1) void attn_mma(
    const __nv_bfloat16* __restrict__ qhi, const __nv_bfloat16* __restrict__ qlo,
    const __nv_bfloat16* __restrict__ khi, const __nv_bfloat16* __restrict__ klo,
    const __nv_bfloat16* __restrict__ vhi, const __nv_bfloat16* __restrict__ vlo,
    __nv_bfloat16* __restrict__ ohi, __nv_bfloat16* __restrict__ olo)
{
    extern __shared__ char sm[];
    const int tid = threadIdx.x, lane = tid & 31, warp = tid >> 5;
    const int bh = blockIdx.y, q0 = blockIdx.x * 128;
    const __nv_bfloat16* qh = qhi + (size_t)bh * S_LEN * DKH;
    const __nv_bfloat16* ql = qlo + (size_t)bh * S_LEN * DKH;
    const __nv_bfloat16* kh = khi + (size_t)bh * S_LEN * DKH;
    const __nv_bfloat16* kl = klo + (size_t)bh * S_LEN * DKH;
    const __nv_bfloat16* vh = vhi + (size_t)bh * DKH * S_LEN;
    const __nv_bfloat16* vl = vlo + (size_t)bh * DKH * S_LEN;

    // ---- stage Q into K stage-0 buffers, extract persistent fragments ----
#pragma unroll
    for (int i = 0; i < 4; ++i) {
        int u = tid + i * 256;                // 0..1023
        int r = u >> 3, c = u & 7;
        unsigned off = (unsigned)(r * 144 + c * 16);
        *(uint4*)(sm + off) =
            *(const uint4*)((const char*)(qh + (size_t)(q0 + r) * DKH) + c * 16);
        *(uint4*)(sm + K_BUF + off) =
            *(const uint4*)((const char*)(ql + (size_t)(q0 + r) * DKH) + c * 16);
    }
    __syncthreads();
    unsigned qf[2][4][4];
#pragma unroll
    for (int ks = 0; ks < 4; ++ks) {
        int row = warp * 16 + (lane & 15);
        int col = ks * 16 + (lane >> 4) * 8;
        ldsm4(qf[0][ks], smem_u32(sm + row * 144 + col * 2));
        ldsm4(qf[1][ks], smem_u32(sm + K_BUF + row * 144 + col * 2));
    }
    __syncthreads();

    auto load_kv = [&](int st, int kt) {
        char* kb_ = sm + st * 2 * K_BUF;
#pragma unroll
        for (int i = 0; i < 4; ++i) {
            int u = tid + i * 256;
            int r = u >> 3, c = u & 7;
            unsigned off = (unsigned)(r * 144 + c * 16);
            CP16(smem_u32(kb_ + off),
                 (const char*)(kh + (size_t)(kt + r) * DKH) + c * 16);
            CP16(smem_u32(kb_ + K_BUF + off),
                 (const char*)(kl + (size_t)(kt + r) * DKH) + c * 16);
        }
        char* vb_ = sm + V_BASE + st * 2 * V_BUF;
#pragma unroll
        for (int i = 0; i < 4; ++i) {
            int u = tid + i * 256;
            int r = u >> 4, c = u & 15;
            unsigned off = (unsigned)(r * 272 + c * 16);
            CP16(smem_u32(vb_ + off),
                 (const char*)(vh + (size_t)r * S_LEN + kt) + c * 16);
            CP16(smem_u32(vb_ + V_BUF + off),
                 (const char*)(vl + (size_t)r * S_LEN + kt) + c * 16);
        }
    };

    float m_[2] = {-1e30f, -1e30f}, l_[2] = {0.f, 0.f};
    float o[8][4] = {};

    load_kv(0, 0);
    CP_COMMIT();

    for (int t = 0; t < 16; ++t) {
        const int st = t & 1;
        if (t + 1 < 16) {
            load_kv(st ^ 1, (t + 1) * 128);
            CP_COMMIT();
            CP_WAIT1();
        } else {
            CP_WAIT0();
        }
        __syncthreads();

        char* kb_ = sm + st * 2 * K_BUF;
        char* vb_ = sm + V_BASE + st * 2 * V_BUF;

        // ---- scores: 16 rows x 128 keys per warp ----
        float sc[16][4] = {};
#pragma unroll
        for (int g = 0; g < 8; ++g) {
#pragma unroll
            for (int ks = 0; ks < 4; ++ks) {
                int row = g * 16 + (lane & 7) + ((lane & 16) >> 1);
                int col = ks * 16 + ((lane >> 3) & 1) * 8;
                unsigned kbh[4], kbl[4];
                ldsm4(kbh, smem_u32(kb_ + row * 144 + col * 2));
                ldsm4(kbl, smem_u32(kb_ + K_BUF + row * 144 + col * 2));
                mma_bf16(sc[2 * g],     qf[0][ks], kbh[0], kbh[1]);
                mma_bf16(sc[2 * g],     qf[0][ks], kbl[0], kbl[1]);
                mma_bf16(sc[2 * g],     qf[1][ks], kbh[0], kbh[1]);
                mma_bf16(sc[2 * g + 1], qf[0][ks], kbh[2], kbh[3]);
                mma_bf16(sc[2 * g + 1], qf[0][ks], kbl[2], kbl[3]);
                mma_bf16(sc[2 * g + 1], qf[1][ks], kbh[2], kbh[3]);
            }
        }
#pragma unroll
        for (int tt = 0; tt < 16; ++tt)
#pragma unroll
            for (int j = 0; j < 4; ++j) sc[tt][j] *= 0.0625f;

        // ---- online softmax (rows lane/4 and lane/4+8) ----
        float corr[2];
#pragma unroll
        for (int h = 0; h < 2; ++h) {
            float mt = -1e30f;
#pragma unroll
            for (int tt = 0; tt < 16; ++tt)
                mt = fmaxf(mt, fmaxf(sc[tt][2 * h], sc[tt][2 * h + 1]));
            mt = fmaxf(mt, __shfl_xor_sync(0xffffffffu, mt, 1));
            mt = fmaxf(mt, __shfl_xor_sync(0xffffffffu, mt, 2));
            float mn = fmaxf(m_[h], mt);
            float sum = 0.f;
#pragma unroll
            for (int tt = 0; tt < 16; ++tt) {
                sc[tt][2 * h]     = exp2f((sc[tt][2 * h]     - mn) * 1.44269504f);
                sc[tt][2 * h + 1] = exp2f((sc[tt][2 * h + 1] - mn) * 1.44269504f);
                sum += sc[tt][2 * h] + sc[tt][2 * h + 1];
            }
            sum += __shfl_xor_sync(0xffffffffu, sum, 1);
            sum += __shfl_xor_sync(0xffffffffu, sum, 2);
            corr[h] = exp2f((m_[h] - mn) * 1.44269504f);
            l_[h] = l_[h] * corr[h] + sum;
            m_[h] = mn;
        }
#pragma unroll
        for (int tt = 0; tt < 8; ++tt) {
            o[tt][0] *= corr[0]; o[tt][1] *= corr[0];
            o[tt][2] *= corr[1]; o[tt][3] *= corr[1];
        }

        // ---- PV: P(16x128) x V(128x64), split-3 ----
#pragma unroll
        for (int ks = 0; ks < 8; ++ks) {
            unsigned ph_[4], pl_[4];
            split_pack(sc[2 * ks][0],     sc[2 * ks][1],     ph_[0], pl_[0]);
            split_pack(sc[2 * ks][2],     sc[2 * ks][3],     ph_[1], pl_[1]);
            split_pack(sc[2 * ks + 1][0], sc[2 * ks + 1][1], ph_[2], pl_[2]);
            split_pack(sc[2 * ks + 1][2], sc[2 * ks + 1][3], ph_[3], pl_[3]);
#pragma unroll
            for (int g = 0; g < 4; ++g) {
                int row = g * 16 + (lane & 7) + ((lane & 16) >> 1);
                int col = ks * 16 + ((lane >> 3) & 1) * 8;
                unsigned vbh[4], vbl[4];
                ldsm4(vbh, smem_u32(vb_ + row * 272 + col * 2));
                ldsm4(vbl, smem_u32(vb_ + V_BUF + row * 272 + col * 2));
                mma_bf16(o[2 * g],     ph_, vbh[0], vbh[1]);
                mma_bf16(o[2 * g],     ph_, vbl[0], vbl[1]);
                mma_bf16(o[2 * g],     pl_, vbh[0], vbh[1]);
                mma_bf16(o[2 * g + 1], ph_, vbh[2], vbh[3]);
                mma_bf16(o[2 * g + 1], ph_, vbl[2], vbl[3]);
                mma_bf16(o[2 * g + 1], pl_, vbh[2], vbh[3]);
            }
        }
        __syncthreads();
    }

    // ---- epilogue: normalize, split to bf16 hi/lo in plain [B*S, D] ----
    const int b = bh >> 4, head = bh & 15;
#pragma unroll
    for (int h = 0; h < 2; ++h) {
        float inv = 1.f / l_[h];
        int s = q0 + warp * 16 + (lane >> 2) + 8 * h;
        size_t rowbase = ((size_t)(b * S_LEN + s)) * DMODEL + head * DKH;
#pragma unroll
        for (int tt = 0; tt < 8; ++tt) {
            int dd = tt * 8 + (lane & 3) * 2;
            unsigned H, L;
            split_pack(o[tt][2 * h] * inv, o[tt][2 * h + 1] * inv, H, L);
            *(unsigned*)&ohi[rowbase + dd] = H;
            *(unsigned*)&olo[rowbase + dd] = L;
        }
    }
}

// ---------------- launch ----------------
extern "C" void kernel_launch(void* const* d_in, const int* in_sizes, int n_in,
                              void* d_out, int out_size)
{
    const float* x  = (const float*)d_in[0];
    const float* Wq = (const float*)d_in[1];
    const float* bq = (const float*)d_in[2];
    const float* Wk = (const float*)d_in[3];
    const float* bk = (const float*)d_in[4];
    const float* Wv = (const float*)d_in[5];
    const float* bv = (const float*)d_in[6];
    const float* Wo = (const float*)d_in[7];
    const float* bo = (const float*)d_in[8];
    float* out = (float*)d_out;

    __nv_bfloat16 *xhi, *xlo, *whi, *wlo, *qahi, *qalo, *kahi, *kalo,
                  *vthi, *vtlo, *ahi, *alo;
    float *qp, *kp, *vp;
    cudaGetSymbolAddress((void**)&xhi, g_xhi);
    cudaGetSymbolAddress((void**)&xlo, g_xlo);
    cudaGetSymbolAddress((void**)&whi, g_whi);
    cudaGetSymbolAddress((void**)&wlo, g_wlo);
    cudaGetSymbolAddress((void**)&qp, g_q);
    cudaGetSymbolAddress((void**)&kp, g_k);
    cudaGetSymbolAddress((void**)&vp, g_v);
    cudaGetSymbolAddress((void**)&qahi, g_qahi);
    cudaGetSymbolAddress((void**)&qalo, g_qalo);
    cudaGetSymbolAddress((void**)&kahi, g_kahi);
    cudaGetSymbolAddress((void**)&kalo, g_kalo);
    cudaGetSymbolAddress((void**)&vthi, g_vthi);
    cudaGetSymbolAddress((void**)&vtlo, g_vtlo);
    cudaGetSymbolAddress((void**)&ahi, g_ahi);
    cudaGetSymbolAddress((void**)&alo, g_alo);

    const int WSZ = DMODEL * DMODEL;
    split_kernel<<<(M_TOT * DMODEL / 4 + 255) / 256, 256>>>(x, xhi, xlo, M_TOT * DMODEL / 4);
    split_kernel<<<(WSZ / 4 + 255) / 256, 256>>>(Wq, whi + 0 * WSZ, wlo + 0 * WSZ, WSZ / 4);
    split_kernel<<<(WSZ / 4 + 255) / 256, 256>>>(Wk, whi + 1 * WSZ, wlo + 1 * WSZ, WSZ / 4);
    split_kernel<<<(WSZ / 4 + 255) / 256, 256>>>(Wv, whi + 2 * WSZ, wlo + 2 * WSZ, WSZ / 4);
    split_kernel<<<(WSZ / 4 + 255) / 256, 256>>>(Wo, whi + 3 * WSZ, wlo + 3 * WSZ, WSZ / 4);

    cudaFuncSetAttribute(mma_gemm<0>, cudaFuncAttributeMaxDynamicSharedMemorySize, GEMM_SMEM);
    cudaFuncSetAttribute(mma_gemm<1>, cudaFuncAttributeMaxDynamicSharedMemorySize, GEMM_SMEM);

    dim3 gg(DMODEL / 128, M_TOT / 128);   // (8, 32)
    mma_gemm<1><<<gg, 256, GEMM_SMEM>>>(xhi, xlo, whi + 0 * WSZ, wlo + 0 * WSZ, bq, qp);
    mma_gemm<1><<<gg, 256, GEMM_SMEM>>>(xhi, xlo, whi + 1 * WSZ, wlo + 1 * WSZ, bk, kp);
    mma_gemm<1><<<gg, 256, GEMM_SMEM>>>(xhi, xlo, whi + 2 * WSZ, wlo + 2 * WSZ, bv, vp);

    prep_qk<<<BH * S_LEN / 8, 256>>>(qp, qahi, qalo);
    prep_qk<<<BH * S_LEN / 8, 256>>>(kp, kahi, kalo);
    prep_vt<<<dim3(S_LEN / 64, BH), 256>>>(vp, vthi, vtlo);

    cudaFuncSetAttribute(attn_mma, cudaFuncAttributeMaxDynamicSharedMemorySize,
                         ATT_SMEM_BYTES);
    attn_mma<<<dim3(S_LEN / 128, BH), 256, ATT_SMEM_BYTES>>>(
        qahi, qalo, kahi, kalo, vthi, vtlo, ahi, alo);

    mma_gemm<0><<<gg, 256, GEMM_SMEM>>>(ahi, alo, whi + 3 * WSZ, wlo + 3 * WSZ, bo, out);
}

// round 6
// speedup vs baseline: 3.5439x; 1.1858x over previous
#include <cuda_runtime.h>
#include <cuda_bf16.h>
#include <cuda_fp16.h>
#include <cstdint>

#define BATCH  2
#define S_LEN  2048
#define DMODEL 1024
#define NHEAD  16
#define DKH    64
#define M_TOT  (BATCH * S_LEN)
#define BH     (BATCH * NHEAD)

// ---------------- scratch (device globals; allocation-free) ----------------
__device__ __align__(16) __nv_bfloat16 g_xhi[M_TOT * DMODEL];
__device__ __align__(16) __nv_bfloat16 g_xlo[M_TOT * DMODEL];
__device__ __align__(16) __nv_bfloat16 g_whi[3][DMODEL * DMODEL];
__device__ __align__(16) __nv_bfloat16 g_wlo[3][DMODEL * DMODEL];
__device__ __align__(16) __half g_wo16[DMODEL * DMODEL];
__device__ __align__(16) float g_q[BH * S_LEN * DKH];
__device__ __align__(16) float g_k[BH * S_LEN * DKH];
__device__ __align__(16) float g_v[BH * S_LEN * DKH];
__device__ __align__(16) __half g_qhi[BH * S_LEN * DKH];
__device__ __align__(16) __half g_qlo[BH * S_LEN * DKH];
__device__ __align__(16) __half g_k16[BH * S_LEN * DKH];
__device__ __align__(16) __half g_vt16[BH * DKH * S_LEN];   // [bh][d][s]
__device__ __align__(16) __half g_ahi[M_TOT * DMODEL];
__device__ __align__(16) __half g_alo[M_TOT * DMODEL];

// ---------------- helpers ----------------
__device__ __forceinline__ unsigned smem_u32(const void* p) {
    return (unsigned)__cvta_generic_to_shared(p);
}
__device__ __forceinline__ void ldsm4(unsigned* r, unsigned addr) {
    asm volatile("ldmatrix.sync.aligned.m8n8.x4.shared.b16 {%0,%1,%2,%3}, [%4];\n"
                 : "=r"(r[0]), "=r"(r[1]), "=r"(r[2]), "=r"(r[3]) : "r"(addr));
}
__device__ __forceinline__ void mma_bf16(float* c, const unsigned* a, unsigned b0, unsigned b1) {
    asm volatile("mma.sync.aligned.m16n8k16.row.col.f32.bf16.bf16.f32 "
                 "{%0,%1,%2,%3}, {%4,%5,%6,%7}, {%8,%9}, {%0,%1,%2,%3};\n"
                 : "+f"(c[0]), "+f"(c[1]), "+f"(c[2]), "+f"(c[3])
                 : "r"(a[0]), "r"(a[1]), "r"(a[2]), "r"(a[3]), "r"(b0), "r"(b1));
}
__device__ __forceinline__ void mma_f16(float* c, const unsigned* a, unsigned b0, unsigned b1) {
    asm volatile("mma.sync.aligned.m16n8k16.row.col.f32.f16.f16.f32 "
                 "{%0,%1,%2,%3}, {%4,%5,%6,%7}, {%8,%9}, {%0,%1,%2,%3};\n"
                 : "+f"(c[0]), "+f"(c[1]), "+f"(c[2]), "+f"(c[3])
                 : "r"(a[0]), "r"(a[1]), "r"(a[2]), "r"(a[3]), "r"(b0), "r"(b1));
}
__device__ __forceinline__ void split_pack_bf(float x, float y, unsigned& hi, unsigned& lo) {
    __nv_bfloat16 hx = __float2bfloat16(x), hy = __float2bfloat16(y);
    __nv_bfloat16 lx = __float2bfloat16(x - __bfloat162float(hx));
    __nv_bfloat16 ly = __float2bfloat16(y - __bfloat162float(hy));
    __nv_bfloat162 H = __halves2bfloat162(hx, hy);
    __nv_bfloat162 L = __halves2bfloat162(lx, ly);
    hi = *(unsigned*)&H; lo = *(unsigned*)&L;
}
__device__ __forceinline__ void split_pack_h(float x, float y, unsigned& hi, unsigned& lo) {
    __half hx = __float2half_rn(x), hy = __float2half_rn(y);
    __half lx = __float2half_rn(x - __half2float(hx));
    __half ly = __float2half_rn(y - __half2float(hy));
    __half2 H = __halves2half2(hx, hy);
    __half2 L = __halves2half2(lx, ly);
    hi = *(unsigned*)&H; lo = *(unsigned*)&L;
}
#define CP16(dst, src) \
    asm volatile("cp.async.cg.shared.global [%0], [%1], 16;\n" :: "r"(dst), "l"(src))
#define CP_COMMIT() asm volatile("cp.async.commit_group;\n" ::: "memory")
#define CP_WAIT1()  asm volatile("cp.async.wait_group 1;\n" ::: "memory")
#define CP_WAIT0()  asm volatile("cp.async.wait_group 0;\n" ::: "memory")

// ---------------- fp32 -> bf16 hi/lo split ----------------
__global__ void split_kernel(const float* __restrict__ in,
                             __nv_bfloat16* __restrict__ hi,
                             __nv_bfloat16* __restrict__ lo, int n4) {
    int i = blockIdx.x * blockDim.x + threadIdx.x;
    if (i >= n4) return;
    float4 v = ((const float4*)in)[i];
    float vv[4] = {v.x, v.y, v.z, v.w};
    __nv_bfloat16 h[4], l[4];
#pragma unroll
    for (int j = 0; j < 4; ++j) {
        h[j] = __float2bfloat16(vv[j]);
        l[j] = __float2bfloat16(vv[j] - __bfloat162float(h[j]));
    }
    *(__nv_bfloat162*)&hi[4 * i]     = __halves2bfloat162(h[0], h[1]);
    *(__nv_bfloat162*)&hi[4 * i + 2] = __halves2bfloat162(h[2], h[3]);
    *(__nv_bfloat162*)&lo[4 * i]     = __halves2bfloat162(l[0], l[1]);
    *(__nv_bfloat162*)&lo[4 * i + 2] = __halves2bfloat162(l[2], l[3]);
}

// ---------------- fp32 -> fp16 single ----------------
__global__ void tohalf_kernel(const float* __restrict__ in,
                              __half* __restrict__ out, int n4) {
    int i = blockIdx.x * blockDim.x + threadIdx.x;
    if (i >= n4) return;
    float4 v = ((const float4*)in)[i];
    *(__half2*)&out[4 * i]     = __floats2half2_rn(v.x, v.y);
    *(__half2*)&out[4 * i + 2] = __floats2half2_rn(v.z, v.w);
}

// ---------------- bf16 split-3 GEMM (projections): out = A@W^T + b, fp32 ---
#define G_STAGE 40960
#define GEMM_SMEM (2 * G_STAGE)

__global__ __launch_bounds__(256) void mma_gemm_bf(
    const __nv_bfloat16* __restrict__ Ahi, const __nv_bfloat16* __restrict__ Alo,
    const __nv_bfloat16* __restrict__ Bhi, const __nv_bfloat16* __restrict__ Blo,
    const float* __restrict__ bias, float* __restrict__ out)
{
    extern __shared__ char sm[];
    const int tid = threadIdx.x, lane = tid & 31, warp = tid >> 5;
    const int wm = warp >> 2, wn = warp & 3;
    const int m0 = blockIdx.y * 128, n0 = blockIdx.x * 128;

    auto load_stage = [&](int st, int kt) {
        char* base = sm + st * G_STAGE;
#pragma unroll
        for (int i = 0; i < 2; ++i) {
            int u = tid + i * 256;
            int r = u >> 2, c = u & 3;
            unsigned off = (unsigned)(r * 80 + c * 16);
            CP16(smem_u32(base + off),
                 (const char*)(Ahi + (size_t)(m0 + r) * DMODEL + kt) + c * 16);
            CP16(smem_u32(base + 10240 + off),
                 (const char*)(Alo + (size_t)(m0 + r) * DMODEL + kt) + c * 16);
            CP16(smem_u32(base + 20480 + off),
                 (const char*)(Bhi + (size_t)(n0 + r) * DMODEL + kt) + c * 16);
            CP16(smem_u32(base + 30720 + off),
                 (const char*)(Blo + (size_t)(n0 + r) * DMODEL + kt) + c * 16);
        }
    };

    float d[4][4][4] = {};
    load_stage(0, 0);
    CP_COMMIT();

    for (int kb = 0; kb < 32; ++kb) {
        const int st = kb & 1;
        if (kb + 1 < 32) { load_stage(st ^ 1, (kb + 1) * 32); CP_COMMIT(); CP_WAIT1(); }
        else             { CP_WAIT0(); }
        __syncthreads();

        char* base = sm + st * G_STAGE;
#pragma unroll
        for (int ks = 0; ks < 32; ks += 16) {
            unsigned ah[4][4], al[4][4];
#pragma unroll
            for (int i = 0; i < 4; ++i) {
                int row = wm * 64 + i * 16 + (lane & 15);
                int col = ks + (lane >> 4) * 8;
                ldsm4(ah[i], smem_u32(base + row * 80 + col * 2));
                ldsm4(al[i], smem_u32(base + 10240 + row * 80 + col * 2));
            }
#pragma unroll
            for (int g = 0; g < 2; ++g) {
                int row = wn * 32 + g * 16 + (lane & 7) + ((lane & 16) >> 1);
                int col = ks + ((lane >> 3) & 1) * 8;
                unsigned bhr[4], blr[4];
                ldsm4(bhr, smem_u32(base + 20480 + row * 80 + col * 2));
                ldsm4(blr, smem_u32(base + 30720 + row * 80 + col * 2));
#pragma unroll
                for (int i = 0; i < 4; ++i) {
                    mma_bf16(d[i][2 * g],     ah[i], bhr[0], bhr[1]);
                    mma_bf16(d[i][2 * g],     ah[i], blr[0], blr[1]);
                    mma_bf16(d[i][2 * g],     al[i], bhr[0], bhr[1]);
                    mma_bf16(d[i][2 * g + 1], ah[i], bhr[2], bhr[3]);
                    mma_bf16(d[i][2 * g + 1], ah[i], blr[2], blr[3]);
                    mma_bf16(d[i][2 * g + 1], al[i], bhr[2], bhr[3]);
                }
            }
        }
        __syncthreads();
    }

#pragma unroll
    for (int i = 0; i < 4; ++i)
#pragma unroll
        for (int j = 0; j < 4; ++j) {
            int c = n0 + wn * 32 + j * 8 + (lane & 3) * 2;
            float b0 = bias[c], b1 = bias[c + 1];
#pragma unroll
            for (int h = 0; h < 2; ++h) {
                int m = m0 + wm * 64 + i * 16 + (lane >> 2) + 8 * h;
                float2 r = make_float2(d[i][j][2 * h] + b0, d[i][j][2 * h + 1] + b1);
                int bb = m >> 11, s = m & 2047, hh = c >> 6, dd = c & 63;
                *(float2*)&out[(((size_t)(bb * NHEAD + hh)) * S_LEN + s) * DKH + dd] = r;
            }
        }
}

// ---------------- fp16 2-term GEMM (final): out = A@Wo^T + b, plain fp32 ---
// Stage: Ahi @0, Alo @10240, B @20480; stage size 30720.
#define GF_STAGE 30720
#define GEMMF_SMEM (2 * GF_STAGE)

__global__ __launch_bounds__(256) void mma_gemm_f16(
    const __half* __restrict__ Ahi, const __half* __restrict__ Alo,
    const __half* __restrict__ B,
    const float* __restrict__ bias, float* __restrict__ out)
{
    extern __shared__ char sm[];
    const int tid = threadIdx.x, lane = tid & 31, warp = tid >> 5;
    const int wm = warp >> 2, wn = warp & 3;
    const int m0 = blockIdx.y * 128, n0 = blockIdx.x * 128;

    auto load_stage = [&](int st, int kt) {
        char* base = sm + st * GF_STAGE;
#pragma unroll
        for (int i = 0; i < 2; ++i) {
            int u = tid + i * 256;
            int r = u >> 2, c = u & 3;
            unsigned off = (unsigned)(r * 80 + c * 16);
            CP16(smem_u32(base + off),
                 (const char*)(Ahi + (size_t)(m0 + r) * DMODEL + kt) + c * 16);
            CP16(smem_u32(base + 10240 + off),
                 (const char*)(Alo + (size_t)(m0 + r) * DMODEL + kt) + c * 16);
            CP16(smem_u32(base + 20480 + off),
                 (const char*)(B + (size_t)(n0 + r) * DMODEL + kt) + c * 16);
        }
    };

    float d[4][4][4] = {};
    load_stage(0, 0);
    CP_COMMIT();

    for (int kb = 0; kb < 32; ++kb) {
        const int st = kb & 1;
        if (kb + 1 < 32) { load_stage(st ^ 1, (kb + 1) * 32); CP_COMMIT(); CP_WAIT1(); }
        else             { CP_WAIT0(); }
        __syncthreads();

        char* base = sm + st * GF_STAGE;
#pragma unroll
        for (int ks = 0; ks < 32; ks += 16) {
            unsigned ah[4][4], al[4][4];
#pragma unroll
            for (int i = 0; i < 4; ++i) {
                int row = wm * 64 + i * 16 + (lane & 15);
                int col = ks + (lane >> 4) * 8;
                ldsm4(ah[i], smem_u32(base + row * 80 + col * 2));
                ldsm4(al[i], smem_u32(base + 10240 + row * 80 + col * 2));
            }
#pragma unroll
            for (int g = 0; g < 2; ++g) {
                int row = wn * 32 + g * 16 + (lane & 7) + ((lane & 16) >> 1);
                int col = ks + ((lane >> 3) & 1) * 8;
                unsigned br[4];
                ldsm4(br, smem_u32(base + 20480 + row * 80 + col * 2));
#pragma unroll
                for (int i = 0; i < 4; ++i) {
                    mma_f16(d[i][2 * g],     ah[i], br[0], br[1]);
                    mma_f16(d[i][2 * g],     al[i], br[0], br[1]);
                    mma_f16(d[i][2 * g + 1], ah[i], br[2], br[3]);
                    mma_f16(d[i][2 * g + 1], al[i], br[2], br[3]);
                }
            }
        }
        __syncthreads();
    }

#pragma unroll
    for (int i = 0; i < 4; ++i)
#pragma unroll
        for (int j = 0; j < 4; ++j) {
            int c = n0 + wn * 32 + j * 8 + (lane & 3) * 2;
            float b0 = bias[c], b1 = bias[c + 1];
#pragma unroll
            for (int h = 0; h < 2; ++h) {
                int m = m0 + wm * 64 + i * 16 + (lane >> 2) + 8 * h;
                *(float2*)&out[(size_t)m * DMODEL + c] =
                    make_float2(d[i][j][2 * h] + b0, d[i][j][2 * h + 1] + b1);
            }
        }
}

// ---------------- prep: fold Fourier into q/k; q -> fp16 hi/lo, k -> fp16 --
template <int SPLIT>
__global__ void prep_qk(const float* __restrict__ q,
                        __half* __restrict__ hi, __half* __restrict__ lo) {
    int row = blockIdx.x * 8 + (threadIdx.x >> 5);
    int lane = threadIdx.x & 31;
    const float* src = q + (size_t)row * DKH;
    float v0 = src[lane], v1 = src[lane + 32];
    float a = v0 + v1;
    float b = (lane & 1) ? -(v0 + v1) : (v0 + v1);
#pragma unroll
    for (int o = 16; o >= 1; o >>= 1) {
        a += __shfl_xor_sync(0xffffffffu, a, o);
        b += __shfl_xor_sync(0xffffffffu, b, o);
    }
    const float u = 0.05177669529663689f;   // (sqrt(2)-1)/8
    float adj = u * 0.125f * (a + ((lane & 1) ? -b : b));
    v0 += adj; v1 += adj;
    size_t ob = (size_t)row * DKH;
    __half h0 = __float2half_rn(v0), h1 = __float2half_rn(v1);
    hi[ob + lane]      = h0;
    hi[ob + lane + 32] = h1;
    if (SPLIT) {
        lo[ob + lane]      = __float2half_rn(v0 - __half2float(h0));
        lo[ob + lane + 32] = __float2half_rn(v1 - __half2float(h1));
    }
}

// ---------------- prep: v fp32 [bh][s][64] -> fp16 [bh][d][s] --------------
__global__ void prep_vt(const float* __restrict__ v, __half* __restrict__ o16) {
    __shared__ float smv[64 * 68];
    const int bh = blockIdx.y, s0 = blockIdx.x * 64;
    const int tid = threadIdx.x;
    const float* src = v + ((size_t)bh * S_LEN + s0) * DKH;
#pragma unroll
    for (int i = 0; i < 4; ++i) {
        int u = tid + i * 256;
        int s = u >> 4, d4 = (u & 15) * 4;
        float4 val = *(const float4*)&src[s * DKH + d4];
        smv[(d4 + 0) * 68 + s] = val.x;
        smv[(d4 + 1) * 68 + s] = val.y;
        smv[(d4 + 2) * 68 + s] = val.z;
        smv[(d4 + 3) * 68 + s] = val.w;
    }
    __syncthreads();
#pragma unroll
    for (int i = 0; i < 4; ++i) {
        int u = tid + i * 256;
        int dd = u >> 4, s4 = (u & 15) * 4;
        float4 f = *(const float4*)&smv[dd * 68 + s4];
        size_t ob = ((size_t)bh * DKH + dd) * S_LEN + s0 + s4;
        *(__half2*)&o16[ob]     = __floats2half2_rn(f.x, f.y);
        *(__half2*)&o16[ob + 2] = __floats2half2_rn(f.z, f.w);
    }
}

// ---------------- attention: fp16 asym (A split-2, B single), cp.async x2 --
// smem: K stage st at st*18432 (128 rows x 144B); V at 36864 + st*17408
// (64 rows x 272B). Q staged in K stage buffers at start.
#define K_BUF 18432
#define V_BASE 36864
#define V_BUF 17408
#define ATT_SMEM_BYTES (V_BASE + 2 * V_BUF)   // 71680

__global__ __launch_bounds__(256, 1) void attn_mma(
    const __half* __restrict__ qhi, const __half* __restrict__ qlo,
    const __half* __restrict__ k16, const __half* __restrict__ vt16,
    __half* __restrict__ ohi, __half* __restrict__ olo)
{
    extern __shared__ char sm[];
    const int tid = threadIdx.x, lane = tid & 31, warp = tid >> 5;
    const int bh = blockIdx.y, q0 = blockIdx.x * 128;
    const __half* qh = qhi + (size_t)bh * S_LEN * DKH;
    const __half* ql = qlo + (size_t)bh * S_LEN * DKH;
    const __half* kb = k16 + (size_t)bh * S_LEN * DKH;
    const __half* vb = vt16 + (size_t)bh * DKH * S_LEN;

    // ---- stage Q hi/lo into the two K stage buffers, grab fragments ----
#pragma unroll
    for (int i = 0; i < 4; ++i) {
        int u = tid + i * 256;
        int r = u >> 3, c = u & 7;
        unsigned off = (unsigned)(r * 144 + c * 16);
        *(uint4*)(sm + off) =
            *(const uint4*)((const char*)(qh + (size_t)(q0 + r) * DKH) + c * 16);
        *(uint4*)(sm + K_BUF + off) =
            *(const uint4*)((const char*)(ql + (size_t)(q0 + r) * DKH) + c * 16);
    }
    __syncthreads();
    unsigned qf[2][4][4];
#pragma unroll
    for (int ks = 0; ks < 4; ++ks) {
        int row = warp * 16 + (lane & 15);
        int col = ks * 16 + (lane >> 4) * 8;
        ldsm4(qf[0][ks], smem_u32(sm + row * 144 + col * 2));
        ldsm4(qf[1][ks], smem_u32(sm + K_BUF + row * 144 + col * 2));
    }
    __syncthreads();

    auto load_kv = [&](int st, int kt) {
        char* kd = sm + st * K_BUF;
#pragma unroll
        for (int i = 0; i < 4; ++i) {
            int u = tid + i * 256;
            int r = u >> 3, c = u & 7;
            CP16(smem_u32(kd + r * 144 + c * 16),
                 (const char*)(kb + (size_t)(kt + r) * DKH) + c * 16);
        }
        char* vd = sm + V_BASE + st * V_BUF;
#pragma unroll
        for (int i = 0; i < 4; ++i) {
            int u = tid + i * 256;
            int r = u >> 4, c = u & 15;
            CP16(smem_u32(vd + r * 272 + c * 16),
                 (const char*)(vb + (size_t)r * S_LEN + kt) + c * 16);
        }
    };

    float m_[2] = {-1e30f, -1e30f}, l_[2] = {0.f, 0.f};
    float o[8][4] = {};

    load_kv(0, 0);
    CP_COMMIT();

    for (int t = 0; t < 16; ++t) {
        const int st = t & 1;
        if (t + 1 < 16) { load_kv(st ^ 1, (t + 1) * 128); CP_COMMIT(); CP_WAIT1(); }
        else            { CP_WAIT0(); }
        __syncthreads();

        char* kd = sm + st * K_BUF;
        char* vd = sm + V_BASE + st * V_BUF;

        // ---- scores: 16 rows x 128 keys per warp, 2 terms ----
        float sc[16][4] = {};
#pragma unroll
        for (int g = 0; g < 8; ++g) {
#pragma unroll
            for (int ks = 0; ks < 4; ++ks) {
                int row = g * 16 + (lane & 7) + ((lane & 16) >> 1);
                int col = ks * 16 + ((lane >> 3) & 1) * 8;
                unsigned kr[4];
                ldsm4(kr, smem_u32(kd + row * 144 + col * 2));
                mma_f16(sc[2 * g],     qf[0][ks], kr[0], kr[1]);
                mma_f16(sc[2 * g],     qf[1][ks], kr[0], kr[1]);
                mma_f16(sc[2 * g + 1], qf[0][ks], kr[2], kr[3]);
                mma_f16(sc[2 * g + 1], qf[1][ks], kr[2], kr[3]);
            }
        }
#pragma unroll
        for (int tt = 0; tt < 16; ++tt)
#pragma unroll
            for (int j = 0; j < 4; ++j) sc[tt][j] *= 0.0625f;

        // ---- online softmax (rows lane/4 and lane/4+8) ----
        float corr[2];
#pragma unroll
        for (int h = 0; h < 2; ++h) {
            float mt = -1e30f;
#pragma unroll
            for (int tt = 0; tt < 16; ++tt)
                mt = fmaxf(mt, fmaxf(sc[tt][2 * h], sc[tt][2 * h + 1]));
            mt = fmaxf(mt, __shfl_xor_sync(0xffffffffu, mt, 1));
            mt = fmaxf(mt, __shfl_xor_sync(0xffffffffu, mt, 2));
            float mn = fmaxf(m_[h], mt);
            float sum = 0.f;
#pragma unroll
            for (int tt = 0; tt < 16; ++tt) {
                sc[tt][2 * h]     = exp2f((sc[tt][2 * h]     - mn) * 1.44269504f);
                sc[tt][2 * h + 1] = exp2f((sc[tt][2 * h + 1] - mn) * 1.44269504f);
                sum += sc[tt][2 * h] + sc[tt][2 * h + 1];
            }
            sum += __shfl_xor_sync(0xffffffffu, sum, 1);
            sum += __shfl_xor_sync(0xffffffffu, sum, 2);
            corr[h] = exp2f((m_[h] - mn) * 1.44269504f);
            l_[h] = l_[h] * corr[h] + sum;
            m_[h] = mn;
        }
#pragma unroll
        for (int tt = 0; tt < 8; ++tt) {
            o[tt][0] *= corr[0]; o[tt][1] *= corr[0];
            o[tt][2] *= corr[1]; o[tt][3] *= corr[1];
        }

        // ---- PV: P(16x128, split-2 fp16) x V(128x64, single fp16) ----
#pragma unroll
        for (int ks = 0; ks < 8; ++ks) {
            unsigned ph_[4], pl_[4];
            split_pack_h(sc[2 * ks][0],     sc[2 * ks][1],     ph_[0], pl_[0]);
            split_pack_h(sc[2 * ks][2],     sc[2 * ks][3],     ph_[1], pl_[1]);
            split_pack_h(sc[2 * ks + 1][0], sc[2 * ks + 1][1], ph_[2], pl_[2]);
            split_pack_h(sc[2 * ks + 1][2], sc[2 * ks + 1][3], ph_[3], pl_[3]);
#pragma unroll
            for (int g = 0; g < 4; ++g) {
                int row = g * 16 + (lane & 7) + ((lane & 16) >> 1);
                int col = ks * 16 + ((lane >> 3) & 1) * 8;
                unsigned vr[4];
                ldsm4(vr, smem_u32(vd + row * 272 + col * 2));
                mma_f16(o[2 * g],     ph_, vr[0], vr[1]);
                mma_f16(o[2 * g],     pl_, vr[0], vr[1]);
                mma_f16(o[2 * g + 1], ph_, vr[2], vr[3]);
                mma_f16(o[2 * g + 1], pl_, vr[2], vr[3]);
            }
        }
        __syncthreads();
    }

    // ---- epilogue: normalize, split fp16 hi/lo to plain [B*S, D] ----
    const int b = bh >> 4, head = bh & 15;
#pragma unroll
    for (int h = 0; h < 2; ++h) {
        float inv = 1.f / l_[h];
        int s = q0 + warp * 16 + (lane >> 2) + 8 * h;
        size_t rowbase = ((size_t)(b * S_LEN + s)) * DMODEL + head * DKH;
#pragma unroll
        for (int tt = 0; tt < 8; ++tt) {
            int dd = tt * 8 + (lane & 3) * 2;
            unsigned H, L;
            split_pack_h(o[tt][2 * h] * inv, o[tt][2 * h + 1] * inv, H, L);
            *(unsigned*)&ohi[rowbase + dd] = H;
            *(unsigned*)&olo[rowbase + dd] = L;
        }
    }
}

// ---------------- launch ----------------
extern "C" void kernel_launch(void* const* d_in, const int* in_sizes, int n_in,
                              void* d_out, int out_size)
{
    const float* x  = (const float*)d_in[0];
    const float* Wq = (const float*)d_in[1];
    const float* bq = (const float*)d_in[2];
    const float* Wk = (const float*)d_in[3];
    const float* bk = (const float*)d_in[4];
    const float* Wv = (const float*)d_in[5];
    const float* bv = (const float*)d_in[6];
    const float* Wo = (const float*)d_in[7];
    const float* bo = (const float*)d_in[8];
    float* out = (float*)d_out;

    __nv_bfloat16 *xhi, *xlo, *whi, *wlo;
    __half *wo16, *qhi, *qlo, *k16, *vt16, *ahi, *alo;
    float *qp, *kp, *vp;
    cudaGetSymbolAddress((void**)&xhi, g_xhi);
    cudaGetSymbolAddress((void**)&xlo, g_xlo);
    cudaGetSymbolAddress((void**)&whi, g_whi);
    cudaGetSymbolAddress((void**)&wlo, g_wlo);
    cudaGetSymbolAddress((void**)&wo16, g_wo16);
    cudaGetSymbolAddress((void**)&qp, g_q);
    cudaGetSymbolAddress((void**)&kp, g_k);
    cudaGetSymbolAddress((void**)&vp, g_v);
    cudaGetSymbolAddress((void**)&qhi, g_qhi);
    cudaGetSymbolAddress((void**)&qlo, g_qlo);
    cudaGetSymbolAddress((void**)&k16, g_k16);
    cudaGetSymbolAddress((void**)&vt16, g_vt16);
    cudaGetSymbolAddress((void**)&ahi, g_ahi);
    cudaGetSymbolAddress((void**)&alo, g_alo);

    const int WSZ = DMODEL * DMODEL;
    split_kernel<<<(M_TOT * DMODEL / 4 + 255) / 256, 256>>>(x, xhi, xlo, M_TOT * DMODEL / 4);
    split_kernel<<<(WSZ / 4 + 255) / 256, 256>>>(Wq, whi + 0 * WSZ, wlo + 0 * WSZ, WSZ / 4);
    split_kernel<<<(WSZ / 4 + 255) / 256, 256>>>(Wk, whi + 1 * WSZ, wlo + 1 * WSZ, WSZ / 4);
    split_kernel<<<(WSZ / 4 + 255) / 256, 256>>>(Wv, whi + 2 * WSZ, wlo + 2 * WSZ, WSZ / 4);
    tohalf_kernel<<<(WSZ / 4 + 255) / 256, 256>>>(Wo, wo16, WSZ / 4);

    cudaFuncSetAttribute(mma_gemm_bf, cudaFuncAttributeMaxDynamicSharedMemorySize, GEMM_SMEM);
    cudaFuncSetAttribute(mma_gemm_f16, cudaFuncAttributeMaxDynamicSharedMemorySize, GEMMF_SMEM);

    dim3 gg(DMODEL / 128, M_TOT / 128);   // (8, 32)
    mma_gemm_bf<<<gg, 256, GEMM_SMEM>>>(xhi, xlo, whi + 0 * WSZ, wlo + 0 * WSZ, bq, qp);
    mma_gemm_bf<<<gg, 256, GEMM_SMEM>>>(xhi, xlo, whi + 1 * WSZ, wlo + 1 * WSZ, bk, kp);
    mma_gemm_bf<<<gg, 256, GEMM_SMEM>>>(xhi, xlo, whi + 2 * WSZ, wlo + 2 * WSZ, bv, vp);

    prep_qk<1><<<BH * S_LEN / 8, 256>>>(qp, qhi, qlo);
    prep_qk<0><<<BH * S_LEN / 8, 256>>>(kp, k16, nullptr);
    prep_vt<<<dim3(S_LEN / 64, BH), 256>>>(vp, vt16);

    cudaFuncSetAttribute(attn_mma, cudaFuncAttributeMaxDynamicSharedMemorySize,
                         ATT_SMEM_BYTES);
    attn_mma<<<dim3(S_LEN / 128, BH), 256, ATT_SMEM_BYTES>>>(
        qhi, qlo, k16, vt16, ahi, alo);

    mma_gemm_f16<<<gg, 256, GEMMF_SMEM>>>(ahi, alo, wo16, bo, out);
}

// round 7
// speedup vs baseline: 4.1464x; 1.1700x over previous
#include <cuda_runtime.h>
#include <cuda_fp16.h>
#include <cstdint>

#define BATCH  2
#define S_LEN  2048
#define DMODEL 1024
#define NHEAD  16
#define DKH    64
#define M_TOT  (BATCH * S_LEN)
#define BH     (BATCH * NHEAD)

// ---------------- scratch (device globals; allocation-free) ----------------
__device__ __align__(16) __half g_xhi[M_TOT * DMODEL];
__device__ __align__(16) __half g_xlo[M_TOT * DMODEL];
__device__ __align__(16) __half g_wq16[DMODEL * DMODEL];   // folded
__device__ __align__(16) __half g_wk16[DMODEL * DMODEL];   // folded
__device__ __align__(16) __half g_wv16[DMODEL * DMODEL];
__device__ __align__(16) __half g_wo16[DMODEL * DMODEL];
__device__ __align__(16) float  g_bqf[DMODEL];             // folded bias
__device__ __align__(16) float  g_bkf[DMODEL];
__device__ __align__(16) __half g_qhi[BH * S_LEN * DKH];
__device__ __align__(16) __half g_qlo[BH * S_LEN * DKH];
__device__ __align__(16) __half g_k16[BH * S_LEN * DKH];
__device__ __align__(16) __half g_v16[BH * S_LEN * DKH];   // natural [bh][s][d]
__device__ __align__(16) __half g_ahi[M_TOT * DMODEL];
__device__ __align__(16) __half g_alo[M_TOT * DMODEL];

// ---------------- helpers ----------------
__device__ __forceinline__ unsigned smem_u32(const void* p) {
    return (unsigned)__cvta_generic_to_shared(p);
}
__device__ __forceinline__ void ldsm4(unsigned* r, unsigned addr) {
    asm volatile("ldmatrix.sync.aligned.m8n8.x4.shared.b16 {%0,%1,%2,%3}, [%4];\n"
                 : "=r"(r[0]), "=r"(r[1]), "=r"(r[2]), "=r"(r[3]) : "r"(addr));
}
__device__ __forceinline__ void ldsm4_t(unsigned* r, unsigned addr) {
    asm volatile("ldmatrix.sync.aligned.m8n8.x4.trans.shared.b16 {%0,%1,%2,%3}, [%4];\n"
                 : "=r"(r[0]), "=r"(r[1]), "=r"(r[2]), "=r"(r[3]) : "r"(addr));
}
__device__ __forceinline__ void mma_f16(float* c, const unsigned* a, unsigned b0, unsigned b1) {
    asm volatile("mma.sync.aligned.m16n8k16.row.col.f32.f16.f16.f32 "
                 "{%0,%1,%2,%3}, {%4,%5,%6,%7}, {%8,%9}, {%0,%1,%2,%3};\n"
                 : "+f"(c[0]), "+f"(c[1]), "+f"(c[2]), "+f"(c[3])
                 : "r"(a[0]), "r"(a[1]), "r"(a[2]), "r"(a[3]), "r"(b0), "r"(b1));
}
__device__ __forceinline__ void split_pack_h(float x, float y, unsigned& hi, unsigned& lo) {
    __half hx = __float2half_rn(x), hy = __float2half_rn(y);
    __half lx = __float2half_rn(x - __half2float(hx));
    __half ly = __float2half_rn(y - __half2float(hy));
    __half2 H = __halves2half2(hx, hy);
    __half2 L = __halves2half2(lx, ly);
    hi = *(unsigned*)&H; lo = *(unsigned*)&L;
}
#define CP16(dst, src) \
    asm volatile("cp.async.cg.shared.global [%0], [%1], 16;\n" :: "r"(dst), "l"(src))
#define CP_COMMIT() asm volatile("cp.async.commit_group;\n" ::: "memory")
#define CP_WAIT1()  asm volatile("cp.async.wait_group 1;\n" ::: "memory")
#define CP_WAIT0()  asm volatile("cp.async.wait_group 0;\n" ::: "memory")

// ---------------- fp32 -> fp16 hi/lo split (x) ----------------
__global__ void splitx_h(const float* __restrict__ in,
                         __half* __restrict__ hi, __half* __restrict__ lo, int n4) {
    int i = blockIdx.x * blockDim.x + threadIdx.x;
    if (i >= n4) return;
    float4 v = ((const float4*)in)[i];
    float vv[4] = {v.x, v.y, v.z, v.w};
    __half h[4], l[4];
#pragma unroll
    for (int j = 0; j < 4; ++j) {
        h[j] = __float2half_rn(vv[j]);
        l[j] = __float2half_rn(vv[j] - __half2float(h[j]));
    }
    *(__half2*)&hi[4 * i]     = __halves2half2(h[0], h[1]);
    *(__half2*)&hi[4 * i + 2] = __halves2half2(h[2], h[3]);
    *(__half2*)&lo[4 * i]     = __halves2half2(l[0], l[1]);
    *(__half2*)&lo[4 * i + 2] = __halves2half2(l[2], l[3]);
}

// ---------------- fp32 -> fp16 single ----------------
__global__ void tohalf_kernel(const float* __restrict__ in,
                              __half* __restrict__ out, int n4) {
    int i = blockIdx.x * blockDim.x + threadIdx.x;
    if (i >= n4) return;
    float4 v = ((const float4*)in)[i];
    *(__half2*)&out[4 * i]     = __floats2half2_rn(v.x, v.y);
    *(__half2*)&out[4 * i + 2] = __floats2half2_rn(v.z, v.w);
}

// ---------------- fold Fourier rank-2 map into W (per-head), emit fp16 -----
// W'[d][k] = W[d][k] + cu*(S1[k] + (-1)^d S2[k]),  cu = (sqrt2-1)/64
__global__ void fold_w(const float* __restrict__ W, __half* __restrict__ Wo) {
    const int h = blockIdx.x;                       // head 0..15
    const int k = blockIdx.y * 128 + threadIdx.x;   // col 0..1023
    float S1 = 0.f, S2 = 0.f;
#pragma unroll 8
    for (int d = 0; d < 64; ++d) {
        float w = W[(size_t)(h * 64 + d) * DMODEL + k];
        S1 += w;
        S2 += (d & 1) ? -w : w;
    }
    const float cu = 0.006472086912079611f;   // (sqrt(2)-1)/8/8
#pragma unroll 8
    for (int d = 0; d < 64; ++d) {
        float w = W[(size_t)(h * 64 + d) * DMODEL + k];
        float wn = w + cu * (S1 + ((d & 1) ? -S2 : S2));
        Wo[(size_t)(h * 64 + d) * DMODEL + k] = __float2half_rn(wn);
    }
}

// ---------------- fold bias (fp32 out) ----------------
__global__ void fold_b(const float* __restrict__ b, float* __restrict__ bo) {
    const int h = blockIdx.x;          // 16
    const int lane = threadIdx.x;      // 32
    float v0 = b[h * 64 + lane], v1 = b[h * 64 + lane + 32];
    float a = v0 + v1;
    float s = (lane & 1) ? -(v0 + v1) : (v0 + v1);
#pragma unroll
    for (int o = 16; o >= 1; o >>= 1) {
        a += __shfl_xor_sync(0xffffffffu, a, o);
        s += __shfl_xor_sync(0xffffffffu, s, o);
    }
    const float cu = 0.006472086912079611f;
    float adj = cu * (a + ((lane & 1) ? -s : s));
    bo[h * 64 + lane]      = v0 + adj;
    bo[h * 64 + lane + 32] = v1 + adj;
}

// ---------------- fp16 2-term GEMM: out = A@B^T + bias ---------------------
// A = (Ahi + Alo) exact fp16 split-2, B single fp16. 128x128 tile, BK=32.
// MODE 0: fp32 plain [M,D]. 1: Q fp16 hi/lo head. 2: K fp16 head. 3: V fp16 head.
#define GF_STAGE 30720
#define GEMMF_SMEM (2 * GF_STAGE)

template <int MODE>
__global__ __launch_bounds__(256) void mma_gemm_f16(
    const __half* __restrict__ Ahi, const __half* __restrict__ Alo,
    const __half* __restrict__ B, const float* __restrict__ bias,
    float* __restrict__ outf, __half* __restrict__ o1, __half* __restrict__ o2)
{
    extern __shared__ char sm[];
    const int tid = threadIdx.x, lane = tid & 31, warp = tid >> 5;
    const int wm = warp >> 2, wn = warp & 3;
    const int m0 = blockIdx.y * 128, n0 = blockIdx.x * 128;

    auto load_stage = [&](int st, int kt) {
        char* base = sm + st * GF_STAGE;
#pragma unroll
        for (int i = 0; i < 2; ++i) {
            int u = tid + i * 256;
            int r = u >> 2, c = u & 3;
            unsigned off = (unsigned)(r * 80 + c * 16);
            CP16(smem_u32(base + off),
                 (const char*)(Ahi + (size_t)(m0 + r) * DMODEL + kt) + c * 16);
            CP16(smem_u32(base + 10240 + off),
                 (const char*)(Alo + (size_t)(m0 + r) * DMODEL + kt) + c * 16);
            CP16(smem_u32(base + 20480 + off),
                 (const char*)(B + (size_t)(n0 + r) * DMODEL + kt) + c * 16);
        }
    };

    float d[4][4][4] = {};
    load_stage(0, 0);
    CP_COMMIT();

    for (int kb = 0; kb < 32; ++kb) {
        const int st = kb & 1;
        if (kb + 1 < 32) { load_stage(st ^ 1, (kb + 1) * 32); CP_COMMIT(); CP_WAIT1(); }
        else             { CP_WAIT0(); }
        __syncthreads();

        char* base = sm + st * GF_STAGE;
#pragma unroll
        for (int ks = 0; ks < 32; ks += 16) {
            unsigned ah[4][4], al[4][4];
#pragma unroll
            for (int i = 0; i < 4; ++i) {
                int row = wm * 64 + i * 16 + (lane & 15);
                int col = ks + (lane >> 4) * 8;
                ldsm4(ah[i], smem_u32(base + row * 80 + col * 2));
                ldsm4(al[i], smem_u32(base + 10240 + row * 80 + col * 2));
            }
#pragma unroll
            for (int g = 0; g < 2; ++g) {
                int row = wn * 32 + g * 16 + (lane & 7) + ((lane & 16) >> 1);
                int col = ks + ((lane >> 3) & 1) * 8;
                unsigned br[4];
                ldsm4(br, smem_u32(base + 20480 + row * 80 + col * 2));
#pragma unroll
                for (int i = 0; i < 4; ++i) {
                    mma_f16(d[i][2 * g],     ah[i], br[0], br[1]);
                    mma_f16(d[i][2 * g],     al[i], br[0], br[1]);
                    mma_f16(d[i][2 * g + 1], ah[i], br[2], br[3]);
                    mma_f16(d[i][2 * g + 1], al[i], br[2], br[3]);
                }
            }
        }
        __syncthreads();
    }

#pragma unroll
    for (int i = 0; i < 4; ++i)
#pragma unroll
        for (int j = 0; j < 4; ++j) {
            int c = n0 + wn * 32 + j * 8 + (lane & 3) * 2;
            float b0 = bias[c], b1 = bias[c + 1];
#pragma unroll
            for (int h = 0; h < 2; ++h) {
                int m = m0 + wm * 64 + i * 16 + (lane >> 2) + 8 * h;
                float v0 = d[i][j][2 * h] + b0, v1 = d[i][j][2 * h + 1] + b1;
                if (MODE == 0) {
                    *(float2*)&outf[(size_t)m * DMODEL + c] = make_float2(v0, v1);
                } else {
                    int bb = m >> 11, s = m & 2047, hh = c >> 6, dd = c & 63;
                    size_t idx = (((size_t)(bb * NHEAD + hh)) * S_LEN + s) * DKH + dd;
                    if (MODE == 1) {
                        unsigned H, L;
                        split_pack_h(v0, v1, H, L);
                        *(unsigned*)&o1[idx] = H;
                        *(unsigned*)&o2[idx] = L;
                    } else {
                        *(__half2*)&o1[idx] = __floats2half2_rn(v0, v1);
                    }
                }
            }
        }
}

// ---------------- attention: fp16 asym, V natural via ldmatrix.trans -------
// smem: K stage st at st*18432 (128 rows x 144B, [s][d]); V at 36864 +
// st*18432 (128 rows x 144B, [s][d]). Q staged in K buffers at start.
#define K_BUF 18432
#define V_BASE 36864
#define ATT_SMEM_BYTES (V_BASE + 2 * K_BUF)   // 73728

__global__ __launch_bounds__(256, 1) void attn_mma(
    const __half* __restrict__ qhi, const __half* __restrict__ qlo,
    const __half* __restrict__ k16, const __half* __restrict__ v16,
    __half* __restrict__ ohi, __half* __restrict__ olo)
{
    extern __shared__ char sm[];
    const int tid = threadIdx.x, lane = tid & 31, warp = tid >> 5;
    const int bh = blockIdx.y, q0 = blockIdx.x * 128;
    const __half* qh = qhi + (size_t)bh * S_LEN * DKH;
    const __half* ql = qlo + (size_t)bh * S_LEN * DKH;
    const __half* kb = k16 + (size_t)bh * S_LEN * DKH;
    const __half* vb = v16 + (size_t)bh * S_LEN * DKH;

    // ---- stage Q hi/lo into the two K stage buffers, grab fragments ----
#pragma unroll
    for (int i = 0; i < 4; ++i) {
        int u = tid + i * 256;
        int r = u >> 3, c = u & 7;
        unsigned off = (unsigned)(r * 144 + c * 16);
        *(uint4*)(sm + off) =
            *(const uint4*)((const char*)(qh + (size_t)(q0 + r) * DKH) + c * 16);
        *(uint4*)(sm + K_BUF + off) =
            *(const uint4*)((const char*)(ql + (size_t)(q0 + r) * DKH) + c * 16);
    }
    __syncthreads();
    unsigned qf[2][4][4];
#pragma unroll
    for (int ks = 0; ks < 4; ++ks) {
        int row = warp * 16 + (lane & 15);
        int col = ks * 16 + (lane >> 4) * 8;
        ldsm4(qf[0][ks], smem_u32(sm + row * 144 + col * 2));
        ldsm4(qf[1][ks], smem_u32(sm + K_BUF + row * 144 + col * 2));
    }
    __syncthreads();

    auto load_kv = [&](int st, int kt) {
        char* kd = sm + st * K_BUF;
        char* vd = sm + V_BASE + st * K_BUF;
#pragma unroll
        for (int i = 0; i < 4; ++i) {
            int u = tid + i * 256;
            int r = u >> 3, c = u & 7;
            CP16(smem_u32(kd + r * 144 + c * 16),
                 (const char*)(kb + (size_t)(kt + r) * DKH) + c * 16);
            CP16(smem_u32(vd + r * 144 + c * 16),
                 (const char*)(vb + (size_t)(kt + r) * DKH) + c * 16);
        }
    };

    float m_[2] = {-1e30f, -1e30f}, l_[2] = {0.f, 0.f};
    float o[8][4] = {};

    load_kv(0, 0);
    CP_COMMIT();

    for (int t = 0; t < 16; ++t) {
        const int st = t & 1;
        if (t + 1 < 16) { load_kv(st ^ 1, (t + 1) * 128); CP_COMMIT(); CP_WAIT1(); }
        else            { CP_WAIT0(); }
        __syncthreads();

        char* kd = sm + st * K_BUF;
        char* vd = sm + V_BASE + st * K_BUF;

        // ---- scores: 16 rows x 128 keys per warp, 2 terms ----
        float sc[16][4] = {};
#pragma unroll
        for (int g = 0; g < 8; ++g) {
#pragma unroll
            for (int ks = 0; ks < 4; ++ks) {
                int row = g * 16 + (lane & 7) + ((lane & 16) >> 1);
                int col = ks * 16 + ((lane >> 3) & 1) * 8;
                unsigned kr[4];
                ldsm4(kr, smem_u32(kd + row * 144 + col * 2));
                mma_f16(sc[2 * g],     qf[0][ks], kr[0], kr[1]);
                mma_f16(sc[2 * g],     qf[1][ks], kr[0], kr[1]);
                mma_f16(sc[2 * g + 1], qf[0][ks], kr[2], kr[3]);
                mma_f16(sc[2 * g + 1], qf[1][ks], kr[2], kr[3]);
            }
        }
#pragma unroll
        for (int tt = 0; tt < 16; ++tt)
#pragma unroll
            for (int j = 0; j < 4; ++j) sc[tt][j] *= 0.0625f;

        // ---- online softmax (rows lane/4 and lane/4+8) ----
        float corr[2];
#pragma unroll
        for (int h = 0; h < 2; ++h) {
            float mt = -1e30f;
#pragma unroll
            for (int tt = 0; tt < 16; ++tt)
                mt = fmaxf(mt, fmaxf(sc[tt][2 * h], sc[tt][2 * h + 1]));
            mt = fmaxf(mt, __shfl_xor_sync(0xffffffffu, mt, 1));
            mt = fmaxf(mt, __shfl_xor_sync(0xffffffffu, mt, 2));
            float mn = fmaxf(m_[h], mt);
            float sum = 0.f;
#pragma unroll
            for (int tt = 0; tt < 16; ++tt) {
                sc[tt][2 * h]     = exp2f((sc[tt][2 * h]     - mn) * 1.44269504f);
                sc[tt][2 * h + 1] = exp2f((sc[tt][2 * h + 1] - mn) * 1.44269504f);
                sum += sc[tt][2 * h] + sc[tt][2 * h + 1];
            }
            sum += __shfl_xor_sync(0xffffffffu, sum, 1);
            sum += __shfl_xor_sync(0xffffffffu, sum, 2);
            corr[h] = exp2f((m_[h] - mn) * 1.44269504f);
            l_[h] = l_[h] * corr[h] + sum;
            m_[h] = mn;
        }
#pragma unroll
        for (int tt = 0; tt < 8; ++tt) {
            o[tt][0] *= corr[0]; o[tt][1] *= corr[0];
            o[tt][2] *= corr[1]; o[tt][3] *= corr[1];
        }

        // ---- PV: P(16x128, split-2 fp16) x V via trans-ldmatrix ----
#pragma unroll
        for (int ks = 0; ks < 8; ++ks) {
            unsigned ph_[4], pl_[4];
            split_pack_h(sc[2 * ks][0],     sc[2 * ks][1],     ph_[0], pl_[0]);
            split_pack_h(sc[2 * ks][2],     sc[2 * ks][3],     ph_[1], pl_[1]);
            split_pack_h(sc[2 * ks + 1][0], sc[2 * ks + 1][1], ph_[2], pl_[2]);
            split_pack_h(sc[2 * ks + 1][2], sc[2 * ks + 1][3], ph_[3], pl_[3]);
#pragma unroll
            for (int g = 0; g < 4; ++g) {
                // trans tiles: srow = s index within 128, scol = d
                int srow = ks * 16 + (lane & 7) + (((lane >> 3) & 1) << 3);
                int scol = g * 16 + (((lane >> 4) & 1) << 3);
                unsigned vr[4];
                ldsm4_t(vr, smem_u32(vd + srow * 144 + scol * 2));
                mma_f16(o[2 * g],     ph_, vr[0], vr[1]);
                mma_f16(o[2 * g],     pl_, vr[0], vr[1]);
                mma_f16(o[2 * g + 1], ph_, vr[2], vr[3]);
                mma_f16(o[2 * g + 1], pl_, vr[2], vr[3]);
            }
        }
        __syncthreads();
    }

    // ---- epilogue: normalize, split fp16 hi/lo to plain [B*S, D] ----
    const int b = bh >> 4, head = bh & 15;
#pragma unroll
    for (int h = 0; h < 2; ++h) {
        float inv = 1.f / l_[h];
        int s = q0 + warp * 16 + (lane >> 2) + 8 * h;
        size_t rowbase = ((size_t)(b * S_LEN + s)) * DMODEL + head * DKH;
#pragma unroll
        for (int tt = 0; tt < 8; ++tt) {
            int dd = tt * 8 + (lane & 3) * 2;
            unsigned H, L;
            split_pack_h(o[tt][2 * h] * inv, o[tt][2 * h + 1] * inv, H, L);
            *(unsigned*)&ohi[rowbase + dd] = H;
            *(unsigned*)&olo[rowbase + dd] = L;
        }
    }
}

// ---------------- launch ----------------
extern "C" void kernel_launch(void* const* d_in, const int* in_sizes, int n_in,
                              void* d_out, int out_size)
{
    const float* x  = (const float*)d_in[0];
    const float* Wq = (const float*)d_in[1];
    const float* bq = (const float*)d_in[2];
    const float* Wk = (const float*)d_in[3];
    const float* bk = (const float*)d_in[4];
    const float* Wv = (const float*)d_in[5];
    const float* bv = (const float*)d_in[6];
    const float* Wo = (const float*)d_in[7];
    const float* bo = (const float*)d_in[8];
    float* out = (float*)d_out;

    __half *xhi, *xlo, *wq16, *wk16, *wv16, *wo16, *qhi, *qlo, *k16, *v16, *ahi, *alo;
    float *bqf, *bkf;
    cudaGetSymbolAddress((void**)&xhi, g_xhi);
    cudaGetSymbolAddress((void**)&xlo, g_xlo);
    cudaGetSymbolAddress((void**)&wq16, g_wq16);
    cudaGetSymbolAddress((void**)&wk16, g_wk16);
    cudaGetSymbolAddress((void**)&wv16, g_wv16);
    cudaGetSymbolAddress((void**)&wo16, g_wo16);
    cudaGetSymbolAddress((void**)&bqf, g_bqf);
    cudaGetSymbolAddress((void**)&bkf, g_bkf);
    cudaGetSymbolAddress((void**)&qhi, g_qhi);
    cudaGetSymbolAddress((void**)&qlo, g_qlo);
    cudaGetSymbolAddress((void**)&k16, g_k16);
    cudaGetSymbolAddress((void**)&v16, g_v16);
    cudaGetSymbolAddress((void**)&ahi, g_ahi);
    cudaGetSymbolAddress((void**)&alo, g_alo);

    const int WSZ = DMODEL * DMODEL;
    splitx_h<<<(M_TOT * DMODEL / 4 + 255) / 256, 256>>>(x, xhi, xlo, M_TOT * DMODEL / 4);
    fold_w<<<dim3(NHEAD, DMODEL / 128), 128>>>(Wq, wq16);
    fold_w<<<dim3(NHEAD, DMODEL / 128), 128>>>(Wk, wk16);
    fold_b<<<NHEAD, 32>>>(bq, bqf);
    fold_b<<<NHEAD, 32>>>(bk, bkf);
    tohalf_kernel<<<(WSZ / 4 + 255) / 256, 256>>>(Wv, wv16, WSZ / 4);
    tohalf_kernel<<<(WSZ / 4 + 255) / 256, 256>>>(Wo, wo16, WSZ / 4);

    cudaFuncSetAttribute(mma_gemm_f16<0>, cudaFuncAttributeMaxDynamicSharedMemorySize, GEMMF_SMEM);
    cudaFuncSetAttribute(mma_gemm_f16<1>, cudaFuncAttributeMaxDynamicSharedMemorySize, GEMMF_SMEM);
    cudaFuncSetAttribute(mma_gemm_f16<2>, cudaFuncAttributeMaxDynamicSharedMemorySize, GEMMF_SMEM);
    cudaFuncSetAttribute(mma_gemm_f16<3>, cudaFuncAttributeMaxDynamicSharedMemorySize, GEMMF_SMEM);

    dim3 gg(DMODEL / 128, M_TOT / 128);   // (8, 32)
    mma_gemm_f16<1><<<gg, 256, GEMMF_SMEM>>>(xhi, xlo, wq16, bqf, nullptr, qhi, qlo);
    mma_gemm_f16<2><<<gg, 256, GEMMF_SMEM>>>(xhi, xlo, wk16, bkf, nullptr, k16, nullptr);
    mma_gemm_f16<3><<<gg, 256, GEMMF_SMEM>>>(xhi, xlo, wv16, bv, nullptr, v16, nullptr);

    cudaFuncSetAttribute(attn_mma, cudaFuncAttributeMaxDynamicSharedMemorySize,
                         ATT_SMEM_BYTES);
    attn_mma<<<dim3(S_LEN / 128, BH), 256, ATT_SMEM_BYTES>>>(
        qhi, qlo, k16, v16, ahi, alo);

    mma_gemm_f16<0><<<gg, 256, GEMMF_SMEM>>>(ahi, alo, wo16, bo, out, nullptr, nullptr);
}

// round 8
// speedup vs baseline: 4.7895x; 1.1551x over previous
#include <cuda_runtime.h>
#include <cuda_fp16.h>
#include <cstdint>

#define BATCH  2
#define S_LEN  2048
#define DMODEL 1024
#define NHEAD  16
#define DKH    64
#define M_TOT  (BATCH * S_LEN)
#define BH     (BATCH * NHEAD)

// ---------------- scratch (device globals; allocation-free) ----------------
__device__ __align__(16) __half g_xhi[M_TOT * DMODEL];
__device__ __align__(16) __half g_xlo[M_TOT * DMODEL];
__device__ __align__(16) __half g_wq16[DMODEL * DMODEL];   // folded
__device__ __align__(16) __half g_wk16[DMODEL * DMODEL];   // folded
__device__ __align__(16) __half g_wv16[DMODEL * DMODEL];
__device__ __align__(16) __half g_wo16[DMODEL * DMODEL];
__device__ __align__(16) float  g_bqf[DMODEL];             // folded bias
__device__ __align__(16) float  g_bkf[DMODEL];
__device__ __align__(16) __half g_q16[BH * S_LEN * DKH];
__device__ __align__(16) __half g_k16[BH * S_LEN * DKH];
__device__ __align__(16) __half g_v16[BH * S_LEN * DKH];   // natural [bh][s][d]
__device__ __align__(16) __half g_ahi[M_TOT * DMODEL];
__device__ __align__(16) __half g_alo[M_TOT * DMODEL];

// ---------------- helpers ----------------
__device__ __forceinline__ unsigned smem_u32(const void* p) {
    return (unsigned)__cvta_generic_to_shared(p);
}
__device__ __forceinline__ void ldsm4(unsigned* r, unsigned addr) {
    asm volatile("ldmatrix.sync.aligned.m8n8.x4.shared.b16 {%0,%1,%2,%3}, [%4];\n"
                 : "=r"(r[0]), "=r"(r[1]), "=r"(r[2]), "=r"(r[3]) : "r"(addr));
}
__device__ __forceinline__ void ldsm4_t(unsigned* r, unsigned addr) {
    asm volatile("ldmatrix.sync.aligned.m8n8.x4.trans.shared.b16 {%0,%1,%2,%3}, [%4];\n"
                 : "=r"(r[0]), "=r"(r[1]), "=r"(r[2]), "=r"(r[3]) : "r"(addr));
}
__device__ __forceinline__ void mma_f16(float* c, const unsigned* a, unsigned b0, unsigned b1) {
    asm volatile("mma.sync.aligned.m16n8k16.row.col.f32.f16.f16.f32 "
                 "{%0,%1,%2,%3}, {%4,%5,%6,%7}, {%8,%9}, {%0,%1,%2,%3};\n"
                 : "+f"(c[0]), "+f"(c[1]), "+f"(c[2]), "+f"(c[3])
                 : "r"(a[0]), "r"(a[1]), "r"(a[2]), "r"(a[3]), "r"(b0), "r"(b1));
}
__device__ __forceinline__ unsigned pack_h2(float x, float y) {
    __half2 h = __floats2half2_rn(x, y);
    return *(unsigned*)&h;
}
__device__ __forceinline__ void split_pack_h(float x, float y, unsigned& hi, unsigned& lo) {
    __half hx = __float2half_rn(x), hy = __float2half_rn(y);
    __half lx = __float2half_rn(x - __half2float(hx));
    __half ly = __float2half_rn(y - __half2float(hy));
    __half2 H = __halves2half2(hx, hy);
    __half2 L = __halves2half2(lx, ly);
    hi = *(unsigned*)&H; lo = *(unsigned*)&L;
}
#define CP16(dst, src) \
    asm volatile("cp.async.cg.shared.global [%0], [%1], 16;\n" :: "r"(dst), "l"(src))
#define CP_COMMIT() asm volatile("cp.async.commit_group;\n" ::: "memory")
#define CP_WAIT1()  asm volatile("cp.async.wait_group 1;\n" ::: "memory")
#define CP_WAIT0()  asm volatile("cp.async.wait_group 0;\n" ::: "memory")

// ---------------- fp32 -> fp16 hi/lo split (x) ----------------
__global__ void splitx_h(const float* __restrict__ in,
                         __half* __restrict__ hi, __half* __restrict__ lo, int n4) {
    int i = blockIdx.x * blockDim.x + threadIdx.x;
    if (i >= n4) return;
    float4 v = ((const float4*)in)[i];
    float vv[4] = {v.x, v.y, v.z, v.w};
    __half h[4], l[4];
#pragma unroll
    for (int j = 0; j < 4; ++j) {
        h[j] = __float2half_rn(vv[j]);
        l[j] = __float2half_rn(vv[j] - __half2float(h[j]));
    }
    *(__half2*)&hi[4 * i]     = __halves2half2(h[0], h[1]);
    *(__half2*)&hi[4 * i + 2] = __halves2half2(h[2], h[3]);
    *(__half2*)&lo[4 * i]     = __halves2half2(l[0], l[1]);
    *(__half2*)&lo[4 * i + 2] = __halves2half2(l[2], l[3]);
}

// ---------------- fp32 -> fp16 single ----------------
__global__ void tohalf_kernel(const float* __restrict__ in,
                              __half* __restrict__ out, int n4) {
    int i = blockIdx.x * blockDim.x + threadIdx.x;
    if (i >= n4) return;
    float4 v = ((const float4*)in)[i];
    *(__half2*)&out[4 * i]     = __floats2half2_rn(v.x, v.y);
    *(__half2*)&out[4 * i + 2] = __floats2half2_rn(v.z, v.w);
}

// ---------------- fold Fourier rank-2 map into W (per-head), emit fp16 -----
__global__ void fold_w(const float* __restrict__ W, __half* __restrict__ Wo) {
    const int h = blockIdx.x;
    const int k = blockIdx.y * 128 + threadIdx.x;
    float S1 = 0.f, S2 = 0.f;
#pragma unroll 8
    for (int d = 0; d < 64; ++d) {
        float w = W[(size_t)(h * 64 + d) * DMODEL + k];
        S1 += w;
        S2 += (d & 1) ? -w : w;
    }
    const float cu = 0.006472086912079611f;   // (sqrt(2)-1)/64
#pragma unroll 8
    for (int d = 0; d < 64; ++d) {
        float w = W[(size_t)(h * 64 + d) * DMODEL + k];
        float wn = w + cu * (S1 + ((d & 1) ? -S2 : S2));
        Wo[(size_t)(h * 64 + d) * DMODEL + k] = __float2half_rn(wn);
    }
}

// ---------------- fold bias (fp32 out) ----------------
__global__ void fold_b(const float* __restrict__ b, float* __restrict__ bo) {
    const int h = blockIdx.x;
    const int lane = threadIdx.x;
    float v0 = b[h * 64 + lane], v1 = b[h * 64 + lane + 32];
    float a = v0 + v1;
    float s = (lane & 1) ? -(v0 + v1) : (v0 + v1);
#pragma unroll
    for (int o = 16; o >= 1; o >>= 1) {
        a += __shfl_xor_sync(0xffffffffu, a, o);
        s += __shfl_xor_sync(0xffffffffu, s, o);
    }
    const float cu = 0.006472086912079611f;
    float adj = cu * (a + ((lane & 1) ? -s : s));
    bo[h * 64 + lane]      = v0 + adj;
    bo[h * 64 + lane + 32] = v1 + adj;
}

// ---------------- fp16 2-term GEMM: out = A@B^T + bias ---------------------
// MODE 0: fp32 plain [M,D].  MODE 1: fp16 single in head layout.
#define GF_STAGE 30720
#define GEMMF_SMEM (2 * GF_STAGE)

template <int MODE>
__global__ __launch_bounds__(256) void mma_gemm_f16(
    const __half* __restrict__ Ahi, const __half* __restrict__ Alo,
    const __half* __restrict__ B, const float* __restrict__ bias,
    float* __restrict__ outf, __half* __restrict__ o1)
{
    extern __shared__ char sm[];
    const int tid = threadIdx.x, lane = tid & 31, warp = tid >> 5;
    const int wm = warp >> 2, wn = warp & 3;
    const int m0 = blockIdx.y * 128, n0 = blockIdx.x * 128;

    auto load_stage = [&](int st, int kt) {
        char* base = sm + st * GF_STAGE;
#pragma unroll
        for (int i = 0; i < 2; ++i) {
            int u = tid + i * 256;
            int r = u >> 2, c = u & 3;
            unsigned off = (unsigned)(r * 80 + c * 16);
            CP16(smem_u32(base + off),
                 (const char*)(Ahi + (size_t)(m0 + r) * DMODEL + kt) + c * 16);
            CP16(smem_u32(base + 10240 + off),
                 (const char*)(Alo + (size_t)(m0 + r) * DMODEL + kt) + c * 16);
            CP16(smem_u32(base + 20480 + off),
                 (const char*)(B + (size_t)(n0 + r) * DMODEL + kt) + c * 16);
        }
    };

    float d[4][4][4] = {};
    load_stage(0, 0);
    CP_COMMIT();

    for (int kb = 0; kb < 32; ++kb) {
        const int st = kb & 1;
        if (kb + 1 < 32) { load_stage(st ^ 1, (kb + 1) * 32); CP_COMMIT(); CP_WAIT1(); }
        else             { CP_WAIT0(); }
        __syncthreads();

        char* base = sm + st * GF_STAGE;
#pragma unroll
        for (int ks = 0; ks < 32; ks += 16) {
            unsigned ah[4][4], al[4][4];
#pragma unroll
            for (int i = 0; i < 4; ++i) {
                int row = wm * 64 + i * 16 + (lane & 15);
                int col = ks + (lane >> 4) * 8;
                ldsm4(ah[i], smem_u32(base + row * 80 + col * 2));
                ldsm4(al[i], smem_u32(base + 10240 + row * 80 + col * 2));
            }
#pragma unroll
            for (int g = 0; g < 2; ++g) {
                int row = wn * 32 + g * 16 + (lane & 7) + ((lane & 16) >> 1);
                int col = ks + ((lane >> 3) & 1) * 8;
                unsigned br[4];
                ldsm4(br, smem_u32(base + 20480 + row * 80 + col * 2));
#pragma unroll
                for (int i = 0; i < 4; ++i) {
                    mma_f16(d[i][2 * g],     ah[i], br[0], br[1]);
                    mma_f16(d[i][2 * g],     al[i], br[0], br[1]);
                    mma_f16(d[i][2 * g + 1], ah[i], br[2], br[3]);
                    mma_f16(d[i][2 * g + 1], al[i], br[2], br[3]);
                }
            }
        }
        __syncthreads();
    }

#pragma unroll
    for (int i = 0; i < 4; ++i)
#pragma unroll
        for (int j = 0; j < 4; ++j) {
            int c = n0 + wn * 32 + j * 8 + (lane & 3) * 2;
            float b0 = bias[c], b1 = bias[c + 1];
#pragma unroll
            for (int h = 0; h < 2; ++h) {
                int m = m0 + wm * 64 + i * 16 + (lane >> 2) + 8 * h;
                float v0 = d[i][j][2 * h] + b0, v1 = d[i][j][2 * h + 1] + b1;
                if (MODE == 0) {
                    *(float2*)&outf[(size_t)m * DMODEL + c] = make_float2(v0, v1);
                } else {
                    int bb = m >> 11, s = m & 2047, hh = c >> 6, dd = c & 63;
                    size_t idx = (((size_t)(bb * NHEAD + hh)) * S_LEN + s) * DKH + dd;
                    *(__half2*)&o1[idx] = __floats2half2_rn(v0, v1);
                }
            }
        }
}

// ---------------- attention: all-single fp16 core, cp.async x2 -------------
// smem: K stage st at st*18432 (128 rows x 144B, [s][d]); V at 36864 +
// st*18432 (128 rows x 144B, [s][d]). Q staged in K buffer 0 at start.
#define K_BUF 18432
#define V_BASE 36864
#define ATT_SMEM_BYTES (V_BASE + 2 * K_BUF)   // 73728

__global__ __launch_bounds__(256, 1) void attn_mma(
    const __half* __restrict__ q16, const __half* __restrict__ k16,
    const __half* __restrict__ v16,
    __half* __restrict__ ohi, __half* __restrict__ olo)
{
    extern __shared__ char sm[];
    const int tid = threadIdx.x, lane = tid & 31, warp = tid >> 5;
    const int bh = blockIdx.y, q0 = blockIdx.x * 128;
    const __half* qb = q16 + (size_t)bh * S_LEN * DKH;
    const __half* kb = k16 + (size_t)bh * S_LEN * DKH;
    const __half* vb = v16 + (size_t)bh * S_LEN * DKH;

    // ---- stage Q into K buffer 0, grab persistent fragments ----
#pragma unroll
    for (int i = 0; i < 4; ++i) {
        int u = tid + i * 256;
        int r = u >> 3, c = u & 7;
        *(uint4*)(sm + r * 144 + c * 16) =
            *(const uint4*)((const char*)(qb + (size_t)(q0 + r) * DKH) + c * 16);
    }
    __syncthreads();
    unsigned qf[4][4];
#pragma unroll
    for (int ks = 0; ks < 4; ++ks) {
        int row = warp * 16 + (lane & 15);
        int col = ks * 16 + (lane >> 4) * 8;
        ldsm4(qf[ks], smem_u32(sm + row * 144 + col * 2));
    }
    __syncthreads();

    auto load_kv = [&](int st, int kt) {
        char* kd = sm + st * K_BUF;
        char* vd = sm + V_BASE + st * K_BUF;
#pragma unroll
        for (int i = 0; i < 4; ++i) {
            int u = tid + i * 256;
            int r = u >> 3, c = u & 7;
            CP16(smem_u32(kd + r * 144 + c * 16),
                 (const char*)(kb + (size_t)(kt + r) * DKH) + c * 16);
            CP16(smem_u32(vd + r * 144 + c * 16),
                 (const char*)(vb + (size_t)(kt + r) * DKH) + c * 16);
        }
    };

    float m_[2] = {-1e30f, -1e30f}, l_[2] = {0.f, 0.f};
    float o[8][4] = {};

    load_kv(0, 0);
    CP_COMMIT();

    for (int t = 0; t < 16; ++t) {
        const int st = t & 1;
        if (t + 1 < 16) { load_kv(st ^ 1, (t + 1) * 128); CP_COMMIT(); CP_WAIT1(); }
        else            { CP_WAIT0(); }
        __syncthreads();

        char* kd = sm + st * K_BUF;
        char* vd = sm + V_BASE + st * K_BUF;

        // ---- scores: 16 rows x 128 keys per warp, 1 term ----
        float sc[16][4] = {};
#pragma unroll
        for (int g = 0; g < 8; ++g) {
#pragma unroll
            for (int ks = 0; ks < 4; ++ks) {
                int row = g * 16 + (lane & 7) + ((lane & 16) >> 1);
                int col = ks * 16 + ((lane >> 3) & 1) * 8;
                unsigned kr[4];
                ldsm4(kr, smem_u32(kd + row * 144 + col * 2));
                mma_f16(sc[2 * g],     qf[ks], kr[0], kr[1]);
                mma_f16(sc[2 * g + 1], qf[ks], kr[2], kr[3]);
            }
        }
#pragma unroll
        for (int tt = 0; tt < 16; ++tt)
#pragma unroll
            for (int j = 0; j < 4; ++j) sc[tt][j] *= 0.0625f;

        // ---- online softmax (rows lane/4 and lane/4+8) ----
        float corr[2];
#pragma unroll
        for (int h = 0; h < 2; ++h) {
            float mt = -1e30f;
#pragma unroll
            for (int tt = 0; tt < 16; ++tt)
                mt = fmaxf(mt, fmaxf(sc[tt][2 * h], sc[tt][2 * h + 1]));
            mt = fmaxf(mt, __shfl_xor_sync(0xffffffffu, mt, 1));
            mt = fmaxf(mt, __shfl_xor_sync(0xffffffffu, mt, 2));
            float mn = fmaxf(m_[h], mt);
            float sum = 0.f;
#pragma unroll
            for (int tt = 0; tt < 16; ++tt) {
                sc[tt][2 * h]     = exp2f((sc[tt][2 * h]     - mn) * 1.44269504f);
                sc[tt][2 * h + 1] = exp2f((sc[tt][2 * h + 1] - mn) * 1.44269504f);
                sum += sc[tt][2 * h] + sc[tt][2 * h + 1];
            }
            sum += __shfl_xor_sync(0xffffffffu, sum, 1);
            sum += __shfl_xor_sync(0xffffffffu, sum, 2);
            corr[h] = exp2f((m_[h] - mn) * 1.44269504f);
            l_[h] = l_[h] * corr[h] + sum;
            m_[h] = mn;
        }
#pragma unroll
        for (int tt = 0; tt < 8; ++tt) {
            o[tt][0] *= corr[0]; o[tt][1] *= corr[0];
            o[tt][2] *= corr[1]; o[tt][3] *= corr[1];
        }

        // ---- PV: P(16x128, single fp16) x V via trans-ldmatrix ----
#pragma unroll
        for (int ks = 0; ks < 8; ++ks) {
            unsigned p_[4];
            p_[0] = pack_h2(sc[2 * ks][0],     sc[2 * ks][1]);
            p_[1] = pack_h2(sc[2 * ks][2],     sc[2 * ks][3]);
            p_[2] = pack_h2(sc[2 * ks + 1][0], sc[2 * ks + 1][1]);
            p_[3] = pack_h2(sc[2 * ks + 1][2], sc[2 * ks + 1][3]);
#pragma unroll
            for (int g = 0; g < 4; ++g) {
                int srow = ks * 16 + (lane & 7) + (((lane >> 3) & 1) << 3);
                int scol = g * 16 + (((lane >> 4) & 1) << 3);
                unsigned vr[4];
                ldsm4_t(vr, smem_u32(vd + srow * 144 + scol * 2));
                mma_f16(o[2 * g],     p_, vr[0], vr[1]);
                mma_f16(o[2 * g + 1], p_, vr[2], vr[3]);
            }
        }
        __syncthreads();
    }

    // ---- epilogue: normalize, split fp16 hi/lo to plain [B*S, D] ----
    const int b = bh >> 4, head = bh & 15;
#pragma unroll
    for (int h = 0; h < 2; ++h) {
        float inv = 1.f / l_[h];
        int s = q0 + warp * 16 + (lane >> 2) + 8 * h;
        size_t rowbase = ((size_t)(b * S_LEN + s)) * DMODEL + head * DKH;
#pragma unroll
        for (int tt = 0; tt < 8; ++tt) {
            int dd = tt * 8 + (lane & 3) * 2;
            unsigned H, L;
            split_pack_h(o[tt][2 * h] * inv, o[tt][2 * h + 1] * inv, H, L);
            *(unsigned*)&ohi[rowbase + dd] = H;
            *(unsigned*)&olo[rowbase + dd] = L;
        }
    }
}

// ---------------- launch ----------------
extern "C" void kernel_launch(void* const* d_in, const int* in_sizes, int n_in,
                              void* d_out, int out_size)
{
    const float* x  = (const float*)d_in[0];
    const float* Wq = (const float*)d_in[1];
    const float* bq = (const float*)d_in[2];
    const float* Wk = (const float*)d_in[3];
    const float* bk = (const float*)d_in[4];
    const float* Wv = (const float*)d_in[5];
    const float* bv = (const float*)d_in[6];
    const float* Wo = (const float*)d_in[7];
    const float* bo = (const float*)d_in[8];
    float* out = (float*)d_out;

    __half *xhi, *xlo, *wq16, *wk16, *wv16, *wo16, *q16, *k16, *v16, *ahi, *alo;
    float *bqf, *bkf;
    cudaGetSymbolAddress((void**)&xhi, g_xhi);
    cudaGetSymbolAddress((void**)&xlo, g_xlo);
    cudaGetSymbolAddress((void**)&wq16, g_wq16);
    cudaGetSymbolAddress((void**)&wk16, g_wk16);
    cudaGetSymbolAddress((void**)&wv16, g_wv16);
    cudaGetSymbolAddress((void**)&wo16, g_wo16);
    cudaGetSymbolAddress((void**)&bqf, g_bqf);
    cudaGetSymbolAddress((void**)&bkf, g_bkf);
    cudaGetSymbolAddress((void**)&q16, g_q16);
    cudaGetSymbolAddress((void**)&k16, g_k16);
    cudaGetSymbolAddress((void**)&v16, g_v16);
    cudaGetSymbolAddress((void**)&ahi, g_ahi);
    cudaGetSymbolAddress((void**)&alo, g_alo);

    const int WSZ = DMODEL * DMODEL;
    splitx_h<<<(M_TOT * DMODEL / 4 + 255) / 256, 256>>>(x, xhi, xlo, M_TOT * DMODEL / 4);
    fold_w<<<dim3(NHEAD, DMODEL / 128), 128>>>(Wq, wq16);
    fold_w<<<dim3(NHEAD, DMODEL / 128), 128>>>(Wk, wk16);
    fold_b<<<NHEAD, 32>>>(bq, bqf);
    fold_b<<<NHEAD, 32>>>(bk, bkf);
    tohalf_kernel<<<(WSZ / 4 + 255) / 256, 256>>>(Wv, wv16, WSZ / 4);
    tohalf_kernel<<<(WSZ / 4 + 255) / 256, 256>>>(Wo, wo16, WSZ / 4);

    cudaFuncSetAttribute(mma_gemm_f16<0>, cudaFuncAttributeMaxDynamicSharedMemorySize, GEMMF_SMEM);
    cudaFuncSetAttribute(mma_gemm_f16<1>, cudaFuncAttributeMaxDynamicSharedMemorySize, GEMMF_SMEM);

    dim3 gg(DMODEL / 128, M_TOT / 128);   // (8, 32)
    mma_gemm_f16<1><<<gg, 256, GEMMF_SMEM>>>(xhi, xlo, wq16, bqf, nullptr, q16);
    mma_gemm_f16<1><<<gg, 256, GEMMF_SMEM>>>(xhi, xlo, wk16, bkf, nullptr, k16);
    mma_gemm_f16<1><<<gg, 256, GEMMF_SMEM>>>(xhi, xlo, wv16, bv, nullptr, v16);

    cudaFuncSetAttribute(attn_mma, cudaFuncAttributeMaxDynamicSharedMemorySize,
                         ATT_SMEM_BYTES);
    attn_mma<<<dim3(S_LEN / 128, BH), 256, ATT_SMEM_BYTES>>>(
        q16, k16, v16, ahi, alo);

    mma_gemm_f16<0><<<gg, 256, GEMMF_SMEM>>>(ahi, alo, wo16, bo, out, nullptr);
}

// round 9
// speedup vs baseline: 6.2440x; 1.3037x over previous
#include <cuda_runtime.h>
#include <cuda_fp16.h>
#include <cstdint>

#define BATCH  2
#define S_LEN  2048
#define DMODEL 1024
#define NHEAD  16
#define DKH    64
#define M_TOT  (BATCH * S_LEN)
#define BH     (BATCH * NHEAD)

// ---------------- scratch (device globals; allocation-free) ----------------
__device__ __align__(16) __half g_x16[M_TOT * DMODEL];
__device__ __align__(16) __half g_wq16[DMODEL * DMODEL];   // folded
__device__ __align__(16) __half g_wk16[DMODEL * DMODEL];   // folded
__device__ __align__(16) __half g_wv16[DMODEL * DMODEL];
__device__ __align__(16) __half g_wo16[DMODEL * DMODEL];
__device__ __align__(16) float  g_bqf[DMODEL];             // folded bias
__device__ __align__(16) float  g_bkf[DMODEL];
__device__ __align__(16) __half g_q16[BH * S_LEN * DKH];
__device__ __align__(16) __half g_k16[BH * S_LEN * DKH];
__device__ __align__(16) __half g_v16[BH * S_LEN * DKH];   // natural [bh][s][d]
__device__ __align__(16) __half g_a16[M_TOT * DMODEL];     // attention out

// ---------------- helpers ----------------
__device__ __forceinline__ unsigned smem_u32(const void* p) {
    return (unsigned)__cvta_generic_to_shared(p);
}
__device__ __forceinline__ void ldsm4(unsigned* r, unsigned addr) {
    asm volatile("ldmatrix.sync.aligned.m8n8.x4.shared.b16 {%0,%1,%2,%3}, [%4];\n"
                 : "=r"(r[0]), "=r"(r[1]), "=r"(r[2]), "=r"(r[3]) : "r"(addr));
}
__device__ __forceinline__ void ldsm4_t(unsigned* r, unsigned addr) {
    asm volatile("ldmatrix.sync.aligned.m8n8.x4.trans.shared.b16 {%0,%1,%2,%3}, [%4];\n"
                 : "=r"(r[0]), "=r"(r[1]), "=r"(r[2]), "=r"(r[3]) : "r"(addr));
}
__device__ __forceinline__ void mma_f16(float* c, const unsigned* a, unsigned b0, unsigned b1) {
    asm volatile("mma.sync.aligned.m16n8k16.row.col.f32.f16.f16.f32 "
                 "{%0,%1,%2,%3}, {%4,%5,%6,%7}, {%8,%9}, {%0,%1,%2,%3};\n"
                 : "+f"(c[0]), "+f"(c[1]), "+f"(c[2]), "+f"(c[3])
                 : "r"(a[0]), "r"(a[1]), "r"(a[2]), "r"(a[3]), "r"(b0), "r"(b1));
}
__device__ __forceinline__ unsigned pack_h2(float x, float y) {
    __half2 h = __floats2half2_rn(x, y);
    return *(unsigned*)&h;
}
#define CP16(dst, src) \
    asm volatile("cp.async.cg.shared.global [%0], [%1], 16;\n" :: "r"(dst), "l"(src))
#define CP_COMMIT() asm volatile("cp.async.commit_group;\n" ::: "memory")
#define CP_WAIT1()  asm volatile("cp.async.wait_group 1;\n" ::: "memory")
#define CP_WAIT0()  asm volatile("cp.async.wait_group 0;\n" ::: "memory")

// ---------------- fp32 -> fp16 single ----------------
__global__ void tohalf_kernel(const float* __restrict__ in,
                              __half* __restrict__ out, int n4) {
    int i = blockIdx.x * blockDim.x + threadIdx.x;
    if (i >= n4) return;
    float4 v = ((const float4*)in)[i];
    *(__half2*)&out[4 * i]     = __floats2half2_rn(v.x, v.y);
    *(__half2*)&out[4 * i + 2] = __floats2half2_rn(v.z, v.w);
}

// ---------------- fold Fourier rank-2 map into Wq & Wk (per-head) ----------
__global__ void fold_w(const float* __restrict__ Wq, const float* __restrict__ Wk,
                       __half* __restrict__ Wqo, __half* __restrict__ Wko) {
    const int h = blockIdx.x;
    const int k = blockIdx.y * 128 + threadIdx.x;
    const float* W = blockIdx.z ? Wk : Wq;
    __half* Wo = blockIdx.z ? Wko : Wqo;
    float S1 = 0.f, S2 = 0.f;
#pragma unroll 8
    for (int d = 0; d < 64; ++d) {
        float w = W[(size_t)(h * 64 + d) * DMODEL + k];
        S1 += w;
        S2 += (d & 1) ? -w : w;
    }
    const float cu = 0.006472086912079611f;   // (sqrt(2)-1)/64
#pragma unroll 8
    for (int d = 0; d < 64; ++d) {
        float w = W[(size_t)(h * 64 + d) * DMODEL + k];
        float wn = w + cu * (S1 + ((d & 1) ? -S2 : S2));
        Wo[(size_t)(h * 64 + d) * DMODEL + k] = __float2half_rn(wn);
    }
}

// ---------------- fold both biases (fp32 out), one launch ------------------
__global__ void fold_b(const float* __restrict__ bq, const float* __restrict__ bk,
                       float* __restrict__ bqo, float* __restrict__ bko) {
    const int h = blockIdx.x;
    const int lane = threadIdx.x & 31;
    const float* b = (threadIdx.x >= 32) ? bk : bq;
    float* bo = (threadIdx.x >= 32) ? bko : bqo;
    float v0 = b[h * 64 + lane], v1 = b[h * 64 + lane + 32];
    float a = v0 + v1;
    float s = (lane & 1) ? -(v0 + v1) : (v0 + v1);
#pragma unroll
    for (int o = 16; o >= 1; o >>= 1) {
        a += __shfl_xor_sync(0xffffffffu, a, o);
        s += __shfl_xor_sync(0xffffffffu, s, o);
    }
    const float cu = 0.006472086912079611f;
    float adj = cu * (a + ((lane & 1) ? -s : s));
    bo[h * 64 + lane]      = v0 + adj;
    bo[h * 64 + lane + 32] = v1 + adj;
}

// ---------------- fp16 1-term GEMM: out = A@B^T + bias ---------------------
// A @0, B @10240 per stage (128 rows x 80B each). Stage = 20480 bytes.
// MODE 0: fp32 plain [M,D].  MODE 1: fp16 single in head layout.
#define GF_STAGE 20480
#define GEMMF_SMEM (2 * GF_STAGE)

template <int MODE>
__global__ __launch_bounds__(256) void mma_gemm_f16(
    const __half* __restrict__ A, const __half* __restrict__ B,
    const float* __restrict__ bias,
    float* __restrict__ outf, __half* __restrict__ o1)
{
    extern __shared__ char sm[];
    const int tid = threadIdx.x, lane = tid & 31, warp = tid >> 5;
    const int wm = warp >> 2, wn = warp & 3;
    const int m0 = blockIdx.y * 128, n0 = blockIdx.x * 128;

    auto load_stage = [&](int st, int kt) {
        char* base = sm + st * GF_STAGE;
#pragma unroll
        for (int i = 0; i < 2; ++i) {
            int u = tid + i * 256;
            int r = u >> 2, c = u & 3;
            unsigned off = (unsigned)(r * 80 + c * 16);
            CP16(smem_u32(base + off),
                 (const char*)(A + (size_t)(m0 + r) * DMODEL + kt) + c * 16);
            CP16(smem_u32(base + 10240 + off),
                 (const char*)(B + (size_t)(n0 + r) * DMODEL + kt) + c * 16);
        }
    };

    float d[4][4][4] = {};
    load_stage(0, 0);
    CP_COMMIT();

    for (int kb = 0; kb < 32; ++kb) {
        const int st = kb & 1;
        if (kb + 1 < 32) { load_stage(st ^ 1, (kb + 1) * 32); CP_COMMIT(); CP_WAIT1(); }
        else             { CP_WAIT0(); }
        __syncthreads();

        char* base = sm + st * GF_STAGE;
#pragma unroll
        for (int ks = 0; ks < 32; ks += 16) {
            unsigned ah[4][4];
#pragma unroll
            for (int i = 0; i < 4; ++i) {
                int row = wm * 64 + i * 16 + (lane & 15);
                int col = ks + (lane >> 4) * 8;
                ldsm4(ah[i], smem_u32(base + row * 80 + col * 2));
            }
#pragma unroll
            for (int g = 0; g < 2; ++g) {
                int row = wn * 32 + g * 16 + (lane & 7) + ((lane & 16) >> 1);
                int col = ks + ((lane >> 3) & 1) * 8;
                unsigned br[4];
                ldsm4(br, smem_u32(base + 10240 + row * 80 + col * 2));
#pragma unroll
                for (int i = 0; i < 4; ++i) {
                    mma_f16(d[i][2 * g],     ah[i], br[0], br[1]);
                    mma_f16(d[i][2 * g + 1], ah[i], br[2], br[3]);
                }
            }
        }
        __syncthreads();
    }

#pragma unroll
    for (int i = 0; i < 4; ++i)
#pragma unroll
        for (int j = 0; j < 4; ++j) {
            int c = n0 + wn * 32 + j * 8 + (lane & 3) * 2;
            float b0 = bias[c], b1 = bias[c + 1];
#pragma unroll
            for (int h = 0; h < 2; ++h) {
                int m = m0 + wm * 64 + i * 16 + (lane >> 2) + 8 * h;
                float v0 = d[i][j][2 * h] + b0, v1 = d[i][j][2 * h + 1] + b1;
                if (MODE == 0) {
                    *(float2*)&outf[(size_t)m * DMODEL + c] = make_float2(v0, v1);
                } else {
                    int bb = m >> 11, s = m & 2047, hh = c >> 6, dd = c & 63;
                    size_t idx = (((size_t)(bb * NHEAD + hh)) * S_LEN + s) * DKH + dd;
                    *(__half2*)&o1[idx] = __floats2half2_rn(v0, v1);
                }
            }
        }
}

// ---------------- attention: all-single fp16 core, cp.async x2 -------------
// smem: K stage st at st*18432 (128 rows x 144B, [s][d]); V at 36864 +
// st*18432 (128 rows x 144B, [s][d]). Q staged in K buffer 0 at start.
#define K_BUF 18432
#define V_BASE 36864
#define ATT_SMEM_BYTES (V_BASE + 2 * K_BUF)   // 73728

__global__ __launch_bounds__(256, 1) void attn_mma(
    const __half* __restrict__ q16, const __half* __restrict__ k16,
    const __half* __restrict__ v16, __half* __restrict__ aout)
{
    extern __shared__ char sm[];
    const int tid = threadIdx.x, lane = tid & 31, warp = tid >> 5;
    const int bh = blockIdx.y, q0 = blockIdx.x * 128;
    const __half* qb = q16 + (size_t)bh * S_LEN * DKH;
    const __half* kb = k16 + (size_t)bh * S_LEN * DKH;
    const __half* vb = v16 + (size_t)bh * S_LEN * DKH;

    // ---- stage Q into K buffer 0, grab persistent fragments ----
#pragma unroll
    for (int i = 0; i < 4; ++i) {
        int u = tid + i * 256;
        int r = u >> 3, c = u & 7;
        *(uint4*)(sm + r * 144 + c * 16) =
            *(const uint4*)((const char*)(qb + (size_t)(q0 + r) * DKH) + c * 16);
    }
    __syncthreads();
    unsigned qf[4][4];
#pragma unroll
    for (int ks = 0; ks < 4; ++ks) {
        int row = warp * 16 + (lane & 15);
        int col = ks * 16 + (lane >> 4) * 8;
        ldsm4(qf[ks], smem_u32(sm + row * 144 + col * 2));
    }
    __syncthreads();

    auto load_kv = [&](int st, int kt) {
        char* kd = sm + st * K_BUF;
        char* vd = sm + V_BASE + st * K_BUF;
#pragma unroll
        for (int i = 0; i < 4; ++i) {
            int u = tid + i * 256;
            int r = u >> 3, c = u & 7;
            CP16(smem_u32(kd + r * 144 + c * 16),
                 (const char*)(kb + (size_t)(kt + r) * DKH) + c * 16);
            CP16(smem_u32(vd + r * 144 + c * 16),
                 (const char*)(vb + (size_t)(kt + r) * DKH) + c * 16);
        }
    };

    float m_[2] = {-1e30f, -1e30f}, l_[2] = {0.f, 0.f};
    float o[8][4] = {};

    load_kv(0, 0);
    CP_COMMIT();

    for (int t = 0; t < 16; ++t) {
        const int st = t & 1;
        if (t + 1 < 16) { load_kv(st ^ 1, (t + 1) * 128); CP_COMMIT(); CP_WAIT1(); }
        else            { CP_WAIT0(); }
        __syncthreads();

        char* kd = sm + st * K_BUF;
        char* vd = sm + V_BASE + st * K_BUF;

        // ---- scores: 16 rows x 128 keys per warp, 1 term ----
        float sc[16][4] = {};
#pragma unroll
        for (int g = 0; g < 8; ++g) {
#pragma unroll
            for (int ks = 0; ks < 4; ++ks) {
                int row = g * 16 + (lane & 7) + ((lane & 16) >> 1);
                int col = ks * 16 + ((lane >> 3) & 1) * 8;
                unsigned kr[4];
                ldsm4(kr, smem_u32(kd + row * 144 + col * 2));
                mma_f16(sc[2 * g],     qf[ks], kr[0], kr[1]);
                mma_f16(sc[2 * g + 1], qf[ks], kr[2], kr[3]);
            }
        }
#pragma unroll
        for (int tt = 0; tt < 16; ++tt)
#pragma unroll
            for (int j = 0; j < 4; ++j) sc[tt][j] *= 0.0625f;

        // ---- online softmax (rows lane/4 and lane/4+8) ----
        float corr[2];
#pragma unroll
        for (int h = 0; h < 2; ++h) {
            float mt = -1e30f;
#pragma unroll
            for (int tt = 0; tt < 16; ++tt)
                mt = fmaxf(mt, fmaxf(sc[tt][2 * h], sc[tt][2 * h + 1]));
            mt = fmaxf(mt, __shfl_xor_sync(0xffffffffu, mt, 1));
            mt = fmaxf(mt, __shfl_xor_sync(0xffffffffu, mt, 2));
            float mn = fmaxf(m_[h], mt);
            float sum = 0.f;
#pragma unroll
            for (int tt = 0; tt < 16; ++tt) {
                sc[tt][2 * h]     = exp2f((sc[tt][2 * h]     - mn) * 1.44269504f);
                sc[tt][2 * h + 1] = exp2f((sc[tt][2 * h + 1] - mn) * 1.44269504f);
                sum += sc[tt][2 * h] + sc[tt][2 * h + 1];
            }
            sum += __shfl_xor_sync(0xffffffffu, sum, 1);
            sum += __shfl_xor_sync(0xffffffffu, sum, 2);
            corr[h] = exp2f((m_[h] - mn) * 1.44269504f);
            l_[h] = l_[h] * corr[h] + sum;
            m_[h] = mn;
        }
#pragma unroll
        for (int tt = 0; tt < 8; ++tt) {
            o[tt][0] *= corr[0]; o[tt][1] *= corr[0];
            o[tt][2] *= corr[1]; o[tt][3] *= corr[1];
        }

        // ---- PV: P(16x128, single fp16) x V via trans-ldmatrix ----
#pragma unroll
        for (int ks = 0; ks < 8; ++ks) {
            unsigned p_[4];
            p_[0] = pack_h2(sc[2 * ks][0],     sc[2 * ks][1]);
            p_[1] = pack_h2(sc[2 * ks][2],     sc[2 * ks][3]);
            p_[2] = pack_h2(sc[2 * ks + 1][0], sc[2 * ks + 1][1]);
            p_[3] = pack_h2(sc[2 * ks + 1][2], sc[2 * ks + 1][3]);
#pragma unroll
            for (int g = 0; g < 4; ++g) {
                int srow = ks * 16 + (lane & 7) + (((lane >> 3) & 1) << 3);
                int scol = g * 16 + (((lane >> 4) & 1) << 3);
                unsigned vr[4];
                ldsm4_t(vr, smem_u32(vd + srow * 144 + scol * 2));
                mma_f16(o[2 * g],     p_, vr[0], vr[1]);
                mma_f16(o[2 * g + 1], p_, vr[2], vr[3]);
            }
        }
        __syncthreads();
    }

    // ---- epilogue: normalize, single fp16 to plain [B*S, D] ----
    const int b = bh >> 4, head = bh & 15;
#pragma unroll
    for (int h = 0; h < 2; ++h) {
        float inv = 1.f / l_[h];
        int s = q0 + warp * 16 + (lane >> 2) + 8 * h;
        size_t rowbase = ((size_t)(b * S_LEN + s)) * DMODEL + head * DKH;
#pragma unroll
        for (int tt = 0; tt < 8; ++tt) {
            int dd = tt * 8 + (lane & 3) * 2;
            *(unsigned*)&aout[rowbase + dd] =
                pack_h2(o[tt][2 * h] * inv, o[tt][2 * h + 1] * inv);
        }
    }
}

// ---------------- launch ----------------
extern "C" void kernel_launch(void* const* d_in, const int* in_sizes, int n_in,
                              void* d_out, int out_size)
{
    const float* x  = (const float*)d_in[0];
    const float* Wq = (const float*)d_in[1];
    const float* bq = (const float*)d_in[2];
    const float* Wk = (const float*)d_in[3];
    const float* bk = (const float*)d_in[4];
    const float* Wv = (const float*)d_in[5];
    const float* bv = (const float*)d_in[6];
    const float* Wo = (const float*)d_in[7];
    const float* bo = (const float*)d_in[8];
    float* out = (float*)d_out;

    __half *x16, *wq16, *wk16, *wv16, *wo16, *q16, *k16, *v16, *a16;
    float *bqf, *bkf;
    cudaGetSymbolAddress((void**)&x16, g_x16);
    cudaGetSymbolAddress((void**)&wq16, g_wq16);
    cudaGetSymbolAddress((void**)&wk16, g_wk16);
    cudaGetSymbolAddress((void**)&wv16, g_wv16);
    cudaGetSymbolAddress((void**)&wo16, g_wo16);
    cudaGetSymbolAddress((void**)&bqf, g_bqf);
    cudaGetSymbolAddress((void**)&bkf, g_bkf);
    cudaGetSymbolAddress((void**)&q16, g_q16);
    cudaGetSymbolAddress((void**)&k16, g_k16);
    cudaGetSymbolAddress((void**)&v16, g_v16);
    cudaGetSymbolAddress((void**)&a16, g_a16);

    const int WSZ = DMODEL * DMODEL;
    tohalf_kernel<<<(M_TOT * DMODEL / 4 + 255) / 256, 256>>>(x, x16, M_TOT * DMODEL / 4);
    fold_w<<<dim3(NHEAD, DMODEL / 128, 2), 128>>>(Wq, Wk, wq16, wk16);
    fold_b<<<NHEAD, 64>>>(bq, bk, bqf, bkf);
    tohalf_kernel<<<(WSZ / 4 + 255) / 256, 256>>>(Wv, wv16, WSZ / 4);
    tohalf_kernel<<<(WSZ / 4 + 255) / 256, 256>>>(Wo, wo16, WSZ / 4);

    cudaFuncSetAttribute(mma_gemm_f16<0>, cudaFuncAttributeMaxDynamicSharedMemorySize, GEMMF_SMEM);
    cudaFuncSetAttribute(mma_gemm_f16<1>, cudaFuncAttributeMaxDynamicSharedMemorySize, GEMMF_SMEM);

    dim3 gg(DMODEL / 128, M_TOT / 128);   // (8, 32)
    mma_gemm_f16<1><<<gg, 256, GEMMF_SMEM>>>(x16, wq16, bqf, nullptr, q16);
    mma_gemm_f16<1><<<gg, 256, GEMMF_SMEM>>>(x16, wk16, bkf, nullptr, k16);
    mma_gemm_f16<1><<<gg, 256, GEMMF_SMEM>>>(x16, wv16, bv, nullptr, v16);

    cudaFuncSetAttribute(attn_mma, cudaFuncAttributeMaxDynamicSharedMemorySize,
                         ATT_SMEM_BYTES);
    attn_mma<<<dim3(S_LEN / 128, BH), 256, ATT_SMEM_BYTES>>>(q16, k16, v16, a16);

    mma_gemm_f16<0><<<gg, 256, GEMMF_SMEM>>>(a16, wo16, bo, out, nullptr);
}

// round 11
// speedup vs baseline: 6.3575x; 1.0182x over previous
#include <cuda_runtime.h>
#include <cuda_fp16.h>
#include <cstdint>

#define BATCH  2
#define S_LEN  2048
#define DMODEL 1024
#define NHEAD  16
#define DKH    64
#define M_TOT  (BATCH * S_LEN)
#define BH     (BATCH * NHEAD)

// ---------------- scratch (device globals; allocation-free) ----------------
__device__ __align__(16) __half g_x16[M_TOT * DMODEL];
__device__ __align__(16) __half g_wq16[DMODEL * DMODEL];   // folded
__device__ __align__(16) __half g_wk16[DMODEL * DMODEL];   // folded
__device__ __align__(16) __half g_wv16[DMODEL * DMODEL];
__device__ __align__(16) __half g_wo16[DMODEL * DMODEL];
__device__ __align__(16) float  g_bqf[DMODEL];             // folded bias
__device__ __align__(16) float  g_bkf[DMODEL];
__device__ __align__(16) __half g_q16[BH * S_LEN * DKH];
__device__ __align__(16) __half g_k16[BH * S_LEN * DKH];
__device__ __align__(16) __half g_v16[BH * S_LEN * DKH];   // natural [bh][s][d]
__device__ __align__(16) __half g_a16[M_TOT * DMODEL];     // attention out

// ---------------- helpers ----------------
__device__ __forceinline__ unsigned smem_u32(const void* p) {
    return (unsigned)__cvta_generic_to_shared(p);
}
__device__ __forceinline__ void ldsm4(unsigned* r, unsigned addr) {
    asm volatile("ldmatrix.sync.aligned.m8n8.x4.shared.b16 {%0,%1,%2,%3}, [%4];\n"
                 : "=r"(r[0]), "=r"(r[1]), "=r"(r[2]), "=r"(r[3]) : "r"(addr));
}
__device__ __forceinline__ void ldsm4_t(unsigned* r, unsigned addr) {
    asm volatile("ldmatrix.sync.aligned.m8n8.x4.trans.shared.b16 {%0,%1,%2,%3}, [%4];\n"
                 : "=r"(r[0]), "=r"(r[1]), "=r"(r[2]), "=r"(r[3]) : "r"(addr));
}
__device__ __forceinline__ void mma_f16(float* c, const unsigned* a, unsigned b0, unsigned b1) {
    asm volatile("mma.sync.aligned.m16n8k16.row.col.f32.f16.f16.f32 "
                 "{%0,%1,%2,%3}, {%4,%5,%6,%7}, {%8,%9}, {%0,%1,%2,%3};\n"
                 : "+f"(c[0]), "+f"(c[1]), "+f"(c[2]), "+f"(c[3])
                 : "r"(a[0]), "r"(a[1]), "r"(a[2]), "r"(a[3]), "r"(b0), "r"(b1));
}
__device__ __forceinline__ unsigned pack_h2(float x, float y) {
    __half2 h = __floats2half2_rn(x, y);
    return *(unsigned*)&h;
}
#define CP16(dst, src) \
    asm volatile("cp.async.cg.shared.global [%0], [%1], 16;\n" :: "r"(dst), "l"(src))
#define CP_COMMIT() asm volatile("cp.async.commit_group;\n" ::: "memory")
#define CP_WAIT1()  asm volatile("cp.async.wait_group 1;\n" ::: "memory")
#define CP_WAIT0()  asm volatile("cp.async.wait_group 0;\n" ::: "memory")

// ---------------- fp32 -> fp16 single ----------------
__global__ void tohalf_kernel(const float* __restrict__ in,
                              __half* __restrict__ out, int n4) {
    int i = blockIdx.x * blockDim.x + threadIdx.x;
    if (i >= n4) return;
    float4 v = ((const float4*)in)[i];
    *(__half2*)&out[4 * i]     = __floats2half2_rn(v.x, v.y);
    *(__half2*)&out[4 * i + 2] = __floats2half2_rn(v.z, v.w);
}

// ---------------- fp32 -> fp16 for two tensors in one launch ---------------
__global__ void tohalf2_kernel(const float* __restrict__ in0, __half* __restrict__ out0,
                               const float* __restrict__ in1, __half* __restrict__ out1,
                               int n4) {
    int i = blockIdx.x * blockDim.x + threadIdx.x;
    if (i >= n4) return;
    const float* in = blockIdx.z ? in1 : in0;
    __half* out = blockIdx.z ? out1 : out0;
    float4 v = ((const float4*)in)[i];
    *(__half2*)&out[4 * i]     = __floats2half2_rn(v.x, v.y);
    *(__half2*)&out[4 * i + 2] = __floats2half2_rn(v.z, v.w);
}

// ---------------- fold Fourier rank-2 map into Wq & Wk (per-head) ----------
__global__ void fold_w(const float* __restrict__ Wq, const float* __restrict__ Wk,
                       __half* __restrict__ Wqo, __half* __restrict__ Wko) {
    const int h = blockIdx.x;
    const int k = blockIdx.y * 128 + threadIdx.x;
    const float* W = blockIdx.z ? Wk : Wq;
    __half* Wo = blockIdx.z ? Wko : Wqo;
    float S1 = 0.f, S2 = 0.f;
#pragma unroll 8
    for (int d = 0; d < 64; ++d) {
        float w = W[(size_t)(h * 64 + d) * DMODEL + k];
        S1 += w;
        S2 += (d & 1) ? -w : w;
    }
    const float cu = 0.006472086912079611f;   // (sqrt(2)-1)/64
#pragma unroll 8
    for (int d = 0; d < 64; ++d) {
        float w = W[(size_t)(h * 64 + d) * DMODEL + k];
        float wn = w + cu * (S1 + ((d & 1) ? -S2 : S2));
        Wo[(size_t)(h * 64 + d) * DMODEL + k] = __float2half_rn(wn);
    }
}

// ---------------- fold both biases (fp32 out), one launch ------------------
__global__ void fold_b(const float* __restrict__ bq, const float* __restrict__ bk,
                       float* __restrict__ bqo, float* __restrict__ bko) {
    const int h = blockIdx.x;
    const int lane = threadIdx.x & 31;
    const float* b = (threadIdx.x >= 32) ? bk : bq;
    float* bo = (threadIdx.x >= 32) ? bko : bqo;
    float v0 = b[h * 64 + lane], v1 = b[h * 64 + lane + 32];
    float a = v0 + v1;
    float s = (lane & 1) ? -(v0 + v1) : (v0 + v1);
#pragma unroll
    for (int o = 16; o >= 1; o >>= 1) {
        a += __shfl_xor_sync(0xffffffffu, a, o);
        s += __shfl_xor_sync(0xffffffffu, s, o);
    }
    const float cu = 0.006472086912079611f;
    float adj = cu * (a + ((lane & 1) ? -s : s));
    bo[h * 64 + lane]      = v0 + adj;
    bo[h * 64 + lane + 32] = v1 + adj;
}

// ---------------- fp16 GEMM core (shared by QKV-fused and final) -----------
// A @0, B @10240 per stage (128 rows x 80B each). Stage = 20480 bytes.
#define GF_STAGE 20480
#define GEMMF_SMEM (2 * GF_STAGE)

struct GemmAcc { float d[4][4][4]; };

__device__ __forceinline__ void gemm_core(
    char* sm, const __half* __restrict__ A, const __half* __restrict__ B,
    int m0, int n0, int tid, int lane, int wm, int wn, GemmAcc& acc)
{
    auto load_stage = [&](int st, int kt) {
        char* base = sm + st * GF_STAGE;
#pragma unroll
        for (int i = 0; i < 2; ++i) {
            int u = tid + i * 256;
            int r = u >> 2, c = u & 3;
            unsigned off = (unsigned)(r * 80 + c * 16);
            CP16(smem_u32(base + off),
                 (const char*)(A + (size_t)(m0 + r) * DMODEL + kt) + c * 16);
            CP16(smem_u32(base + 10240 + off),
                 (const char*)(B + (size_t)(n0 + r) * DMODEL + kt) + c * 16);
        }
    };

    load_stage(0, 0);
    CP_COMMIT();

    for (int kb = 0; kb < 32; ++kb) {
        const int st = kb & 1;
        if (kb + 1 < 32) { load_stage(st ^ 1, (kb + 1) * 32); CP_COMMIT(); CP_WAIT1(); }
        else             { CP_WAIT0(); }
        __syncthreads();

        char* base = sm + st * GF_STAGE;
#pragma unroll
        for (int ks = 0; ks < 32; ks += 16) {
            unsigned ah[4][4];
#pragma unroll
            for (int i = 0; i < 4; ++i) {
                int row = wm * 64 + i * 16 + (lane & 15);
                int col = ks + (lane >> 4) * 8;
                ldsm4(ah[i], smem_u32(base + row * 80 + col * 2));
            }
#pragma unroll
            for (int g = 0; g < 2; ++g) {
                int row = wn * 32 + g * 16 + (lane & 7) + ((lane & 16) >> 1);
                int col = ks + ((lane >> 3) & 1) * 8;
                unsigned br[4];
                ldsm4(br, smem_u32(base + 10240 + row * 80 + col * 2));
#pragma unroll
                for (int i = 0; i < 4; ++i) {
                    mma_f16(acc.d[i][2 * g],     ah[i], br[0], br[1]);
                    mma_f16(acc.d[i][2 * g + 1], ah[i], br[2], br[3]);
                }
            }
        }
        __syncthreads();
    }
}

// ---------------- fused QKV GEMM: z selects {Q, K, V} ----------------------
__global__ __launch_bounds__(256) void gemm_qkv(
    const __half* __restrict__ x16,
    const __half* __restrict__ wq, const __half* __restrict__ wk,
    const __half* __restrict__ wv,
    const float* __restrict__ bq, const float* __restrict__ bk,
    const float* __restrict__ bv,
    __half* __restrict__ q16, __half* __restrict__ k16, __half* __restrict__ v16)
{
    extern __shared__ char sm[];
    const int tid = threadIdx.x, lane = tid & 31, warp = tid >> 5;
    const int wm = warp >> 2, wn = warp & 3;
    const int m0 = blockIdx.y * 128, n0 = blockIdx.x * 128;
    const int z = blockIdx.z;
    const __half* B = (z == 0) ? wq : (z == 1) ? wk : wv;
    const float* bias = (z == 0) ? bq : (z == 1) ? bk : bv;
    __half* o1 = (z == 0) ? q16 : (z == 1) ? k16 : v16;

    GemmAcc acc = {};
    gemm_core(sm, x16, B, m0, n0, tid, lane, wm, wn, acc);

#pragma unroll
    for (int i = 0; i < 4; ++i)
#pragma unroll
        for (int j = 0; j < 4; ++j) {
            int c = n0 + wn * 32 + j * 8 + (lane & 3) * 2;
            float b0 = bias[c], b1 = bias[c + 1];
#pragma unroll
            for (int h = 0; h < 2; ++h) {
                int m = m0 + wm * 64 + i * 16 + (lane >> 2) + 8 * h;
                float v0 = acc.d[i][j][2 * h] + b0, v1 = acc.d[i][j][2 * h + 1] + b1;
                int bb = m >> 11, s = m & 2047, hh = c >> 6, dd = c & 63;
                size_t idx = (((size_t)(bb * NHEAD + hh)) * S_LEN + s) * DKH + dd;
                *(__half2*)&o1[idx] = __floats2half2_rn(v0, v1);
            }
        }
}

// ---------------- final GEMM: fp32 plain output ----------------------------
__global__ __launch_bounds__(256) void gemm_out(
    const __half* __restrict__ A, const __half* __restrict__ B,
    const float* __restrict__ bias, float* __restrict__ outf)
{
    extern __shared__ char sm[];
    const int tid = threadIdx.x, lane = tid & 31, warp = tid >> 5;
    const int wm = warp >> 2, wn = warp & 3;
    const int m0 = blockIdx.y * 128, n0 = blockIdx.x * 128;

    GemmAcc acc = {};
    gemm_core(sm, A, B, m0, n0, tid, lane, wm, wn, acc);

#pragma unroll
    for (int i = 0; i < 4; ++i)
#pragma unroll
        for (int j = 0; j < 4; ++j) {
            int c = n0 + wn * 32 + j * 8 + (lane & 3) * 2;
            float b0 = bias[c], b1 = bias[c + 1];
#pragma unroll
            for (int h = 0; h < 2; ++h) {
                int m = m0 + wm * 64 + i * 16 + (lane >> 2) + 8 * h;
                *(float2*)&outf[(size_t)m * DMODEL + c] =
                    make_float2(acc.d[i][j][2 * h] + b0, acc.d[i][j][2 * h + 1] + b1);
            }
        }
}

// ---------------- attention: all-single fp16 core, cp.async x2 -------------
#define K_BUF 18432
#define V_BASE 36864
#define ATT_SMEM_BYTES (V_BASE + 2 * K_BUF)   // 73728

__global__ __launch_bounds__(256, 1) void attn_mma(
    const __half* __restrict__ q16, const __half* __restrict__ k16,
    const __half* __restrict__ v16, __half* __restrict__ aout)
{
    extern __shared__ char sm[];
    const int tid = threadIdx.x, lane = tid & 31, warp = tid >> 5;
    const int bh = blockIdx.y, q0 = blockIdx.x * 128;
    const __half* qb = q16 + (size_t)bh * S_LEN * DKH;
    const __half* kb = k16 + (size_t)bh * S_LEN * DKH;
    const __half* vb = v16 + (size_t)bh * S_LEN * DKH;

    // ---- stage Q into K buffer 0, grab persistent fragments ----
#pragma unroll
    for (int i = 0; i < 4; ++i) {
        int u = tid + i * 256;
        int r = u >> 3, c = u & 7;
        *(uint4*)(sm + r * 144 + c * 16) =
            *(const uint4*)((const char*)(qb + (size_t)(q0 + r) * DKH) + c * 16);
    }
    __syncthreads();
    unsigned qf[4][4];
#pragma unroll
    for (int ks = 0; ks < 4; ++ks) {
        int row = warp * 16 + (lane & 15);
        int col = ks * 16 + (lane >> 4) * 8;
        ldsm4(qf[ks], smem_u32(sm + row * 144 + col * 2));
    }
    __syncthreads();

    auto load_kv = [&](int st, int kt) {
        char* kd = sm + st * K_BUF;
        char* vd = sm + V_BASE + st * K_BUF;
#pragma unroll
        for (int i = 0; i < 4; ++i) {
            int u = tid + i * 256;
            int r = u >> 3, c = u & 7;
            CP16(smem_u32(kd + r * 144 + c * 16),
                 (const char*)(kb + (size_t)(kt + r) * DKH) + c * 16);
            CP16(smem_u32(vd + r * 144 + c * 16),
                 (const char*)(vb + (size_t)(kt + r) * DKH) + c * 16);
        }
    };

    float m_[2] = {-1e30f, -1e30f}, l_[2] = {0.f, 0.f};
    float o[8][4] = {};

    load_kv(0, 0);
    CP_COMMIT();

    for (int t = 0; t < 16; ++t) {
        const int st = t & 1;
        if (t + 1 < 16) { load_kv(st ^ 1, (t + 1) * 128); CP_COMMIT(); CP_WAIT1(); }
        else            { CP_WAIT0(); }
        __syncthreads();

        char* kd = sm + st * K_BUF;
        char* vd = sm + V_BASE + st * K_BUF;

        // ---- scores: 16 rows x 128 keys per warp, 1 term ----
        float sc[16][4] = {};
#pragma unroll
        for (int g = 0; g < 8; ++g) {
#pragma unroll
            for (int ks = 0; ks < 4; ++ks) {
                int row = g * 16 + (lane & 7) + ((lane & 16) >> 1);
                int col = ks * 16 + ((lane >> 3) & 1) * 8;
                unsigned kr[4];
                ldsm4(kr, smem_u32(kd + row * 144 + col * 2));
                mma_f16(sc[2 * g],     qf[ks], kr[0], kr[1]);
                mma_f16(sc[2 * g + 1], qf[ks], kr[2], kr[3]);
            }
        }
#pragma unroll
        for (int tt = 0; tt < 16; ++tt)
#pragma unroll
            for (int j = 0; j < 4; ++j) sc[tt][j] *= 0.0625f;

        // ---- online softmax (rows lane/4 and lane/4+8) ----
        float corr[2];
#pragma unroll
        for (int h = 0; h < 2; ++h) {
            float mt = -1e30f;
#pragma unroll
            for (int tt = 0; tt < 16; ++tt)
                mt = fmaxf(mt, fmaxf(sc[tt][2 * h], sc[tt][2 * h + 1]));
            mt = fmaxf(mt, __shfl_xor_sync(0xffffffffu, mt, 1));
            mt = fmaxf(mt, __shfl_xor_sync(0xffffffffu, mt, 2));
            float mn = fmaxf(m_[h], mt);
            float sum = 0.f;
#pragma unroll
            for (int tt = 0; tt < 16; ++tt) {
                sc[tt][2 * h]     = exp2f((sc[tt][2 * h]     - mn) * 1.44269504f);
                sc[tt][2 * h + 1] = exp2f((sc[tt][2 * h + 1] - mn) * 1.44269504f);
                sum += sc[tt][2 * h] + sc[tt][2 * h + 1];
            }
            sum += __shfl_xor_sync(0xffffffffu, sum, 1);
            sum += __shfl_xor_sync(0xffffffffu, sum, 2);
            corr[h] = exp2f((m_[h] - mn) * 1.44269504f);
            l_[h] = l_[h] * corr[h] + sum;
            m_[h] = mn;
        }
#pragma unroll
        for (int tt = 0; tt < 8; ++tt) {
            o[tt][0] *= corr[0]; o[tt][1] *= corr[0];
            o[tt][2] *= corr[1]; o[tt][3] *= corr[1];
        }

        // ---- PV: P(16x128, single fp16) x V via trans-ldmatrix ----
#pragma unroll
        for (int ks = 0; ks < 8; ++ks) {
            unsigned p_[4];
            p_[0] = pack_h2(sc[2 * ks][0],     sc[2 * ks][1]);
            p_[1] = pack_h2(sc[2 * ks][2],     sc[2 * ks][3]);
            p_[2] = pack_h2(sc[2 * ks + 1][0], sc[2 * ks + 1][1]);
            p_[3] = pack_h2(sc[2 * ks + 1][2], sc[2 * ks + 1][3]);
#pragma unroll
            for (int g = 0; g < 4; ++g) {
                int srow = ks * 16 + (lane & 7) + (((lane >> 3) & 1) << 3);
                int scol = g * 16 + (((lane >> 4) & 1) << 3);
                unsigned vr[4];
                ldsm4_t(vr, smem_u32(vd + srow * 144 + scol * 2));
                mma_f16(o[2 * g],     p_, vr[0], vr[1]);
                mma_f16(o[2 * g + 1], p_, vr[2], vr[3]);
            }
        }
        __syncthreads();
    }

    // ---- epilogue: normalize, single fp16 to plain [B*S, D] ----
    const int b = bh >> 4, head = bh & 15;
#pragma unroll
    for (int h = 0; h < 2; ++h) {
        float inv = 1.f / l_[h];
        int s = q0 + warp * 16 + (lane >> 2) + 8 * h;
        size_t rowbase = ((size_t)(b * S_LEN + s)) * DMODEL + head * DKH;
#pragma unroll
        for (int tt = 0; tt < 8; ++tt) {
            int dd = tt * 8 + (lane & 3) * 2;
            *(unsigned*)&aout[rowbase + dd] =
                pack_h2(o[tt][2 * h] * inv, o[tt][2 * h + 1] * inv);
        }
    }
}

// ---------------- launch ----------------
extern "C" void kernel_launch(void* const* d_in, const int* in_sizes, int n_in,
                              void* d_out, int out_size)
{
    const float* x  = (const float*)d_in[0];
    const float* Wq = (const float*)d_in[1];
    const float* bq = (const float*)d_in[2];
    const float* Wk = (const float*)d_in[3];
    const float* bk = (const float*)d_in[4];
    const float* Wv = (const float*)d_in[5];
    const float* bv = (const float*)d_in[6];
    const float* Wo = (const float*)d_in[7];
    const float* bo = (const float*)d_in[8];
    float* out = (float*)d_out;

    __half *x16, *wq16, *wk16, *wv16, *wo16, *q16, *k16, *v16, *a16;
    float *bqf, *bkf;
    cudaGetSymbolAddress((void**)&x16, g_x16);
    cudaGetSymbolAddress((void**)&wq16, g_wq16);
    cudaGetSymbolAddress((void**)&wk16, g_wk16);
    cudaGetSymbolAddress((void**)&wv16, g_wv16);
    cudaGetSymbolAddress((void**)&wo16, g_wo16);
    cudaGetSymbolAddress((void**)&bqf, g_bqf);
    cudaGetSymbolAddress((void**)&bkf, g_bkf);
    cudaGetSymbolAddress((void**)&q16, g_q16);
    cudaGetSymbolAddress((void**)&k16, g_k16);
    cudaGetSymbolAddress((void**)&v16, g_v16);
    cudaGetSymbolAddress((void**)&a16, g_a16);

    const int WSZ = DMODEL * DMODEL;
    tohalf_kernel<<<(M_TOT * DMODEL / 4 + 255) / 256, 256>>>(x, x16, M_TOT * DMODEL / 4);
    fold_w<<<dim3(NHEAD, DMODEL / 128, 2), 128>>>(Wq, Wk, wq16, wk16);
    fold_b<<<NHEAD, 64>>>(bq, bk, bqf, bkf);
    tohalf2_kernel<<<dim3((WSZ / 4 + 255) / 256, 1, 2), 256>>>(Wv, wv16, Wo, wo16, WSZ / 4);

    cudaFuncSetAttribute(gemm_qkv, cudaFuncAttributeMaxDynamicSharedMemorySize, GEMMF_SMEM);
    cudaFuncSetAttribute(gemm_out, cudaFuncAttributeMaxDynamicSharedMemorySize, GEMMF_SMEM);

    dim3 gq(DMODEL / 128, M_TOT / 128, 3);   // (8, 32, 3) = 768 CTAs
    gemm_qkv<<<gq, 256, GEMMF_SMEM>>>(x16, wq16, wk16, wv16, bqf, bkf, bv,
                                      q16, k16, v16);

    cudaFuncSetAttribute(attn_mma, cudaFuncAttributeMaxDynamicSharedMemorySize,
                         ATT_SMEM_BYTES);
    attn_mma<<<dim3(S_LEN / 128, BH), 256, ATT_SMEM_BYTES>>>(q16, k16, v16, a16);

    dim3 gg(DMODEL / 128, M_TOT / 128);      // (8, 32)
    gemm_out<<<gg, 256, GEMMF_SMEM>>>(a16, wo16, bo, out);
}

// round 12
// speedup vs baseline: 6.9448x; 1.0924x over previous
#include <cuda_runtime.h>
#include <cuda_fp16.h>
#include <cstdint>

#define BATCH  2
#define S_LEN  2048
#define DMODEL 1024
#define NHEAD  16
#define DKH    64
#define M_TOT  (BATCH * S_LEN)
#define BH     (BATCH * NHEAD)

// ---------------- scratch (device globals; allocation-free) ----------------
__device__ __align__(16) __half g_x16[M_TOT * DMODEL];
__device__ __align__(16) __half g_wq16[DMODEL * DMODEL];   // folded
__device__ __align__(16) __half g_wk16[DMODEL * DMODEL];   // folded
__device__ __align__(16) __half g_wv16[DMODEL * DMODEL];
__device__ __align__(16) __half g_wo16[DMODEL * DMODEL];
__device__ __align__(16) float  g_bqf[DMODEL];             // folded bias
__device__ __align__(16) float  g_bkf[DMODEL];
__device__ __align__(16) __half g_q16[BH * S_LEN * DKH];
__device__ __align__(16) __half g_k16[BH * S_LEN * DKH];
__device__ __align__(16) __half g_v16[BH * S_LEN * DKH];   // natural [bh][s][d]
__device__ __align__(16) __half g_a16[M_TOT * DMODEL];     // attention out

// ---------------- helpers ----------------
__device__ __forceinline__ unsigned smem_u32(const void* p) {
    return (unsigned)__cvta_generic_to_shared(p);
}
__device__ __forceinline__ void ldsm4(unsigned* r, unsigned addr) {
    asm volatile("ldmatrix.sync.aligned.m8n8.x4.shared.b16 {%0,%1,%2,%3}, [%4];\n"
                 : "=r"(r[0]), "=r"(r[1]), "=r"(r[2]), "=r"(r[3]) : "r"(addr));
}
__device__ __forceinline__ void ldsm4_t(unsigned* r, unsigned addr) {
    asm volatile("ldmatrix.sync.aligned.m8n8.x4.trans.shared.b16 {%0,%1,%2,%3}, [%4];\n"
                 : "=r"(r[0]), "=r"(r[1]), "=r"(r[2]), "=r"(r[3]) : "r"(addr));
}
__device__ __forceinline__ void mma_f16(float* c, const unsigned* a, unsigned b0, unsigned b1) {
    asm volatile("mma.sync.aligned.m16n8k16.row.col.f32.f16.f16.f32 "
                 "{%0,%1,%2,%3}, {%4,%5,%6,%7}, {%8,%9}, {%0,%1,%2,%3};\n"
                 : "+f"(c[0]), "+f"(c[1]), "+f"(c[2]), "+f"(c[3])
                 : "r"(a[0]), "r"(a[1]), "r"(a[2]), "r"(a[3]), "r"(b0), "r"(b1));
}
__device__ __forceinline__ unsigned pack_h2(float x, float y) {
    __half2 h = __floats2half2_rn(x, y);
    return *(unsigned*)&h;
}
// exp2 of two fp32 values -> packed half2, via cvt.f16x2 + ex2.approx.f16x2
__device__ __forceinline__ unsigned exp2_f16x2(float lo, float hi) {
    unsigned r, p;
    asm("cvt.rn.f16x2.f32 %0, %1, %2;" : "=r"(r) : "f"(hi), "f"(lo));
    asm("ex2.approx.f16x2 %0, %1;" : "=r"(p) : "r"(r));
    return p;
}
#define CP16(dst, src) \
    asm volatile("cp.async.cg.shared.global [%0], [%1], 16;\n" :: "r"(dst), "l"(src))
#define CP_COMMIT() asm volatile("cp.async.commit_group;\n" ::: "memory")
#define CP_WAIT1()  asm volatile("cp.async.wait_group 1;\n" ::: "memory")
#define CP_WAIT0()  asm volatile("cp.async.wait_group 0;\n" ::: "memory")

// ---------------- fp32 -> fp16 single ----------------
__global__ void tohalf_kernel(const float* __restrict__ in,
                              __half* __restrict__ out, int n4) {
    int i = blockIdx.x * blockDim.x + threadIdx.x;
    if (i >= n4) return;
    float4 v = ((const float4*)in)[i];
    *(__half2*)&out[4 * i]     = __floats2half2_rn(v.x, v.y);
    *(__half2*)&out[4 * i + 2] = __floats2half2_rn(v.z, v.w);
}

// ---------------- fp32 -> fp16 for two tensors in one launch ---------------
__global__ void tohalf2_kernel(const float* __restrict__ in0, __half* __restrict__ out0,
                               const float* __restrict__ in1, __half* __restrict__ out1,
                               int n4) {
    int i = blockIdx.x * blockDim.x + threadIdx.x;
    if (i >= n4) return;
    const float* in = blockIdx.z ? in1 : in0;
    __half* out = blockIdx.z ? out1 : out0;
    float4 v = ((const float4*)in)[i];
    *(__half2*)&out[4 * i]     = __floats2half2_rn(v.x, v.y);
    *(__half2*)&out[4 * i + 2] = __floats2half2_rn(v.z, v.w);
}

// ---------------- fold Fourier rank-2 map into Wq & Wk (per-head) ----------
__global__ void fold_w(const float* __restrict__ Wq, const float* __restrict__ Wk,
                       __half* __restrict__ Wqo, __half* __restrict__ Wko) {
    const int h = blockIdx.x;
    const int k = blockIdx.y * 128 + threadIdx.x;
    const float* W = blockIdx.z ? Wk : Wq;
    __half* Wo = blockIdx.z ? Wko : Wqo;
    float S1 = 0.f, S2 = 0.f;
#pragma unroll 8
    for (int d = 0; d < 64; ++d) {
        float w = W[(size_t)(h * 64 + d) * DMODEL + k];
        S1 += w;
        S2 += (d & 1) ? -w : w;
    }
    const float cu = 0.006472086912079611f;   // (sqrt(2)-1)/64
#pragma unroll 8
    for (int d = 0; d < 64; ++d) {
        float w = W[(size_t)(h * 64 + d) * DMODEL + k];
        float wn = w + cu * (S1 + ((d & 1) ? -S2 : S2));
        Wo[(size_t)(h * 64 + d) * DMODEL + k] = __float2half_rn(wn);
    }
}

// ---------------- fold both biases (fp32 out), one launch ------------------
__global__ void fold_b(const float* __restrict__ bq, const float* __restrict__ bk,
                       float* __restrict__ bqo, float* __restrict__ bko) {
    const int h = blockIdx.x;
    const int lane = threadIdx.x & 31;
    const float* b = (threadIdx.x >= 32) ? bk : bq;
    float* bo = (threadIdx.x >= 32) ? bko : bqo;
    float v0 = b[h * 64 + lane], v1 = b[h * 64 + lane + 32];
    float a = v0 + v1;
    float s = (lane & 1) ? -(v0 + v1) : (v0 + v1);
#pragma unroll
    for (int o = 16; o >= 1; o >>= 1) {
        a += __shfl_xor_sync(0xffffffffu, a, o);
        s += __shfl_xor_sync(0xffffffffu, s, o);
    }
    const float cu = 0.006472086912079611f;
    float adj = cu * (a + ((lane & 1) ? -s : s));
    bo[h * 64 + lane]      = v0 + adj;
    bo[h * 64 + lane + 32] = v1 + adj;
}

// ---------------- fp16 GEMM core (shared by QKV-fused and final) -----------
#define GF_STAGE 20480
#define GEMMF_SMEM (2 * GF_STAGE)

struct GemmAcc { float d[4][4][4]; };

__device__ __forceinline__ void gemm_core(
    char* sm, const __half* __restrict__ A, const __half* __restrict__ B,
    int m0, int n0, int tid, int lane, int wm, int wn, GemmAcc& acc)
{
    auto load_stage = [&](int st, int kt) {
        char* base = sm + st * GF_STAGE;
#pragma unroll
        for (int i = 0; i < 2; ++i) {
            int u = tid + i * 256;
            int r = u >> 2, c = u & 3;
            unsigned off = (unsigned)(r * 80 + c * 16);
            CP16(smem_u32(base + off),
                 (const char*)(A + (size_t)(m0 + r) * DMODEL + kt) + c * 16);
            CP16(smem_u32(base + 10240 + off),
                 (const char*)(B + (size_t)(n0 + r) * DMODEL + kt) + c * 16);
        }
    };

    load_stage(0, 0);
    CP_COMMIT();

    for (int kb = 0; kb < 32; ++kb) {
        const int st = kb & 1;
        if (kb + 1 < 32) { load_stage(st ^ 1, (kb + 1) * 32); CP_COMMIT(); CP_WAIT1(); }
        else             { CP_WAIT0(); }
        __syncthreads();

        char* base = sm + st * GF_STAGE;
#pragma unroll
        for (int ks = 0; ks < 32; ks += 16) {
            unsigned ah[4][4];
#pragma unroll
            for (int i = 0; i < 4; ++i) {
                int row = wm * 64 + i * 16 + (lane & 15);
                int col = ks + (lane >> 4) * 8;
                ldsm4(ah[i], smem_u32(base + row * 80 + col * 2));
            }
#pragma unroll
            for (int g = 0; g < 2; ++g) {
                int row = wn * 32 + g * 16 + (lane & 7) + ((lane & 16) >> 1);
                int col = ks + ((lane >> 3) & 1) * 8;
                unsigned br[4];
                ldsm4(br, smem_u32(base + 10240 + row * 80 + col * 2));
#pragma unroll
                for (int i = 0; i < 4; ++i) {
                    mma_f16(acc.d[i][2 * g],     ah[i], br[0], br[1]);
                    mma_f16(acc.d[i][2 * g + 1], ah[i], br[2], br[3]);
                }
            }
        }
        __syncthreads();
    }
}

// ---------------- fused QKV GEMM: z selects {Q, K, V} ----------------------
__global__ __launch_bounds__(256) void gemm_qkv(
    const __half* __restrict__ x16,
    const __half* __restrict__ wq, const __half* __restrict__ wk,
    const __half* __restrict__ wv,
    const float* __restrict__ bq, const float* __restrict__ bk,
    const float* __restrict__ bv,
    __half* __restrict__ q16, __half* __restrict__ k16, __half* __restrict__ v16)
{
    extern __shared__ char sm[];
    const int tid = threadIdx.x, lane = tid & 31, warp = tid >> 5;
    const int wm = warp >> 2, wn = warp & 3;
    const int m0 = blockIdx.y * 128, n0 = blockIdx.x * 128;
    const int z = blockIdx.z;
    const __half* B = (z == 0) ? wq : (z == 1) ? wk : wv;
    const float* bias = (z == 0) ? bq : (z == 1) ? bk : bv;
    __half* o1 = (z == 0) ? q16 : (z == 1) ? k16 : v16;

    GemmAcc acc = {};
    gemm_core(sm, x16, B, m0, n0, tid, lane, wm, wn, acc);

#pragma unroll
    for (int i = 0; i < 4; ++i)
#pragma unroll
        for (int j = 0; j < 4; ++j) {
            int c = n0 + wn * 32 + j * 8 + (lane & 3) * 2;
            float b0 = bias[c], b1 = bias[c + 1];
#pragma unroll
            for (int h = 0; h < 2; ++h) {
                int m = m0 + wm * 64 + i * 16 + (lane >> 2) + 8 * h;
                float v0 = acc.d[i][j][2 * h] + b0, v1 = acc.d[i][j][2 * h + 1] + b1;
                int bb = m >> 11, s = m & 2047, hh = c >> 6, dd = c & 63;
                size_t idx = (((size_t)(bb * NHEAD + hh)) * S_LEN + s) * DKH + dd;
                *(__half2*)&o1[idx] = __floats2half2_rn(v0, v1);
            }
        }
}

// ---------------- final GEMM: fp32 plain output ----------------------------
__global__ __launch_bounds__(256) void gemm_out(
    const __half* __restrict__ A, const __half* __restrict__ B,
    const float* __restrict__ bias, float* __restrict__ outf)
{
    extern __shared__ char sm[];
    const int tid = threadIdx.x, lane = tid & 31, warp = tid >> 5;
    const int wm = warp >> 2, wn = warp & 3;
    const int m0 = blockIdx.y * 128, n0 = blockIdx.x * 128;

    GemmAcc acc = {};
    gemm_core(sm, A, B, m0, n0, tid, lane, wm, wn, acc);

#pragma unroll
    for (int i = 0; i < 4; ++i)
#pragma unroll
        for (int j = 0; j < 4; ++j) {
            int c = n0 + wn * 32 + j * 8 + (lane & 3) * 2;
            float b0 = bias[c], b1 = bias[c + 1];
#pragma unroll
            for (int h = 0; h < 2; ++h) {
                int m = m0 + wm * 64 + i * 16 + (lane >> 2) + 8 * h;
                *(float2*)&outf[(size_t)m * DMODEL + c] =
                    make_float2(acc.d[i][j][2 * h] + b0, acc.d[i][j][2 * h + 1] + b1);
            }
        }
}

// ---------------- attention v2: half-tile softmax, f16x2 exp, ones-MMA l ---
// smem: Q at 0 (128x144B), K stages at 18432 + st*18432, V at 55296 + st*18432.
#define ATT_Q_OFF 0
#define ATT_K_OFF 18432
#define ATT_V_OFF (3 * 18432)
#define ATT_SMEM_BYTES (5 * 18432)   // 92160; x2 CTAs = 184320 <= 228KB

__global__ __launch_bounds__(256, 2) void attn_mma(
    const __half* __restrict__ q16, const __half* __restrict__ k16,
    const __half* __restrict__ v16, __half* __restrict__ aout)
{
    extern __shared__ char sm[];
    const int tid = threadIdx.x, lane = tid & 31, warp = tid >> 5;
    const int bh = blockIdx.y, q0 = blockIdx.x * 128;
    const __half* qb = q16 + (size_t)bh * S_LEN * DKH;
    const __half* kb = k16 + (size_t)bh * S_LEN * DKH;
    const __half* vb = v16 + (size_t)bh * S_LEN * DKH;

    // ---- stage Q into its own region (plain stores; first sync covers it) --
#pragma unroll
    for (int i = 0; i < 4; ++i) {
        int u = tid + i * 256;
        int r = u >> 3, c = u & 7;
        *(uint4*)(sm + ATT_Q_OFF + r * 144 + c * 16) =
            *(const uint4*)((const char*)(qb + (size_t)(q0 + r) * DKH) + c * 16);
    }

    auto load_kv = [&](int st, int kt) {
        char* kd = sm + ATT_K_OFF + st * 18432;
        char* vd = sm + ATT_V_OFF + st * 18432;
#pragma unroll
        for (int i = 0; i < 4; ++i) {
            int u = tid + i * 256;
            int r = u >> 3, c = u & 7;
            CP16(smem_u32(kd + r * 144 + c * 16),
                 (const char*)(kb + (size_t)(kt + r) * DKH) + c * 16);
            CP16(smem_u32(vd + r * 144 + c * 16),
                 (const char*)(vb + (size_t)(kt + r) * DKH) + c * 16);
        }
    };

    float m_[2] = {-1e30f, -1e30f};
    float o[8][4] = {};
    float o_l[4] = {};   // ones-column accumulator: col0 = running row-sum (l)
    const unsigned ones_b = (lane < 4) ? 0x3C003C00u : 0u;  // B[k][0]=1 frag
    const float cexp = 0.0625f * 1.44269504f;

    load_kv(0, 0);
    CP_COMMIT();

    for (int t = 0; t < 16; ++t) {
        const int st = t & 1;
        if (t + 1 < 16) { load_kv(st ^ 1, (t + 1) * 128); CP_COMMIT(); CP_WAIT1(); }
        else            { CP_WAIT0(); }
        __syncthreads();

        char* kd = sm + ATT_K_OFF + st * 18432;
        char* vd = sm + ATT_V_OFF + st * 18432;

#pragma unroll
        for (int half = 0; half < 2; ++half) {
            // ---- QK for 64 keys (kd-outer so Q frag is reloaded, not held) --
            float sc[8][4] = {};
#pragma unroll
            for (int kd4 = 0; kd4 < 4; ++kd4) {
                unsigned qt[4];
                int qrow = warp * 16 + (lane & 15);
                int qcol = kd4 * 16 + (lane >> 4) * 8;
                ldsm4(qt, smem_u32(sm + ATT_Q_OFF + qrow * 144 + qcol * 2));
#pragma unroll
                for (int g = 0; g < 4; ++g) {
                    int krow = half * 64 + g * 16 + (lane & 7) + ((lane & 16) >> 1);
                    int kcol = kd4 * 16 + ((lane >> 3) & 1) * 8;
                    unsigned kr[4];
                    ldsm4(kr, smem_u32(kd + krow * 144 + kcol * 2));
                    mma_f16(sc[2 * g],     qt, kr[0], kr[1]);
                    mma_f16(sc[2 * g + 1], qt, kr[2], kr[3]);
                }
            }

            // ---- online max + corr (raw scores; scale folded into exp) -----
            float corr[2], nmc[2];
#pragma unroll
            for (int h = 0; h < 2; ++h) {
                float mt = -1e30f;
#pragma unroll
                for (int tt = 0; tt < 8; ++tt)
                    mt = fmaxf(mt, fmaxf(sc[tt][2 * h], sc[tt][2 * h + 1]));
                mt = fmaxf(mt, __shfl_xor_sync(0xffffffffu, mt, 1));
                mt = fmaxf(mt, __shfl_xor_sync(0xffffffffu, mt, 2));
                float mn = fmaxf(m_[h], mt);
                corr[h] = exp2f((m_[h] - mn) * cexp);
                m_[h] = mn;
                nmc[h] = mn * cexp;
            }
#pragma unroll
            for (int tt = 0; tt < 8; ++tt) {
                o[tt][0] *= corr[0]; o[tt][1] *= corr[0];
                o[tt][2] *= corr[1]; o[tt][3] *= corr[1];
            }
            o_l[0] *= corr[0]; o_l[1] *= corr[0];
            o_l[2] *= corr[1]; o_l[3] *= corr[1];

            // ---- exp in f16x2, packed directly as P fragments --------------
            unsigned p[8][2];
#pragma unroll
            for (int tt = 0; tt < 8; ++tt) {
                float a0 = fmaf(sc[tt][0], cexp, -nmc[0]);
                float a1 = fmaf(sc[tt][1], cexp, -nmc[0]);
                float a2 = fmaf(sc[tt][2], cexp, -nmc[1]);
                float a3 = fmaf(sc[tt][3], cexp, -nmc[1]);
                p[tt][0] = exp2_f16x2(a0, a1);
                p[tt][1] = exp2_f16x2(a2, a3);
            }

            // ---- PV (+ ones-column MMA accumulates l) ----------------------
#pragma unroll
            for (int ks = 0; ks < 4; ++ks) {
                unsigned a_[4] = {p[2 * ks][0], p[2 * ks][1],
                                  p[2 * ks + 1][0], p[2 * ks + 1][1]};
#pragma unroll
                for (int g = 0; g < 4; ++g) {
                    int srow = half * 64 + ks * 16 + (lane & 7) + (((lane >> 3) & 1) << 3);
                    int scol = g * 16 + (((lane >> 4) & 1) << 3);
                    unsigned vr[4];
                    ldsm4_t(vr, smem_u32(vd + srow * 144 + scol * 2));
                    mma_f16(o[2 * g],     a_, vr[0], vr[1]);
                    mma_f16(o[2 * g + 1], a_, vr[2], vr[3]);
                }
                mma_f16(o_l, a_, ones_b, ones_b);
            }
        }
        __syncthreads();
    }

    // ---- l lives in col 0 of the ones-column accum (lanes with lane%4==0) --
    float l0 = __shfl_sync(0xffffffffu, o_l[0], lane & ~3);
    float l1 = __shfl_sync(0xffffffffu, o_l[2], lane & ~3);
    float inv0 = 1.f / l0, inv1 = 1.f / l1;

    const int b = bh >> 4, head = bh & 15;
#pragma unroll
    for (int h = 0; h < 2; ++h) {
        float inv = h ? inv1 : inv0;
        int s = q0 + warp * 16 + (lane >> 2) + 8 * h;
        size_t rowbase = ((size_t)(b * S_LEN + s)) * DMODEL + head * DKH;
#pragma unroll
        for (int tt = 0; tt < 8; ++tt) {
            int dd = tt * 8 + (lane & 3) * 2;
            *(unsigned*)&aout[rowbase + dd] =
                pack_h2(o[tt][2 * h] * inv, o[tt][2 * h + 1] * inv);
        }
    }
}

// ---------------- launch ----------------
extern "C" void kernel_launch(void* const* d_in, const int* in_sizes, int n_in,
                              void* d_out, int out_size)
{
    const float* x  = (const float*)d_in[0];
    const float* Wq = (const float*)d_in[1];
    const float* bq = (const float*)d_in[2];
    const float* Wk = (const float*)d_in[3];
    const float* bk = (const float*)d_in[4];
    const float* Wv = (const float*)d_in[5];
    const float* bv = (const float*)d_in[6];
    const float* Wo = (const float*)d_in[7];
    const float* bo = (const float*)d_in[8];
    float* out = (float*)d_out;

    __half *x16, *wq16, *wk16, *wv16, *wo16, *q16, *k16, *v16, *a16;
    float *bqf, *bkf;
    cudaGetSymbolAddress((void**)&x16, g_x16);
    cudaGetSymbolAddress((void**)&wq16, g_wq16);
    cudaGetSymbolAddress((void**)&wk16, g_wk16);
    cudaGetSymbolAddress((void**)&wv16, g_wv16);
    cudaGetSymbolAddress((void**)&wo16, g_wo16);
    cudaGetSymbolAddress((void**)&bqf, g_bqf);
    cudaGetSymbolAddress((void**)&bkf, g_bkf);
    cudaGetSymbolAddress((void**)&q16, g_q16);
    cudaGetSymbolAddress((void**)&k16, g_k16);
    cudaGetSymbolAddress((void**)&v16, g_v16);
    cudaGetSymbolAddress((void**)&a16, g_a16);

    const int WSZ = DMODEL * DMODEL;
    tohalf_kernel<<<(M_TOT * DMODEL / 4 + 255) / 256, 256>>>(x, x16, M_TOT * DMODEL / 4);
    fold_w<<<dim3(NHEAD, DMODEL / 128, 2), 128>>>(Wq, Wk, wq16, wk16);
    fold_b<<<NHEAD, 64>>>(bq, bk, bqf, bkf);
    tohalf2_kernel<<<dim3((WSZ / 4 + 255) / 256, 1, 2), 256>>>(Wv, wv16, Wo, wo16, WSZ / 4);

    cudaFuncSetAttribute(gemm_qkv, cudaFuncAttributeMaxDynamicSharedMemorySize, GEMMF_SMEM);
    cudaFuncSetAttribute(gemm_out, cudaFuncAttributeMaxDynamicSharedMemorySize, GEMMF_SMEM);

    dim3 gq(DMODEL / 128, M_TOT / 128, 3);   // (8, 32, 3) = 768 CTAs
    gemm_qkv<<<gq, 256, GEMMF_SMEM>>>(x16, wq16, wk16, wv16, bqf, bkf, bv,
                                      q16, k16, v16);

    cudaFuncSetAttribute(attn_mma, cudaFuncAttributeMaxDynamicSharedMemorySize,
                         ATT_SMEM_BYTES);
    attn_mma<<<dim3(S_LEN / 128, BH), 256, ATT_SMEM_BYTES>>>(q16, k16, v16, a16);

    dim3 gg(DMODEL / 128, M_TOT / 128);      // (8, 32)
    gemm_out<<<gg, 256, GEMMF_SMEM>>>(a16, wo16, bo, out);
}

// round 13
// speedup vs baseline: 7.3686x; 1.0610x over previous
#include <cuda_runtime.h>
#include <cuda_fp16.h>
#include <cstdint>

#define BATCH  2
#define S_LEN  2048
#define DMODEL 1024
#define NHEAD  16
#define DKH    64
#define M_TOT  (BATCH * S_LEN)
#define BH     (BATCH * NHEAD)

// ---------------- scratch (device globals; allocation-free) ----------------
__device__ __align__(16) __half g_x16[M_TOT * DMODEL];
__device__ __align__(16) __half g_wq16[DMODEL * DMODEL];   // folded
__device__ __align__(16) __half g_wk16[DMODEL * DMODEL];   // folded
__device__ __align__(16) __half g_wv16[DMODEL * DMODEL];
__device__ __align__(16) __half g_wo16[DMODEL * DMODEL];
__device__ __align__(16) float  g_bqf[DMODEL];             // folded bias
__device__ __align__(16) float  g_bkf[DMODEL];
__device__ __align__(16) __half g_q16[BH * S_LEN * DKH];
__device__ __align__(16) __half g_k16[BH * S_LEN * DKH];
__device__ __align__(16) __half g_v16[BH * S_LEN * DKH];   // natural [bh][s][d]
__device__ __align__(16) __half g_a16[M_TOT * DMODEL];     // attention out

// ---------------- helpers ----------------
__device__ __forceinline__ unsigned smem_u32(const void* p) {
    return (unsigned)__cvta_generic_to_shared(p);
}
__device__ __forceinline__ void ldsm4(unsigned* r, unsigned addr) {
    asm volatile("ldmatrix.sync.aligned.m8n8.x4.shared.b16 {%0,%1,%2,%3}, [%4];\n"
                 : "=r"(r[0]), "=r"(r[1]), "=r"(r[2]), "=r"(r[3]) : "r"(addr));
}
__device__ __forceinline__ void ldsm4_t(unsigned* r, unsigned addr) {
    asm volatile("ldmatrix.sync.aligned.m8n8.x4.trans.shared.b16 {%0,%1,%2,%3}, [%4];\n"
                 : "=r"(r[0]), "=r"(r[1]), "=r"(r[2]), "=r"(r[3]) : "r"(addr));
}
__device__ __forceinline__ void mma_f16(float* c, const unsigned* a, unsigned b0, unsigned b1) {
    asm volatile("mma.sync.aligned.m16n8k16.row.col.f32.f16.f16.f32 "
                 "{%0,%1,%2,%3}, {%4,%5,%6,%7}, {%8,%9}, {%0,%1,%2,%3};\n"
                 : "+f"(c[0]), "+f"(c[1]), "+f"(c[2]), "+f"(c[3])
                 : "r"(a[0]), "r"(a[1]), "r"(a[2]), "r"(a[3]), "r"(b0), "r"(b1));
}
__device__ __forceinline__ unsigned pack_h2(float x, float y) {
    __half2 h = __floats2half2_rn(x, y);
    return *(unsigned*)&h;
}
// exp2 of two fp32 values -> packed half2
__device__ __forceinline__ unsigned exp2_f16x2(float lo, float hi) {
    unsigned r, p;
    asm("cvt.rn.f16x2.f32 %0, %1, %2;" : "=r"(r) : "f"(hi), "f"(lo));
    asm("ex2.approx.f16x2 %0, %1;" : "=r"(p) : "r"(r));
    return p;
}
#define CP16(dst, src) \
    asm volatile("cp.async.cg.shared.global [%0], [%1], 16;\n" :: "r"(dst), "l"(src))
#define CP_COMMIT() asm volatile("cp.async.commit_group;\n" ::: "memory")
#define CP_WAIT2()  asm volatile("cp.async.wait_group 2;\n" ::: "memory")
#define CP_WAIT1()  asm volatile("cp.async.wait_group 1;\n" ::: "memory")
#define CP_WAIT0()  asm volatile("cp.async.wait_group 0;\n" ::: "memory")

// ---------------- mega prep: all conversions + folds in ONE launch ---------
// block ranges: [0,4096) x->fp16 | [4096,5120) Wv | [5120,6144) Wo |
//               [6144,6272) fold_w (Wq/Wk) | [6272,6276) fold_b
#define PREP_XB  4096
#define PREP_WVB 1024
#define PREP_WOB 1024
#define PREP_FWB 128
#define PREP_FBB 4
#define PREP_BLOCKS (PREP_XB + PREP_WVB + PREP_WOB + PREP_FWB + PREP_FBB)

__global__ __launch_bounds__(256) void mega_prep(
    const float* __restrict__ x,  __half* __restrict__ x16,
    const float* __restrict__ Wv, __half* __restrict__ wv16,
    const float* __restrict__ Wo, __half* __restrict__ wo16,
    const float* __restrict__ Wq, const float* __restrict__ Wk,
    __half* __restrict__ wq16, __half* __restrict__ wk16,
    const float* __restrict__ bq, const float* __restrict__ bk,
    float* __restrict__ bqf, float* __restrict__ bkf)
{
    const int bid = blockIdx.x, tid = threadIdx.x;

    if (bid < PREP_XB + PREP_WVB + PREP_WOB) {
        const float* in;
        __half* out;
        int i;
        if (bid < PREP_XB)                  { in = x;  out = x16;  i = bid * 256 + tid; }
        else if (bid < PREP_XB + PREP_WVB)  { in = Wv; out = wv16; i = (bid - PREP_XB) * 256 + tid; }
        else                                { in = Wo; out = wo16; i = (bid - PREP_XB - PREP_WVB) * 256 + tid; }
        float4 v = ((const float4*)in)[i];
        *(__half2*)&out[4 * (size_t)i]     = __floats2half2_rn(v.x, v.y);
        *(__half2*)&out[4 * (size_t)i + 2] = __floats2half2_rn(v.z, v.w);
        return;
    }

    const float cu = 0.006472086912079611f;   // (sqrt(2)-1)/64

    if (bid < PREP_XB + PREP_WVB + PREP_WOB + PREP_FWB) {
        // fold_w: 128 blocks x 256 threads
        int idx = bid - (PREP_XB + PREP_WVB + PREP_WOB);
        int z = idx & 1, rest = idx >> 1;
        int h = rest & 15, kg = rest >> 4;       // kg 0..3
        int k = kg * 256 + tid;
        const float* W = z ? Wk : Wq;
        __half* Wdst = z ? wk16 : wq16;
        float S1 = 0.f, S2 = 0.f;
#pragma unroll 8
        for (int d = 0; d < 64; ++d) {
            float w = W[(size_t)(h * 64 + d) * DMODEL + k];
            S1 += w;
            S2 += (d & 1) ? -w : w;
        }
#pragma unroll 8
        for (int d = 0; d < 64; ++d) {
            float w = W[(size_t)(h * 64 + d) * DMODEL + k];
            float wn = w + cu * (S1 + ((d & 1) ? -S2 : S2));
            Wdst[(size_t)(h * 64 + d) * DMODEL + k] = __float2half_rn(wn);
        }
        return;
    }

    // fold_b: 4 blocks x 8 warps; each warp handles one (h, which) task
    {
        int idx = bid - (PREP_XB + PREP_WVB + PREP_WOB + PREP_FWB);
        int w = tid >> 5, lane = tid & 31;
        int task = idx * 8 + w;                 // 0..31
        int h = task >> 1, which = task & 1;
        const float* b = which ? bk : bq;
        float* bo = which ? bkf : bqf;
        float v0 = b[h * 64 + lane], v1 = b[h * 64 + lane + 32];
        float a = v0 + v1;
        float s = (lane & 1) ? -(v0 + v1) : (v0 + v1);
#pragma unroll
        for (int o = 16; o >= 1; o >>= 1) {
            a += __shfl_xor_sync(0xffffffffu, a, o);
            s += __shfl_xor_sync(0xffffffffu, s, o);
        }
        float adj = cu * (a + ((lane & 1) ? -s : s));
        bo[h * 64 + lane]      = v0 + adj;
        bo[h * 64 + lane + 32] = v1 + adj;
    }
}

// ---------------- fp16 GEMM core: 3-stage cp.async pipeline ----------------
// A @0, B @10240 per stage (128 rows x 80B each). Stage = 20480 bytes.
#define GF_STAGE 20480
#define GEMMF_SMEM (3 * GF_STAGE)    // 61440; 2 CTAs/SM = 122880

struct GemmAcc { float d[4][4][4]; };

__device__ __forceinline__ void gemm_core(
    char* sm, const __half* __restrict__ A, const __half* __restrict__ B,
    int m0, int n0, int tid, int lane, int wm, int wn, GemmAcc& acc)
{
    auto load_stage = [&](int st, int kt) {
        char* base = sm + st * GF_STAGE;
#pragma unroll
        for (int i = 0; i < 2; ++i) {
            int u = tid + i * 256;
            int r = u >> 2, c = u & 3;
            unsigned off = (unsigned)(r * 80 + c * 16);
            CP16(smem_u32(base + off),
                 (const char*)(A + (size_t)(m0 + r) * DMODEL + kt) + c * 16);
            CP16(smem_u32(base + 10240 + off),
                 (const char*)(B + (size_t)(n0 + r) * DMODEL + kt) + c * 16);
        }
    };

    load_stage(0, 0);
    CP_COMMIT();
    load_stage(1, 32);
    CP_COMMIT();

    int st = 0;
    for (int kb = 0; kb < 32; ++kb) {
        if (kb + 2 < 32) {
            int nst = st + 2; if (nst >= 3) nst -= 3;
            load_stage(nst, (kb + 2) * 32);
            CP_COMMIT();
            CP_WAIT2();
        } else if (kb + 1 < 32) {
            CP_WAIT1();
        } else {
            CP_WAIT0();
        }
        __syncthreads();

        char* base = sm + st * GF_STAGE;
#pragma unroll
        for (int ks = 0; ks < 32; ks += 16) {
            unsigned ah[4][4];
#pragma unroll
            for (int i = 0; i < 4; ++i) {
                int row = wm * 64 + i * 16 + (lane & 15);
                int col = ks + (lane >> 4) * 8;
                ldsm4(ah[i], smem_u32(base + row * 80 + col * 2));
            }
#pragma unroll
            for (int g = 0; g < 2; ++g) {
                int row = wn * 32 + g * 16 + (lane & 7) + ((lane & 16) >> 1);
                int col = ks + ((lane >> 3) & 1) * 8;
                unsigned br[4];
                ldsm4(br, smem_u32(base + 10240 + row * 80 + col * 2));
#pragma unroll
                for (int i = 0; i < 4; ++i) {
                    mma_f16(acc.d[i][2 * g],     ah[i], br[0], br[1]);
                    mma_f16(acc.d[i][2 * g + 1], ah[i], br[2], br[3]);
                }
            }
        }
        __syncthreads();
        if (++st == 3) st = 0;
    }
}

// ---------------- fused QKV GEMM: z selects {Q, K, V} ----------------------
__global__ __launch_bounds__(256, 2) void gemm_qkv(
    const __half* __restrict__ x16,
    const __half* __restrict__ wq, const __half* __restrict__ wk,
    const __half* __restrict__ wv,
    const float* __restrict__ bq, const float* __restrict__ bk,
    const float* __restrict__ bv,
    __half* __restrict__ q16, __half* __restrict__ k16, __half* __restrict__ v16)
{
    extern __shared__ char sm[];
    const int tid = threadIdx.x, lane = tid & 31, warp = tid >> 5;
    const int wm = warp >> 2, wn = warp & 3;
    const int m0 = blockIdx.y * 128, n0 = blockIdx.x * 128;
    const int z = blockIdx.z;
    const __half* B = (z == 0) ? wq : (z == 1) ? wk : wv;
    const float* bias = (z == 0) ? bq : (z == 1) ? bk : bv;
    __half* o1 = (z == 0) ? q16 : (z == 1) ? k16 : v16;

    GemmAcc acc = {};
    gemm_core(sm, x16, B, m0, n0, tid, lane, wm, wn, acc);

#pragma unroll
    for (int i = 0; i < 4; ++i)
#pragma unroll
        for (int j = 0; j < 4; ++j) {
            int c = n0 + wn * 32 + j * 8 + (lane & 3) * 2;
            float b0 = bias[c], b1 = bias[c + 1];
#pragma unroll
            for (int h = 0; h < 2; ++h) {
                int m = m0 + wm * 64 + i * 16 + (lane >> 2) + 8 * h;
                float v0 = acc.d[i][j][2 * h] + b0, v1 = acc.d[i][j][2 * h + 1] + b1;
                int bb = m >> 11, s = m & 2047, hh = c >> 6, dd = c & 63;
                size_t idx = (((size_t)(bb * NHEAD + hh)) * S_LEN + s) * DKH + dd;
                *(__half2*)&o1[idx] = __floats2half2_rn(v0, v1);
            }
        }
}

// ---------------- final GEMM: fp32 plain output ----------------------------
__global__ __launch_bounds__(256, 2) void gemm_out(
    const __half* __restrict__ A, const __half* __restrict__ B,
    const float* __restrict__ bias, float* __restrict__ outf)
{
    extern __shared__ char sm[];
    const int tid = threadIdx.x, lane = tid & 31, warp = tid >> 5;
    const int wm = warp >> 2, wn = warp & 3;
    const int m0 = blockIdx.y * 128, n0 = blockIdx.x * 128;

    GemmAcc acc = {};
    gemm_core(sm, A, B, m0, n0, tid, lane, wm, wn, acc);

#pragma unroll
    for (int i = 0; i < 4; ++i)
#pragma unroll
        for (int j = 0; j < 4; ++j) {
            int c = n0 + wn * 32 + j * 8 + (lane & 3) * 2;
            float b0 = bias[c], b1 = bias[c + 1];
#pragma unroll
            for (int h = 0; h < 2; ++h) {
                int m = m0 + wm * 64 + i * 16 + (lane >> 2) + 8 * h;
                *(float2*)&outf[(size_t)m * DMODEL + c] =
                    make_float2(acc.d[i][j][2 * h] + b0, acc.d[i][j][2 * h + 1] + b1);
            }
        }
}

// ---------------- attention v2 (unchanged from R12) ------------------------
#define ATT_Q_OFF 0
#define ATT_K_OFF 18432
#define ATT_V_OFF (3 * 18432)
#define ATT_SMEM_BYTES (5 * 18432)   // 92160; x2 CTAs = 184320

__global__ __launch_bounds__(256, 2) void attn_mma(
    const __half* __restrict__ q16, const __half* __restrict__ k16,
    const __half* __restrict__ v16, __half* __restrict__ aout)
{
    extern __shared__ char sm[];
    const int tid = threadIdx.x, lane = tid & 31, warp = tid >> 5;
    const int bh = blockIdx.y, q0 = blockIdx.x * 128;
    const __half* qb = q16 + (size_t)bh * S_LEN * DKH;
    const __half* kb = k16 + (size_t)bh * S_LEN * DKH;
    const __half* vb = v16 + (size_t)bh * S_LEN * DKH;

#pragma unroll
    for (int i = 0; i < 4; ++i) {
        int u = tid + i * 256;
        int r = u >> 3, c = u & 7;
        *(uint4*)(sm + ATT_Q_OFF + r * 144 + c * 16) =
            *(const uint4*)((const char*)(qb + (size_t)(q0 + r) * DKH) + c * 16);
    }

    auto load_kv = [&](int st, int kt) {
        char* kd = sm + ATT_K_OFF + st * 18432;
        char* vd = sm + ATT_V_OFF + st * 18432;
#pragma unroll
        for (int i = 0; i < 4; ++i) {
            int u = tid + i * 256;
            int r = u >> 3, c = u & 7;
            CP16(smem_u32(kd + r * 144 + c * 16),
                 (const char*)(kb + (size_t)(kt + r) * DKH) + c * 16);
            CP16(smem_u32(vd + r * 144 + c * 16),
                 (const char*)(vb + (size_t)(kt + r) * DKH) + c * 16);
        }
    };

    float m_[2] = {-1e30f, -1e30f};
    float o[8][4] = {};
    float o_l[4] = {};
    const unsigned ones_b = (lane < 4) ? 0x3C003C00u : 0u;
    const float cexp = 0.0625f * 1.44269504f;

    load_kv(0, 0);
    CP_COMMIT();

    for (int t = 0; t < 16; ++t) {
        const int st = t & 1;
        if (t + 1 < 16) { load_kv(st ^ 1, (t + 1) * 128); CP_COMMIT(); CP_WAIT1(); }
        else            { CP_WAIT0(); }
        __syncthreads();

        char* kd = sm + ATT_K_OFF + st * 18432;
        char* vd = sm + ATT_V_OFF + st * 18432;

#pragma unroll
        for (int half = 0; half < 2; ++half) {
            float sc[8][4] = {};
#pragma unroll
            for (int kd4 = 0; kd4 < 4; ++kd4) {
                unsigned qt[4];
                int qrow = warp * 16 + (lane & 15);
                int qcol = kd4 * 16 + (lane >> 4) * 8;
                ldsm4(qt, smem_u32(sm + ATT_Q_OFF + qrow * 144 + qcol * 2));
#pragma unroll
                for (int g = 0; g < 4; ++g) {
                    int krow = half * 64 + g * 16 + (lane & 7) + ((lane & 16) >> 1);
                    int kcol = kd4 * 16 + ((lane >> 3) & 1) * 8;
                    unsigned kr[4];
                    ldsm4(kr, smem_u32(kd + krow * 144 + kcol * 2));
                    mma_f16(sc[2 * g],     qt, kr[0], kr[1]);
                    mma_f16(sc[2 * g + 1], qt, kr[2], kr[3]);
                }
            }

            float corr[2], nmc[2];
#pragma unroll
            for (int h = 0; h < 2; ++h) {
                float mt = -1e30f;
#pragma unroll
                for (int tt = 0; tt < 8; ++tt)
                    mt = fmaxf(mt, fmaxf(sc[tt][2 * h], sc[tt][2 * h + 1]));
                mt = fmaxf(mt, __shfl_xor_sync(0xffffffffu, mt, 1));
                mt = fmaxf(mt, __shfl_xor_sync(0xffffffffu, mt, 2));
                float mn = fmaxf(m_[h], mt);
                corr[h] = exp2f((m_[h] - mn) * cexp);
                m_[h] = mn;
                nmc[h] = mn * cexp;
            }
#pragma unroll
            for (int tt = 0; tt < 8; ++tt) {
                o[tt][0] *= corr[0]; o[tt][1] *= corr[0];
                o[tt][2] *= corr[1]; o[tt][3] *= corr[1];
            }
            o_l[0] *= corr[0]; o_l[1] *= corr[0];
            o_l[2] *= corr[1]; o_l[3] *= corr[1];

            unsigned p[8][2];
#pragma unroll
            for (int tt = 0; tt < 8; ++tt) {
                float a0 = fmaf(sc[tt][0], cexp, -nmc[0]);
                float a1 = fmaf(sc[tt][1], cexp, -nmc[0]);
                float a2 = fmaf(sc[tt][2], cexp, -nmc[1]);
                float a3 = fmaf(sc[tt][3], cexp, -nmc[1]);
                p[tt][0] = exp2_f16x2(a0, a1);
                p[tt][1] = exp2_f16x2(a2, a3);
            }

#pragma unroll
            for (int ks = 0; ks < 4; ++ks) {
                unsigned a_[4] = {p[2 * ks][0], p[2 * ks][1],
                                  p[2 * ks + 1][0], p[2 * ks + 1][1]};
#pragma unroll
                for (int g = 0; g < 4; ++g) {
                    int srow = half * 64 + ks * 16 + (lane & 7) + (((lane >> 3) & 1) << 3);
                    int scol = g * 16 + (((lane >> 4) & 1) << 3);
                    unsigned vr[4];
                    ldsm4_t(vr, smem_u32(vd + srow * 144 + scol * 2));
                    mma_f16(o[2 * g],     a_, vr[0], vr[1]);
                    mma_f16(o[2 * g + 1], a_, vr[2], vr[3]);
                }
                mma_f16(o_l, a_, ones_b, ones_b);
            }
        }
        __syncthreads();
    }

    float l0 = __shfl_sync(0xffffffffu, o_l[0], lane & ~3);
    float l1 = __shfl_sync(0xffffffffu, o_l[2], lane & ~3);
    float inv0 = 1.f / l0, inv1 = 1.f / l1;

    const int b = bh >> 4, head = bh & 15;
#pragma unroll
    for (int h = 0; h < 2; ++h) {
        float inv = h ? inv1 : inv0;
        int s = q0 + warp * 16 + (lane >> 2) + 8 * h;
        size_t rowbase = ((size_t)(b * S_LEN + s)) * DMODEL + head * DKH;
#pragma unroll
        for (int tt = 0; tt < 8; ++tt) {
            int dd = tt * 8 + (lane & 3) * 2;
            *(unsigned*)&aout[rowbase + dd] =
                pack_h2(o[tt][2 * h] * inv, o[tt][2 * h + 1] * inv);
        }
    }
}

// ---------------- launch ----------------
extern "C" void kernel_launch(void* const* d_in, const int* in_sizes, int n_in,
                              void* d_out, int out_size)
{
    const float* x  = (const float*)d_in[0];
    const float* Wq = (const float*)d_in[1];
    const float* bq = (const float*)d_in[2];
    const float* Wk = (const float*)d_in[3];
    const float* bk = (const float*)d_in[4];
    const float* Wv = (const float*)d_in[5];
    const float* bv = (const float*)d_in[6];
    const float* Wo = (const float*)d_in[7];
    const float* bo = (const float*)d_in[8];
    float* out = (float*)d_out;

    __half *x16, *wq16, *wk16, *wv16, *wo16, *q16, *k16, *v16, *a16;
    float *bqf, *bkf;
    cudaGetSymbolAddress((void**)&x16, g_x16);
    cudaGetSymbolAddress((void**)&wq16, g_wq16);
    cudaGetSymbolAddress((void**)&wk16, g_wk16);
    cudaGetSymbolAddress((void**)&wv16, g_wv16);
    cudaGetSymbolAddress((void**)&wo16, g_wo16);
    cudaGetSymbolAddress((void**)&bqf, g_bqf);
    cudaGetSymbolAddress((void**)&bkf, g_bkf);
    cudaGetSymbolAddress((void**)&q16, g_q16);
    cudaGetSymbolAddress((void**)&k16, g_k16);
    cudaGetSymbolAddress((void**)&v16, g_v16);
    cudaGetSymbolAddress((void**)&a16, g_a16);

    mega_prep<<<PREP_BLOCKS, 256>>>(x, x16, Wv, wv16, Wo, wo16,
                                    Wq, Wk, wq16, wk16, bq, bk, bqf, bkf);

    cudaFuncSetAttribute(gemm_qkv, cudaFuncAttributeMaxDynamicSharedMemorySize, GEMMF_SMEM);
    cudaFuncSetAttribute(gemm_out, cudaFuncAttributeMaxDynamicSharedMemorySize, GEMMF_SMEM);

    dim3 gq(DMODEL / 128, M_TOT / 128, 3);   // (8, 32, 3) = 768 CTAs
    gemm_qkv<<<gq, 256, GEMMF_SMEM>>>(x16, wq16, wk16, wv16, bqf, bkf, bv,
                                      q16, k16, v16);

    cudaFuncSetAttribute(attn_mma, cudaFuncAttributeMaxDynamicSharedMemorySize,
                         ATT_SMEM_BYTES);
    attn_mma<<<dim3(S_LEN / 128, BH), 256, ATT_SMEM_BYTES>>>(q16, k16, v16, a16);

    dim3 gg(DMODEL / 128, M_TOT / 128);      // (8, 32)
    gemm_out<<<gg, 256, GEMMF_SMEM>>>(a16, wo16, bo, out);
}

// round 17
// speedup vs baseline: 7.5078x; 1.0189x over previous
#include <cuda_runtime.h>
#include <cuda_fp16.h>
#include <cstdint>

#define BATCH  2
#define S_LEN  2048
#define DMODEL 1024
#define NHEAD  16
#define DKH    64
#define M_TOT  (BATCH * S_LEN)
#define BH     (BATCH * NHEAD)

// ---------------- scratch (device globals; allocation-free) ----------------
__device__ __align__(16) __half g_x16[M_TOT * DMODEL];
__device__ __align__(16) __half g_wq16[DMODEL * DMODEL];   // folded
__device__ __align__(16) __half g_wk16[DMODEL * DMODEL];   // folded
__device__ __align__(16) __half g_wv16[DMODEL * DMODEL];
__device__ __align__(16) __half g_wo16[DMODEL * DMODEL];
__device__ __align__(16) float  g_bqf[DMODEL];             // folded bias
__device__ __align__(16) float  g_bkf[DMODEL];
__device__ __align__(16) __half g_q16[BH * S_LEN * DKH];
__device__ __align__(16) __half g_k16[BH * S_LEN * DKH];
__device__ __align__(16) __half g_v16[BH * S_LEN * DKH];   // natural [bh][s][d]
__device__ __align__(16) __half g_a16[M_TOT * DMODEL];     // attention out

// ---------------- helpers ----------------
__device__ __forceinline__ unsigned smem_u32(const void* p) {
    return (unsigned)__cvta_generic_to_shared(p);
}
__device__ __forceinline__ void ldsm4(unsigned* r, unsigned addr) {
    asm volatile("ldmatrix.sync.aligned.m8n8.x4.shared.b16 {%0,%1,%2,%3}, [%4];\n"
                 : "=r"(r[0]), "=r"(r[1]), "=r"(r[2]), "=r"(r[3]) : "r"(addr));
}
__device__ __forceinline__ void ldsm4_t(unsigned* r, unsigned addr) {
    asm volatile("ldmatrix.sync.aligned.m8n8.x4.trans.shared.b16 {%0,%1,%2,%3}, [%4];\n"
                 : "=r"(r[0]), "=r"(r[1]), "=r"(r[2]), "=r"(r[3]) : "r"(addr));
}
__device__ __forceinline__ void mma_f16(float* c, const unsigned* a, unsigned b0, unsigned b1) {
    asm volatile("mma.sync.aligned.m16n8k16.row.col.f32.f16.f16.f32 "
                 "{%0,%1,%2,%3}, {%4,%5,%6,%7}, {%8,%9}, {%0,%1,%2,%3};\n"
                 : "+f"(c[0]), "+f"(c[1]), "+f"(c[2]), "+f"(c[3])
                 : "r"(a[0]), "r"(a[1]), "r"(a[2]), "r"(a[3]), "r"(b0), "r"(b1));
}
__device__ __forceinline__ unsigned pack_h2(float x, float y) {
    __half2 h = __floats2half2_rn(x, y);
    return *(unsigned*)&h;
}
// exp2 of two fp32 values -> packed half2
__device__ __forceinline__ unsigned exp2_f16x2(float lo, float hi) {
    unsigned r, p;
    asm("cvt.rn.f16x2.f32 %0, %1, %2;" : "=r"(r) : "f"(hi), "f"(lo));
    asm("ex2.approx.f16x2 %0, %1;" : "=r"(p) : "r"(r));
    return p;
}
#define CP16(dst, src) \
    asm volatile("cp.async.cg.shared.global [%0], [%1], 16;\n" :: "r"(dst), "l"(src))
#define CP_COMMIT() asm volatile("cp.async.commit_group;\n" ::: "memory")
#define CP_WAIT1()  asm volatile("cp.async.wait_group 1;\n" ::: "memory")
#define CP_WAIT0()  asm volatile("cp.async.wait_group 0;\n" ::: "memory")

// ---------------- mega prep: all conversions + folds in ONE launch ---------
#define PREP_XB  4096
#define PREP_WVB 1024
#define PREP_WOB 1024
#define PREP_FWB 128
#define PREP_FBB 4
#define PREP_BLOCKS (PREP_XB + PREP_WVB + PREP_WOB + PREP_FWB + PREP_FBB)

__global__ __launch_bounds__(256) void mega_prep(
    const float* __restrict__ x,  __half* __restrict__ x16,
    const float* __restrict__ Wv, __half* __restrict__ wv16,
    const float* __restrict__ Wo, __half* __restrict__ wo16,
    const float* __restrict__ Wq, const float* __restrict__ Wk,
    __half* __restrict__ wq16, __half* __restrict__ wk16,
    const float* __restrict__ bq, const float* __restrict__ bk,
    float* __restrict__ bqf, float* __restrict__ bkf)
{
    const int bid = blockIdx.x, tid = threadIdx.x;

    if (bid < PREP_XB + PREP_WVB + PREP_WOB) {
        const float* in;
        __half* out;
        int i;
        if (bid < PREP_XB)                  { in = x;  out = x16;  i = bid * 256 + tid; }
        else if (bid < PREP_XB + PREP_WVB)  { in = Wv; out = wv16; i = (bid - PREP_XB) * 256 + tid; }
        else                                { in = Wo; out = wo16; i = (bid - PREP_XB - PREP_WVB) * 256 + tid; }
        float4 v = ((const float4*)in)[i];
        *(__half2*)&out[4 * (size_t)i]     = __floats2half2_rn(v.x, v.y);
        *(__half2*)&out[4 * (size_t)i + 2] = __floats2half2_rn(v.z, v.w);
        return;
    }

    const float cu = 0.006472086912079611f;   // (sqrt(2)-1)/64

    if (bid < PREP_XB + PREP_WVB + PREP_WOB + PREP_FWB) {
        int idx = bid - (PREP_XB + PREP_WVB + PREP_WOB);
        int z = idx & 1, rest = idx >> 1;
        int h = rest & 15, kg = rest >> 4;
        int k = kg * 256 + tid;
        const float* W = z ? Wk : Wq;
        __half* Wdst = z ? wk16 : wq16;
        float S1 = 0.f, S2 = 0.f;
#pragma unroll 8
        for (int d = 0; d < 64; ++d) {
            float w = W[(size_t)(h * 64 + d) * DMODEL + k];
            S1 += w;
            S2 += (d & 1) ? -w : w;
        }
#pragma unroll 8
        for (int d = 0; d < 64; ++d) {
            float w = W[(size_t)(h * 64 + d) * DMODEL + k];
            float wn = w + cu * (S1 + ((d & 1) ? -S2 : S2));
            Wdst[(size_t)(h * 64 + d) * DMODEL + k] = __float2half_rn(wn);
        }
        return;
    }

    {
        int idx = bid - (PREP_XB + PREP_WVB + PREP_WOB + PREP_FWB);
        int w = tid >> 5, lane = tid & 31;
        int task = idx * 8 + w;
        int h = task >> 1, which = task & 1;
        const float* b = which ? bk : bq;
        float* bo = which ? bkf : bqf;
        float v0 = b[h * 64 + lane], v1 = b[h * 64 + lane + 32];
        float a = v0 + v1;
        float s = (lane & 1) ? -(v0 + v1) : (v0 + v1);
#pragma unroll
        for (int o = 16; o >= 1; o >>= 1) {
            a += __shfl_xor_sync(0xffffffffu, a, o);
            s += __shfl_xor_sync(0xffffffffu, s, o);
        }
        float adj = cu * (a + ((lane & 1) ? -s : s));
        bo[h * 64 + lane]      = v0 + adj;
        bo[h * 64 + lane + 32] = v1 + adj;
    }
}

// ---------------- fp16 GEMM core: 3-stage, CORRECT single-barrier ----------
// Order per k-block: WAIT(own) -> syncthreads (publish) -> issue prefetch ->
// compute. RAW: wait+sync guarantee stage kb fully visible. WAR: prefetch
// target (kb+2)%3 == (kb-1)%3 was read pre-barrier.
#define GF_STAGE 20480
#define GEMMF_SMEM (3 * GF_STAGE)    // 61440; 2 CTAs/SM = 122880

struct GemmAcc { float d[4][4][4]; };

__device__ __forceinline__ void gemm_core(
    char* sm, const __half* __restrict__ A, const __half* __restrict__ B,
    int m0, int n0, int tid, int lane, int wm, int wn, GemmAcc& acc)
{
    auto load_stage = [&](int st, int kt) {
        char* base = sm + st * GF_STAGE;
#pragma unroll
        for (int i = 0; i < 2; ++i) {
            int u = tid + i * 256;
            int r = u >> 2, c = u & 3;
            unsigned off = (unsigned)(r * 80 + c * 16);
            CP16(smem_u32(base + off),
                 (const char*)(A + (size_t)(m0 + r) * DMODEL + kt) + c * 16);
            CP16(smem_u32(base + 10240 + off),
                 (const char*)(B + (size_t)(n0 + r) * DMODEL + kt) + c * 16);
        }
    };

    load_stage(0, 0);
    CP_COMMIT();
    load_stage(1, 32);
    CP_COMMIT();

    int st = 0;
    for (int kb = 0; kb < 32; ++kb) {
        if (kb < 31) CP_WAIT1();     // own group kb retired (1 newer pending)
        else         CP_WAIT0();
        __syncthreads();             // publish ALL threads' completions
        if (kb + 2 < 32) {           // prefetch overlaps the compute below
            int nst = st + 2; if (nst >= 3) nst -= 3;
            load_stage(nst, (kb + 2) * 32);
            CP_COMMIT();
        }

        char* base = sm + st * GF_STAGE;
#pragma unroll
        for (int ks = 0; ks < 32; ks += 16) {
            unsigned bf[2][4], ah[4][4];
#pragma unroll
            for (int g = 0; g < 2; ++g) {
                int row = wn * 32 + g * 16 + (lane & 7) + ((lane & 16) >> 1);
                int col = ks + ((lane >> 3) & 1) * 8;
                ldsm4(bf[g], smem_u32(base + 10240 + row * 80 + col * 2));
            }
#pragma unroll
            for (int i = 0; i < 4; ++i) {
                int row = wm * 64 + i * 16 + (lane & 15);
                int col = ks + (lane >> 4) * 8;
                ldsm4(ah[i], smem_u32(base + row * 80 + col * 2));
            }
#pragma unroll
            for (int g = 0; g < 2; ++g)
#pragma unroll
                for (int i = 0; i < 4; ++i) {
                    mma_f16(acc.d[i][2 * g],     ah[i], bf[g][0], bf[g][1]);
                    mma_f16(acc.d[i][2 * g + 1], ah[i], bf[g][2], bf[g][3]);
                }
        }
        if (++st == 3) st = 0;
    }
}

// ---------------- fused QKV GEMM: z selects {Q, K, V} ----------------------
__global__ __launch_bounds__(256, 2) void gemm_qkv(
    const __half* __restrict__ x16,
    const __half* __restrict__ wq, const __half* __restrict__ wk,
    const __half* __restrict__ wv,
    const float* __restrict__ bq, const float* __restrict__ bk,
    const float* __restrict__ bv,
    __half* __restrict__ q16, __half* __restrict__ k16, __half* __restrict__ v16)
{
    extern __shared__ char sm[];
    const int tid = threadIdx.x, lane = tid & 31, warp = tid >> 5;
    const int wm = warp >> 2, wn = warp & 3;
    const int m0 = blockIdx.y * 128, n0 = blockIdx.x * 128;
    const int z = blockIdx.z;
    const __half* B = (z == 0) ? wq : (z == 1) ? wk : wv;
    const float* bias = (z == 0) ? bq : (z == 1) ? bk : bv;
    __half* o1 = (z == 0) ? q16 : (z == 1) ? k16 : v16;

    GemmAcc acc = {};
    gemm_core(sm, x16, B, m0, n0, tid, lane, wm, wn, acc);

#pragma unroll
    for (int i = 0; i < 4; ++i)
#pragma unroll
        for (int j = 0; j < 4; ++j) {
            int c = n0 + wn * 32 + j * 8 + (lane & 3) * 2;
            float b0 = bias[c], b1 = bias[c + 1];
#pragma unroll
            for (int h = 0; h < 2; ++h) {
                int m = m0 + wm * 64 + i * 16 + (lane >> 2) + 8 * h;
                float v0 = acc.d[i][j][2 * h] + b0, v1 = acc.d[i][j][2 * h + 1] + b1;
                int bb = m >> 11, s = m & 2047, hh = c >> 6, dd = c & 63;
                size_t idx = (((size_t)(bb * NHEAD + hh)) * S_LEN + s) * DKH + dd;
                *(__half2*)&o1[idx] = __floats2half2_rn(v0, v1);
            }
        }
}

// ---------------- final GEMM: fp32 plain output ----------------------------
__global__ __launch_bounds__(256, 2) void gemm_out(
    const __half* __restrict__ A, const __half* __restrict__ B,
    const float* __restrict__ bias, float* __restrict__ outf)
{
    extern __shared__ char sm[];
    const int tid = threadIdx.x, lane = tid & 31, warp = tid >> 5;
    const int wm = warp >> 2, wn = warp & 3;
    const int m0 = blockIdx.y * 128, n0 = blockIdx.x * 128;

    GemmAcc acc = {};
    gemm_core(sm, A, B, m0, n0, tid, lane, wm, wn, acc);

#pragma unroll
    for (int i = 0; i < 4; ++i)
#pragma unroll
        for (int j = 0; j < 4; ++j) {
            int c = n0 + wn * 32 + j * 8 + (lane & 3) * 2;
            float b0 = bias[c], b1 = bias[c + 1];
#pragma unroll
            for (int h = 0; h < 2; ++h) {
                int m = m0 + wm * 64 + i * 16 + (lane >> 2) + 8 * h;
                *(float2*)&outf[(size_t)m * DMODEL + c] =
                    make_float2(acc.d[i][j][2 * h] + b0, acc.d[i][j][2 * h + 1] + b1);
            }
        }
}

// ---------------- attention v2 (unchanged; proven wait->sync order) --------
#define ATT_Q_OFF 0
#define ATT_K_OFF 18432
#define ATT_V_OFF (3 * 18432)
#define ATT_SMEM_BYTES (5 * 18432)   // 92160; x2 CTAs = 184320

__global__ __launch_bounds__(256, 2) void attn_mma(
    const __half* __restrict__ q16, const __half* __restrict__ k16,
    const __half* __restrict__ v16, __half* __restrict__ aout)
{
    extern __shared__ char sm[];
    const int tid = threadIdx.x, lane = tid & 31, warp = tid >> 5;
    const int bh = blockIdx.y, q0 = blockIdx.x * 128;
    const __half* qb = q16 + (size_t)bh * S_LEN * DKH;
    const __half* kb = k16 + (size_t)bh * S_LEN * DKH;
    const __half* vb = v16 + (size_t)bh * S_LEN * DKH;

#pragma unroll
    for (int i = 0; i < 4; ++i) {
        int u = tid + i * 256;
        int r = u >> 3, c = u & 7;
        *(uint4*)(sm + ATT_Q_OFF + r * 144 + c * 16) =
            *(const uint4*)((const char*)(qb + (size_t)(q0 + r) * DKH) + c * 16);
    }

    auto load_kv = [&](int st, int kt) {
        char* kd = sm + ATT_K_OFF + st * 18432;
        char* vd = sm + ATT_V_OFF + st * 18432;
#pragma unroll
        for (int i = 0; i < 4; ++i) {
            int u = tid + i * 256;
            int r = u >> 3, c = u & 7;
            CP16(smem_u32(kd + r * 144 + c * 16),
                 (const char*)(kb + (size_t)(kt + r) * DKH) + c * 16);
            CP16(smem_u32(vd + r * 144 + c * 16),
                 (const char*)(vb + (size_t)(kt + r) * DKH) + c * 16);
        }
    };

    float m_[2] = {-1e30f, -1e30f};
    float o[8][4] = {};
    float o_l[4] = {};
    const unsigned ones_b = (lane < 4) ? 0x3C003C00u : 0u;
    const float cexp = 0.0625f * 1.44269504f;

    load_kv(0, 0);
    CP_COMMIT();

    for (int t = 0; t < 16; ++t) {
        const int st = t & 1;
        if (t + 1 < 16) { load_kv(st ^ 1, (t + 1) * 128); CP_COMMIT(); CP_WAIT1(); }
        else            { CP_WAIT0(); }
        __syncthreads();

        char* kd = sm + ATT_K_OFF + st * 18432;
        char* vd = sm + ATT_V_OFF + st * 18432;

#pragma unroll
        for (int half = 0; half < 2; ++half) {
            float sc[8][4] = {};
#pragma unroll
            for (int kd4 = 0; kd4 < 4; ++kd4) {
                unsigned qt[4];
                int qrow = warp * 16 + (lane & 15);
                int qcol = kd4 * 16 + (lane >> 4) * 8;
                ldsm4(qt, smem_u32(sm + ATT_Q_OFF + qrow * 144 + qcol * 2));
#pragma unroll
                for (int g = 0; g < 4; ++g) {
                    int krow = half * 64 + g * 16 + (lane & 7) + ((lane & 16) >> 1);
                    int kcol = kd4 * 16 + ((lane >> 3) & 1) * 8;
                    unsigned kr[4];
                    ldsm4(kr, smem_u32(kd + krow * 144 + kcol * 2));
                    mma_f16(sc[2 * g],     qt, kr[0], kr[1]);
                    mma_f16(sc[2 * g + 1], qt, kr[2], kr[3]);
                }
            }

            float corr[2], nmc[2];
#pragma unroll
            for (int h = 0; h < 2; ++h) {
                float mt = -1e30f;
#pragma unroll
                for (int tt = 0; tt < 8; ++tt)
                    mt = fmaxf(mt, fmaxf(sc[tt][2 * h], sc[tt][2 * h + 1]));
                mt = fmaxf(mt, __shfl_xor_sync(0xffffffffu, mt, 1));
                mt = fmaxf(mt, __shfl_xor_sync(0xffffffffu, mt, 2));
                float mn = fmaxf(m_[h], mt);
                corr[h] = exp2f((m_[h] - mn) * cexp);
                m_[h] = mn;
                nmc[h] = mn * cexp;
            }
#pragma unroll
            for (int tt = 0; tt < 8; ++tt) {
                o[tt][0] *= corr[0]; o[tt][1] *= corr[0];
                o[tt][2] *= corr[1]; o[tt][3] *= corr[1];
            }
            o_l[0] *= corr[0]; o_l[1] *= corr[0];
            o_l[2] *= corr[1]; o_l[3] *= corr[1];

            unsigned p[8][2];
#pragma unroll
            for (int tt = 0; tt < 8; ++tt) {
                float a0 = fmaf(sc[tt][0], cexp, -nmc[0]);
                float a1 = fmaf(sc[tt][1], cexp, -nmc[0]);
                float a2 = fmaf(sc[tt][2], cexp, -nmc[1]);
                float a3 = fmaf(sc[tt][3], cexp, -nmc[1]);
                p[tt][0] = exp2_f16x2(a0, a1);
                p[tt][1] = exp2_f16x2(a2, a3);
            }

#pragma unroll
            for (int ks = 0; ks < 4; ++ks) {
                unsigned a_[4] = {p[2 * ks][0], p[2 * ks][1],
                                  p[2 * ks + 1][0], p[2 * ks + 1][1]};
#pragma unroll
                for (int g = 0; g < 4; ++g) {
                    int srow = half * 64 + ks * 16 + (lane & 7) + (((lane >> 3) & 1) << 3);
                    int scol = g * 16 + (((lane >> 4) & 1) << 3);
                    unsigned vr[4];
                    ldsm4_t(vr, smem_u32(vd + srow * 144 + scol * 2));
                    mma_f16(o[2 * g],     a_, vr[0], vr[1]);
                    mma_f16(o[2 * g + 1], a_, vr[2], vr[3]);
                }
                mma_f16(o_l, a_, ones_b, ones_b);
            }
        }
        __syncthreads();
    }

    float l0 = __shfl_sync(0xffffffffu, o_l[0], lane & ~3);
    float l1 = __shfl_sync(0xffffffffu, o_l[2], lane & ~3);
    float inv0 = 1.f / l0, inv1 = 1.f / l1;

    const int b = bh >> 4, head = bh & 15;
#pragma unroll
    for (int h = 0; h < 2; ++h) {
        float inv = h ? inv1 : inv0;
        int s = q0 + warp * 16 + (lane >> 2) + 8 * h;
        size_t rowbase = ((size_t)(b * S_LEN + s)) * DMODEL + head * DKH;
#pragma unroll
        for (int tt = 0; tt < 8; ++tt) {
            int dd = tt * 8 + (lane & 3) * 2;
            *(unsigned*)&aout[rowbase + dd] =
                pack_h2(o[tt][2 * h] * inv, o[tt][2 * h + 1] * inv);
        }
    }
}

// ---------------- launch ----------------
extern "C" void kernel_launch(void* const* d_in, const int* in_sizes, int n_in,
                              void* d_out, int out_size)
{
    const float* x  = (const float*)d_in[0];
    const float* Wq = (const float*)d_in[1];
    const float* bq = (const float*)d_in[2];
    const float* Wk = (const float*)d_in[3];
    const float* bk = (const float*)d_in[4];
    const float* Wv = (const float*)d_in[5];
    const float* bv = (const float*)d_in[6];
    const float* Wo = (const float*)d_in[7];
    const float* bo = (const float*)d_in[8];
    float* out = (float*)d_out;

    __half *x16, *wq16, *wk16, *wv16, *wo16, *q16, *k16, *v16, *a16;
    float *bqf, *bkf;
    cudaGetSymbolAddress((void**)&x16, g_x16);
    cudaGetSymbolAddress((void**)&wq16, g_wq16);
    cudaGetSymbolAddress((void**)&wk16, g_wk16);
    cudaGetSymbolAddress((void**)&wv16, g_wv16);
    cudaGetSymbolAddress((void**)&wo16, g_wo16);
    cudaGetSymbolAddress((void**)&bqf, g_bqf);
    cudaGetSymbolAddress((void**)&bkf, g_bkf);
    cudaGetSymbolAddress((void**)&q16, g_q16);
    cudaGetSymbolAddress((void**)&k16, g_k16);
    cudaGetSymbolAddress((void**)&v16, g_v16);
    cudaGetSymbolAddress((void**)&a16, g_a16);

    mega_prep<<<PREP_BLOCKS, 256>>>(x, x16, Wv, wv16, Wo, wo16,
                                    Wq, Wk, wq16, wk16, bq, bk, bqf, bkf);

    cudaFuncSetAttribute(gemm_qkv, cudaFuncAttributeMaxDynamicSharedMemorySize, GEMMF_SMEM);
    cudaFuncSetAttribute(gemm_out, cudaFuncAttributeMaxDynamicSharedMemorySize, GEMMF_SMEM);

    dim3 gq(DMODEL / 128, M_TOT / 128, 3);   // (8, 32, 3) = 768 CTAs
    gemm_qkv<<<gq, 256, GEMMF_SMEM>>>(x16, wq16, wk16, wv16, bqf, bkf, bv,
                                      q16, k16, v16);

    cudaFuncSetAttribute(attn_mma, cudaFuncAttributeMaxDynamicSharedMemorySize,
                         ATT_SMEM_BYTES);
    attn_mma<<<dim3(S_LEN / 128, BH), 256, ATT_SMEM_BYTES>>>(q16, k16, v16, a16);

    dim3 gg(DMODEL / 128, M_TOT / 128);      // (8, 32)
    gemm_out<<<gg, 256, GEMMF_SMEM>>>(a16, wo16, bo, out);
}